// round 1
// baseline (speedup 1.0000x reference)
#include <cuda_runtime.h>

// Problem constants
#define BB  4
#define SS  2048
#define DDm 1024
#define HHn 16
#define DKk 64
#define BSr (BB*SS)     // 8192 rows
#define N3  3072        // concat of Q|K|V projection outputs
#define BHh (BB*HHn)    // 64 head-batches

// ------------------------- scratch (static device memory) -------------------
__device__ float  g_B  [DDm * N3];                    // [1024][3072] concat B matrix
__device__ float  g_IN [(size_t)BSr * N3];            // [8192][3072] raw projections
__device__ float  g_lam[BSr];                         // per-row lambda
__device__ float4 g_par[2048];                        // per-col {2*zn, cosh2r, sinh2r, 0} (Q then K)
__device__ float  g_QT [(size_t)BHh * DKk * SS];      // Q transposed: [bh][dk][s], pre-scaled by 1/8
__device__ float  g_KT [(size_t)BHh * DKk * SS];      // K transposed: [bh][dk][s]
__device__ float  g_V  [(size_t)BHh * SS * DKk];      // V natural:    [bh][s][dk]

// ------------------------- block reduction helpers --------------------------
__device__ __forceinline__ float bcastSum(float v) {
    __shared__ float sm[8];
    #pragma unroll
    for (int m = 16; m > 0; m >>= 1) v += __shfl_xor_sync(0xffffffffu, v, m);
    int w = threadIdx.x >> 5;
    if ((threadIdx.x & 31) == 0) sm[w] = v;
    __syncthreads();
    if (threadIdx.x < 8) {
        v = sm[threadIdx.x];
        #pragma unroll
        for (int m = 4; m > 0; m >>= 1) v += __shfl_xor_sync(0x000000ffu, v, m);
        if (threadIdx.x == 0) sm[0] = v;
    }
    __syncthreads();
    v = sm[0];
    __syncthreads();
    return v;
}

__device__ __forceinline__ void bcastSum4(float v[4]) {
    __shared__ float sm4[8][4];
    #pragma unroll
    for (int m = 16; m > 0; m >>= 1) {
        #pragma unroll
        for (int c = 0; c < 4; c++) v[c] += __shfl_xor_sync(0xffffffffu, v[c], m);
    }
    int w = threadIdx.x >> 5;
    if ((threadIdx.x & 31) == 0) {
        #pragma unroll
        for (int c = 0; c < 4; c++) sm4[w][c] = v[c];
    }
    __syncthreads();
    if (threadIdx.x < 8) {
        #pragma unroll
        for (int c = 0; c < 4; c++) v[c] = sm4[threadIdx.x][c];
        #pragma unroll
        for (int m = 4; m > 0; m >>= 1) {
            #pragma unroll
            for (int c = 0; c < 4; c++) v[c] += __shfl_xor_sync(0x000000ffu, v[c], m);
        }
        if (threadIdx.x == 0) {
            #pragma unroll
            for (int c = 0; c < 4; c++) sm4[0][c] = v[c];
        }
    }
    __syncthreads();
    #pragma unroll
    for (int c = 0; c < 4; c++) v[c] = sm4[0][c];
    __syncthreads();
}

// ------------------------- prep: build concat B + per-col params ------------
// grid = 3072 blocks, 256 threads. Block j:
//   j <  1024 : column j of z_q  -> g_B[:,j] = z_q[:,j]/zn ; g_par[j]
//   j <  2048 : column j-1024 of z_k -> g_B[:,j]          ; g_par[j]
//   j >= 2048 : g_B[:,j] = w_v[j-2048, :]  (transpose copy for V = x @ w_v^T)
__global__ __launch_bounds__(256) void prep_kernel(
    const float* __restrict__ zq, const float* __restrict__ bq,
    const float* __restrict__ zk, const float* __restrict__ bk,
    const float* __restrict__ wv)
{
    int j = blockIdx.x;
    int tid = threadIdx.x;
    if (j >= 2048) {
        int col = j - 2048;
        for (int d = tid; d < DDm; d += 256)
            g_B[(size_t)d * N3 + j] = wv[(size_t)col * DDm + d];
        return;
    }
    const float* z; const float* bias; int col;
    if (j < 1024) { z = zq; bias = bq; col = j; }
    else          { z = zk; bias = bk; col = j - 1024; }

    float ss = 0.0f;
    for (int d = tid; d < DDm; d += 256) {
        float v = z[(size_t)d * DDm + col];
        ss += v * v;
    }
    ss = bcastSum(ss);
    float zn = fmaxf(sqrtf(ss), 1e-15f);
    float inv = 1.0f / zn;
    for (int d = tid; d < DDm; d += 256)
        g_B[(size_t)d * N3 + j] = z[(size_t)d * DDm + col] * inv;
    if (tid == 0) {
        float r2 = 2.0f * bias[col];
        g_par[j] = make_float4(2.0f * zn, coshf(r2), sinhf(r2), 0.0f);
    }
}

// ------------------------- lambda: per-row 2/(1-||x||^2) --------------------
__global__ __launch_bounds__(256) void lam_kernel(const float* __restrict__ x) {
    int r = blockIdx.x;
    float4 v = *(const float4*)(x + (size_t)r * DDm + threadIdx.x * 4);
    float ss = v.x * v.x + v.y * v.y + v.z * v.z + v.w * v.w;
    ss = bcastSum(ss);
    if (threadIdx.x == 0) g_lam[r] = 2.0f / (1.0f - ss);
}

// ------------------------- SGEMM: g_IN = x(8192x1024) @ g_B(1024x3072) ------
// 128x128x8 tiles, 256 threads, 8x8 thread tiles, double-buffered smem.
__global__ __launch_bounds__(256, 2) void gemm_kernel(const float* __restrict__ A) {
    __shared__ float As[2][8][128];
    __shared__ float Bs[2][8][128];
    int tid = threadIdx.x;
    int tx = tid & 15, ty = tid >> 4;
    int m0 = blockIdx.y * 128, n0 = blockIdx.x * 128;

    int arow = tid >> 1;
    int akg  = (tid & 1) * 4;
    int brow = tid >> 5;
    int bcol = (tid & 31) * 4;
    const float* Aptr = A + (size_t)(m0 + arow) * DDm + akg;
    const float* Bptr = g_B + (size_t)brow * N3 + n0 + bcol;

    float4 aReg = *(const float4*)Aptr;
    float4 bReg = *(const float4*)Bptr;
    float acc[8][8];
    #pragma unroll
    for (int i = 0; i < 8; i++)
        #pragma unroll
        for (int j = 0; j < 8; j++) acc[i][j] = 0.0f;

    As[0][akg + 0][arow] = aReg.x;
    As[0][akg + 1][arow] = aReg.y;
    As[0][akg + 2][arow] = aReg.z;
    As[0][akg + 3][arow] = aReg.w;
    *(float4*)&Bs[0][brow][bcol] = bReg;
    __syncthreads();

    int buf = 0;
    for (int kt = 0; kt < 128; kt++) {
        if (kt < 127) {
            aReg = *(const float4*)(Aptr + (size_t)(kt + 1) * 8);
            bReg = *(const float4*)(Bptr + (size_t)(kt + 1) * 8 * N3);
        }
        #pragma unroll
        for (int kk = 0; kk < 8; kk++) {
            float av[8], bv_[8];
            *(float4*)&av[0]  = *(const float4*)&As[buf][kk][ty * 8];
            *(float4*)&av[4]  = *(const float4*)&As[buf][kk][ty * 8 + 4];
            *(float4*)&bv_[0] = *(const float4*)&Bs[buf][kk][tx * 8];
            *(float4*)&bv_[4] = *(const float4*)&Bs[buf][kk][tx * 8 + 4];
            #pragma unroll
            for (int i = 0; i < 8; i++)
                #pragma unroll
                for (int j = 0; j < 8; j++)
                    acc[i][j] += av[i] * bv_[j];
        }
        if (kt < 127) {
            int nb = buf ^ 1;
            As[nb][akg + 0][arow] = aReg.x;
            As[nb][akg + 1][arow] = aReg.y;
            As[nb][akg + 2][arow] = aReg.z;
            As[nb][akg + 3][arow] = aReg.w;
            *(float4*)&Bs[nb][brow][bcol] = bReg;
            buf = nb;
        }
        __syncthreads();
    }

    float* Cp = g_IN + (size_t)(m0 + ty * 8) * N3 + n0 + tx * 8;
    #pragma unroll
    for (int i = 0; i < 8; i++) {
        *(float4*)(Cp + (size_t)i * N3)     = make_float4(acc[i][0], acc[i][1], acc[i][2], acc[i][3]);
        *(float4*)(Cp + (size_t)i * N3 + 4) = make_float4(acc[i][4], acc[i][5], acc[i][6], acc[i][7]);
    }
}

// ------------------------- epilogue: Poincare map + layouts -----------------
// grid = 2048 blocks (4 rows each), 256 threads (4 consecutive cols each).
// Writes Q (scaled by 1/8) and K transposed [bh][dk][s] (float4 along s),
// V natural [bh][s][dk].
__global__ __launch_bounds__(256) void epi_kernel(const float* __restrict__ bvp) {
    int r0 = blockIdx.x * 4;
    int b  = r0 >> 11;
    int s0 = r0 & 2047;
    int tid = threadIdx.x;
    int j0 = tid * 4;

    float lamv[4];
    *(float4*)lamv = *(const float4*)(g_lam + r0);

    // ---------------- Q ----------------
    float wq[4][4];
    float ws[4] = {0.f, 0.f, 0.f, 0.f};
    {
        float4 par[4];
        #pragma unroll
        for (int c = 0; c < 4; c++) par[c] = g_par[j0 + c];
        #pragma unroll
        for (int ri = 0; ri < 4; ri++) {
            float lam = lamv[ri], lm1 = lam - 1.0f;
            float4 inn = *(const float4*)(g_IN + (size_t)(r0 + ri) * N3 + j0);
            float innv[4] = {inn.x, inn.y, inn.z, inn.w};
            #pragma unroll
            for (int c = 0; c < 4; c++) {
                float arg = lam * innv[c] * par[c].y - lm1 * par[c].z;
                float t   = arg + sqrtf(arg * arg + 1.0f);
                float u   = par[c].x * __logf(t);
                float eu  = __expf(u);
                float w   = 0.5f * (eu - __fdividef(1.0f, eu));
                wq[ri][c] = w;
                ws[ri] += w * w;
            }
        }
        bcastSum4(ws);
        float scl[4];
        #pragma unroll
        for (int ri = 0; ri < 4; ri++)
            scl[ri] = 0.125f / (1.0f + sqrtf(1.0f + ws[ri]));   // fold 1/sqrt(Dk)
        #pragma unroll
        for (int c = 0; c < 4; c++) {
            int j = j0 + c;
            float4 ov = make_float4(wq[0][c] * scl[0], wq[1][c] * scl[1],
                                    wq[2][c] * scl[2], wq[3][c] * scl[3]);
            *(float4*)(g_QT + (size_t)(b * 1024 + j) * SS + s0) = ov;
        }
    }
    // ---------------- K ----------------
    {
        float4 par[4];
        #pragma unroll
        for (int c = 0; c < 4; c++) par[c] = g_par[1024 + j0 + c];
        float ws2[4] = {0.f, 0.f, 0.f, 0.f};
        #pragma unroll
        for (int ri = 0; ri < 4; ri++) {
            float lam = lamv[ri], lm1 = lam - 1.0f;
            float4 inn = *(const float4*)(g_IN + (size_t)(r0 + ri) * N3 + 1024 + j0);
            float innv[4] = {inn.x, inn.y, inn.z, inn.w};
            #pragma unroll
            for (int c = 0; c < 4; c++) {
                float arg = lam * innv[c] * par[c].y - lm1 * par[c].z;
                float t   = arg + sqrtf(arg * arg + 1.0f);
                float u   = par[c].x * __logf(t);
                float eu  = __expf(u);
                float w   = 0.5f * (eu - __fdividef(1.0f, eu));
                wq[ri][c] = w;
                ws2[ri] += w * w;
            }
        }
        bcastSum4(ws2);
        float scl[4];
        #pragma unroll
        for (int ri = 0; ri < 4; ri++)
            scl[ri] = 1.0f / (1.0f + sqrtf(1.0f + ws2[ri]));
        #pragma unroll
        for (int c = 0; c < 4; c++) {
            int j = j0 + c;
            float4 ov = make_float4(wq[0][c] * scl[0], wq[1][c] * scl[1],
                                    wq[2][c] * scl[2], wq[3][c] * scl[3]);
            *(float4*)(g_KT + (size_t)(b * 1024 + j) * SS + s0) = ov;
        }
    }
    // ---------------- V ----------------
    {
        float4 bvv = *(const float4*)(bvp + j0);
        int h = j0 >> 6, dk = j0 & 63;
        float* Vb = g_V + (size_t)(b * 16 + h) * SS * DKk;
        #pragma unroll
        for (int ri = 0; ri < 4; ri++) {
            float4 inn = *(const float4*)(g_IN + (size_t)(r0 + ri) * N3 + 2048 + j0);
            float4 ov = make_float4(inn.x + bvv.x, inn.y + bvv.y,
                                    inn.z + bvv.z, inn.w + bvv.w);
            *(float4*)(Vb + (size_t)(s0 + ri) * DKk + dk) = ov;
        }
    }
}

// ------------------------- flash attention ----------------------------------
// grid = (S/64, BH) = (32, 64). 256 threads, 4x4 register tiles.
// smem: sQ/sK d-major [64][64], sV natural [64][64], sP swizzled float4 cells.
__global__ __launch_bounds__(256) void attn_kernel(float* __restrict__ out) {
    extern __shared__ float smem[];
    float*  sQ = smem;
    float*  sK = smem + 4096;
    float*  sV = smem + 8192;
    float4* sP = (float4*)(smem + 12288);

    int tid = threadIdx.x;
    int ty = tid >> 4, tx = tid & 15;
    int bh = blockIdx.y;
    int s0 = blockIdx.x * 64;
    const float* QT = g_QT + (size_t)bh * DKk * SS;
    const float* KT = g_KT + (size_t)bh * DKk * SS;
    const float* Vp = g_V  + (size_t)bh * SS * DKk;

    int lrow = tid >> 4;          // 0..15
    int lg   = (tid & 15) * 4;

    #pragma unroll
    for (int it = 0; it < 4; it++) {
        int d = lrow + it * 16;
        *(float4*)(sQ + d * 64 + lg) = *(const float4*)(QT + (size_t)d * SS + s0 + lg);
    }

    float o[4][4];
    float m_[4], l_[4];
    #pragma unroll
    for (int i = 0; i < 4; i++) {
        m_[i] = -1e30f; l_[i] = 0.0f;
        #pragma unroll
        for (int j = 0; j < 4; j++) o[i][j] = 0.0f;
    }

    for (int kt = 0; kt < 32; kt++) {
        int kc0 = kt * 64;
        __syncthreads();   // prev PV done; sQ visible on first pass
        #pragma unroll
        for (int it = 0; it < 4; it++) {
            int rr = lrow + it * 16;
            *(float4*)(sK + rr * 64 + lg) = *(const float4*)(KT + (size_t)rr * SS + kc0 + lg);
            *(float4*)(sV + rr * 64 + lg) = *(const float4*)(Vp + (size_t)(kc0 + rr) * DKk + lg);
        }
        __syncthreads();

        // S = Q^T-tile . K-tile  (both d-major in smem)
        float sc[4][4];
        #pragma unroll
        for (int i = 0; i < 4; i++)
            #pragma unroll
            for (int j = 0; j < 4; j++) sc[i][j] = 0.0f;
        #pragma unroll 8
        for (int d = 0; d < 64; d++) {
            float4 a4 = *(const float4*)(sQ + d * 64 + ty * 4);
            float4 b4 = *(const float4*)(sK + d * 64 + tx * 4);
            float aa[4] = {a4.x, a4.y, a4.z, a4.w};
            float bb[4] = {b4.x, b4.y, b4.z, b4.w};
            #pragma unroll
            for (int i = 0; i < 4; i++)
                #pragma unroll
                for (int j = 0; j < 4; j++)
                    sc[i][j] += aa[i] * bb[j];
        }

        // online softmax over 16-lane row groups
        #pragma unroll
        for (int i = 0; i < 4; i++) {
            float tm = fmaxf(fmaxf(sc[i][0], sc[i][1]), fmaxf(sc[i][2], sc[i][3]));
            #pragma unroll
            for (int m = 8; m > 0; m >>= 1)
                tm = fmaxf(tm, __shfl_xor_sync(0xffffffffu, tm, m, 16));
            float mn = fmaxf(m_[i], tm);
            float al = __expf(m_[i] - mn);
            float rs = 0.0f;
            #pragma unroll
            for (int j = 0; j < 4; j++) {
                float p = __expf(sc[i][j] - mn);
                sc[i][j] = p; rs += p;
            }
            #pragma unroll
            for (int m = 8; m > 0; m >>= 1)
                rs += __shfl_xor_sync(0xffffffffu, rs, m, 16);
            l_[i] = l_[i] * al + rs;
            m_[i] = mn;
            #pragma unroll
            for (int j = 0; j < 4; j++) o[i][j] *= al;
        }

        // store P column-major with XOR swizzle: cell (k, ty^((k>>2)&7)) holds rows 4ty..4ty+3
        #pragma unroll
        for (int j = 0; j < 4; j++) {
            int k = tx * 4 + j;
            int c = ty ^ (tx & 7);
            sP[k * 16 + c] = make_float4(sc[0][j], sc[1][j], sc[2][j], sc[3][j]);
        }
        __syncthreads();

        // O += P . V
        #pragma unroll 8
        for (int k = 0; k < 64; k++) {
            int c = ty ^ ((k >> 2) & 7);
            float4 a4 = sP[k * 16 + c];
            float4 b4 = *(const float4*)(sV + k * 64 + tx * 4);
            float aa[4] = {a4.x, a4.y, a4.z, a4.w};
            float bb[4] = {b4.x, b4.y, b4.z, b4.w};
            #pragma unroll
            for (int i = 0; i < 4; i++)
                #pragma unroll
                for (int j = 0; j < 4; j++)
                    o[i][j] += aa[i] * bb[j];
        }
    }

    int b = bh >> 4, h = bh & 15;
    #pragma unroll
    for (int i = 0; i < 4; i++) {
        float inv = 1.0f / l_[i];
        float4 ov = make_float4(o[i][0] * inv, o[i][1] * inv,
                                o[i][2] * inv, o[i][3] * inv);
        *(float4*)(out + (size_t)(b * SS + s0 + ty * 4 + i) * DDm + h * 64 + tx * 4) = ov;
    }
}

// ------------------------- launcher ----------------------------------------
extern "C" void kernel_launch(void* const* d_in, const int* in_sizes, int n_in,
                              void* d_out, int out_size) {
    const float* x  = (const float*)d_in[0];
    const float* zq = (const float*)d_in[1];
    const float* bq = (const float*)d_in[2];
    const float* zk = (const float*)d_in[3];
    const float* bk = (const float*)d_in[4];
    const float* wv = (const float*)d_in[5];
    const float* bv = (const float*)d_in[6];
    float* out = (float*)d_out;

    prep_kernel<<<N3, 256>>>(zq, bq, zk, bk, wv);
    lam_kernel<<<BSr, 256>>>(x);
    gemm_kernel<<<dim3(N3 / 128, BSr / 128), 256>>>(x);
    epi_kernel<<<BSr / 4, 256>>>(bv);

    cudaFuncSetAttribute(attn_kernel, cudaFuncAttributeMaxDynamicSharedMemorySize, 65536);
    attn_kernel<<<dim3(SS / 64, BHh), 256, 65536>>>(out);
}

// round 3
// speedup vs baseline: 1.5907x; 1.5907x over previous
#include <cuda_runtime.h>
#include <cstdint>

// Problem constants
#define BB  4
#define SS  2048
#define DDm 1024
#define HHn 16
#define DKk 64
#define BSr (BB*SS)     // 8192 rows
#define N3  3072        // concat of Q|K|V projection outputs
#define BHh (BB*HHn)    // 64 head-batches

// ------------------------- scratch (static device memory) -------------------
__device__ float  g_B  [DDm * N3];                    // [1024][3072] concat B matrix
__device__ float  g_IN [(size_t)BSr * N3];            // [8192][3072] raw projections
__device__ float  g_lam[BSr];                         // per-row lambda
__device__ float4 g_par[2048];                        // per-col {2*zn, cosh2r, sinh2r, 0} (Q then K)
__device__ float  g_Q  [(size_t)BHh * SS * DKk];      // Q natural [bh][s][dk], pre-scaled 1/8
__device__ float  g_K  [(size_t)BHh * SS * DKk];      // K natural [bh][s][dk]
__device__ float  g_V  [(size_t)BHh * SS * DKk];      // V natural [bh][s][dk]

// ------------------------- mma / cvt helpers --------------------------------
__device__ __forceinline__ uint32_t f2tf(float f) {
    uint32_t r; asm("cvt.rna.tf32.f32 %0, %1;" : "=r"(r) : "f"(f)); return r;
}
__device__ __forceinline__ void mma_tf32(float c[4], const uint32_t a[4],
                                         uint32_t b0, uint32_t b1) {
    asm volatile(
        "mma.sync.aligned.m16n8k8.row.col.f32.tf32.tf32.f32 "
        "{%0,%1,%2,%3}, {%4,%5,%6,%7}, {%8,%9}, {%0,%1,%2,%3};\n"
        : "+f"(c[0]), "+f"(c[1]), "+f"(c[2]), "+f"(c[3])
        : "r"(a[0]), "r"(a[1]), "r"(a[2]), "r"(a[3]), "r"(b0), "r"(b1));
}

// ------------------------- block reduction helpers --------------------------
__device__ __forceinline__ float bcastSum(float v) {
    __shared__ float sm[8];
    #pragma unroll
    for (int m = 16; m > 0; m >>= 1) v += __shfl_xor_sync(0xffffffffu, v, m);
    int w = threadIdx.x >> 5;
    if ((threadIdx.x & 31) == 0) sm[w] = v;
    __syncthreads();
    if (threadIdx.x < 8) {
        v = sm[threadIdx.x];
        #pragma unroll
        for (int m = 4; m > 0; m >>= 1) v += __shfl_xor_sync(0x000000ffu, v, m);
        if (threadIdx.x == 0) sm[0] = v;
    }
    __syncthreads();
    v = sm[0];
    __syncthreads();
    return v;
}

__device__ __forceinline__ void bcastSum4(float v[4]) {
    __shared__ float sm4[8][4];
    #pragma unroll
    for (int m = 16; m > 0; m >>= 1) {
        #pragma unroll
        for (int c = 0; c < 4; c++) v[c] += __shfl_xor_sync(0xffffffffu, v[c], m);
    }
    int w = threadIdx.x >> 5;
    if ((threadIdx.x & 31) == 0) {
        #pragma unroll
        for (int c = 0; c < 4; c++) sm4[w][c] = v[c];
    }
    __syncthreads();
    if (threadIdx.x < 8) {
        #pragma unroll
        for (int c = 0; c < 4; c++) v[c] = sm4[threadIdx.x][c];
        #pragma unroll
        for (int m = 4; m > 0; m >>= 1) {
            #pragma unroll
            for (int c = 0; c < 4; c++) v[c] += __shfl_xor_sync(0x000000ffu, v[c], m);
        }
        if (threadIdx.x == 0) {
            #pragma unroll
            for (int c = 0; c < 4; c++) sm4[0][c] = v[c];
        }
    }
    __syncthreads();
    #pragma unroll
    for (int c = 0; c < 4; c++) v[c] = sm4[0][c];
    __syncthreads();
}

// ------------------------- prep: build concat B + per-col params ------------
__global__ __launch_bounds__(256) void prep_kernel(
    const float* __restrict__ zq, const float* __restrict__ bq,
    const float* __restrict__ zk, const float* __restrict__ bk,
    const float* __restrict__ wv)
{
    int j = blockIdx.x;
    int tid = threadIdx.x;
    if (j >= 2048) {
        int col = j - 2048;
        for (int d = tid; d < DDm; d += 256)
            g_B[(size_t)d * N3 + j] = wv[(size_t)col * DDm + d];
        return;
    }
    const float* z; const float* bias; int col;
    if (j < 1024) { z = zq; bias = bq; col = j; }
    else          { z = zk; bias = bk; col = j - 1024; }

    float ss = 0.0f;
    for (int d = tid; d < DDm; d += 256) {
        float v = z[(size_t)d * DDm + col];
        ss += v * v;
    }
    ss = bcastSum(ss);
    float zn = fmaxf(sqrtf(ss), 1e-15f);
    float inv = 1.0f / zn;
    for (int d = tid; d < DDm; d += 256)
        g_B[(size_t)d * N3 + j] = z[(size_t)d * DDm + col] * inv;
    if (tid == 0) {
        float r2 = 2.0f * bias[col];
        g_par[j] = make_float4(2.0f * zn, coshf(r2), sinhf(r2), 0.0f);
    }
}

// ------------------------- lambda: per-row 2/(1-||x||^2) --------------------
__global__ __launch_bounds__(256) void lam_kernel(const float* __restrict__ x) {
    int r = blockIdx.x;
    float4 v = *(const float4*)(x + (size_t)r * DDm + threadIdx.x * 4);
    float ss = v.x * v.x + v.y * v.y + v.z * v.z + v.w * v.w;
    ss = bcastSum(ss);
    if (threadIdx.x == 0) g_lam[r] = 2.0f / (1.0f - ss);
}

// ------------------------- SGEMM: g_IN = x(8192x1024) @ g_B(1024x3072) ------
__global__ __launch_bounds__(256, 2) void gemm_kernel(const float* __restrict__ A) {
    __shared__ float As[2][8][128];
    __shared__ float Bs[2][8][128];
    int tid = threadIdx.x;
    int tx = tid & 15, ty = tid >> 4;
    int m0 = blockIdx.y * 128, n0 = blockIdx.x * 128;

    int arow = tid >> 1;
    int akg  = (tid & 1) * 4;
    int brow = tid >> 5;
    int bcol = (tid & 31) * 4;
    const float* Aptr = A + (size_t)(m0 + arow) * DDm + akg;
    const float* Bptr = g_B + (size_t)brow * N3 + n0 + bcol;

    float4 aReg = *(const float4*)Aptr;
    float4 bReg = *(const float4*)Bptr;
    float acc[8][8];
    #pragma unroll
    for (int i = 0; i < 8; i++)
        #pragma unroll
        for (int j = 0; j < 8; j++) acc[i][j] = 0.0f;

    As[0][akg + 0][arow] = aReg.x;
    As[0][akg + 1][arow] = aReg.y;
    As[0][akg + 2][arow] = aReg.z;
    As[0][akg + 3][arow] = aReg.w;
    *(float4*)&Bs[0][brow][bcol] = bReg;
    __syncthreads();

    int buf = 0;
    for (int kt = 0; kt < 128; kt++) {
        if (kt < 127) {
            aReg = *(const float4*)(Aptr + (size_t)(kt + 1) * 8);
            bReg = *(const float4*)(Bptr + (size_t)(kt + 1) * 8 * N3);
        }
        #pragma unroll
        for (int kk = 0; kk < 8; kk++) {
            float av[8], bv_[8];
            *(float4*)&av[0]  = *(const float4*)&As[buf][kk][ty * 8];
            *(float4*)&av[4]  = *(const float4*)&As[buf][kk][ty * 8 + 4];
            *(float4*)&bv_[0] = *(const float4*)&Bs[buf][kk][tx * 8];
            *(float4*)&bv_[4] = *(const float4*)&Bs[buf][kk][tx * 8 + 4];
            #pragma unroll
            for (int i = 0; i < 8; i++)
                #pragma unroll
                for (int j = 0; j < 8; j++)
                    acc[i][j] += av[i] * bv_[j];
        }
        if (kt < 127) {
            int nb = buf ^ 1;
            As[nb][akg + 0][arow] = aReg.x;
            As[nb][akg + 1][arow] = aReg.y;
            As[nb][akg + 2][arow] = aReg.z;
            As[nb][akg + 3][arow] = aReg.w;
            *(float4*)&Bs[nb][brow][bcol] = bReg;
            buf = nb;
        }
        __syncthreads();
    }

    float* Cp = g_IN + (size_t)(m0 + ty * 8) * N3 + n0 + tx * 8;
    #pragma unroll
    for (int i = 0; i < 8; i++) {
        *(float4*)(Cp + (size_t)i * N3)     = make_float4(acc[i][0], acc[i][1], acc[i][2], acc[i][3]);
        *(float4*)(Cp + (size_t)i * N3 + 4) = make_float4(acc[i][4], acc[i][5], acc[i][6], acc[i][7]);
    }
}

// ------------------------- epilogue: Poincare map + layouts -----------------
// grid = 2048 blocks (4 rows each), 256 threads (4 consecutive cols each).
// Writes Q (scaled 1/8), K, V all natural [bh][s][dk].
__global__ __launch_bounds__(256) void epi_kernel(const float* __restrict__ bvp) {
    int r0 = blockIdx.x * 4;
    int b  = r0 >> 11;
    int s0 = r0 & 2047;
    int tid = threadIdx.x;
    int j0 = tid * 4;
    int h  = j0 >> 6, dk = j0 & 63;

    float lamv[4];
    *(float4*)lamv = *(const float4*)(g_lam + r0);

    float wq[4][4];
    // ---------------- Q ----------------
    {
        float4 par[4];
        #pragma unroll
        for (int c = 0; c < 4; c++) par[c] = g_par[j0 + c];
        float ws[4] = {0.f, 0.f, 0.f, 0.f};
        #pragma unroll
        for (int ri = 0; ri < 4; ri++) {
            float lam = lamv[ri], lm1 = lam - 1.0f;
            float4 inn = *(const float4*)(g_IN + (size_t)(r0 + ri) * N3 + j0);
            float innv[4] = {inn.x, inn.y, inn.z, inn.w};
            #pragma unroll
            for (int c = 0; c < 4; c++) {
                float arg = lam * innv[c] * par[c].y - lm1 * par[c].z;
                float t   = arg + sqrtf(arg * arg + 1.0f);
                float u   = par[c].x * __logf(t);
                float eu  = __expf(u);
                float w   = 0.5f * (eu - __fdividef(1.0f, eu));
                wq[ri][c] = w;
                ws[ri] += w * w;
            }
        }
        bcastSum4(ws);
        #pragma unroll
        for (int ri = 0; ri < 4; ri++) {
            float scl = 0.125f / (1.0f + sqrtf(1.0f + ws[ri]));   // fold 1/sqrt(Dk)
            float4 ov = make_float4(wq[ri][0] * scl, wq[ri][1] * scl,
                                    wq[ri][2] * scl, wq[ri][3] * scl);
            *(float4*)(g_Q + ((size_t)(b * 16 + h) * SS + s0 + ri) * DKk + dk) = ov;
        }
    }
    // ---------------- K ----------------
    {
        float4 par[4];
        #pragma unroll
        for (int c = 0; c < 4; c++) par[c] = g_par[1024 + j0 + c];
        float ws2[4] = {0.f, 0.f, 0.f, 0.f};
        #pragma unroll
        for (int ri = 0; ri < 4; ri++) {
            float lam = lamv[ri], lm1 = lam - 1.0f;
            float4 inn = *(const float4*)(g_IN + (size_t)(r0 + ri) * N3 + 1024 + j0);
            float innv[4] = {inn.x, inn.y, inn.z, inn.w};
            #pragma unroll
            for (int c = 0; c < 4; c++) {
                float arg = lam * innv[c] * par[c].y - lm1 * par[c].z;
                float t   = arg + sqrtf(arg * arg + 1.0f);
                float u   = par[c].x * __logf(t);
                float eu  = __expf(u);
                float w   = 0.5f * (eu - __fdividef(1.0f, eu));
                wq[ri][c] = w;
                ws2[ri] += w * w;
            }
        }
        bcastSum4(ws2);
        #pragma unroll
        for (int ri = 0; ri < 4; ri++) {
            float scl = 1.0f / (1.0f + sqrtf(1.0f + ws2[ri]));
            float4 ov = make_float4(wq[ri][0] * scl, wq[ri][1] * scl,
                                    wq[ri][2] * scl, wq[ri][3] * scl);
            *(float4*)(g_K + ((size_t)(b * 16 + h) * SS + s0 + ri) * DKk + dk) = ov;
        }
    }
    // ---------------- V ----------------
    {
        float4 bvv = *(const float4*)(bvp + j0);
        #pragma unroll
        for (int ri = 0; ri < 4; ri++) {
            float4 inn = *(const float4*)(g_IN + (size_t)(r0 + ri) * N3 + 2048 + j0);
            float4 ov = make_float4(inn.x + bvv.x, inn.y + bvv.y,
                                    inn.z + bvv.z, inn.w + bvv.w);
            *(float4*)(g_V + ((size_t)(b * 16 + h) * SS + s0 + ri) * DKk + dk) = ov;
        }
    }
}

// ------------------------- flash attention (tf32 mma.sync) ------------------
// grid = (S/128, BH) = (16, 64). 256 threads = 8 warps, 16 query rows/warp.
// K-tile 64 keys. Pads: sK stride 68 (4 mod 32), sV stride 72 (8 mod 32)
// make all B-fragment LDS conflict-free.
__global__ __launch_bounds__(256, 2) void attn_kernel(float* __restrict__ out) {
    __shared__ float sK[64][68];
    __shared__ float sV[64][72];

    int tid  = threadIdx.x;
    int warp = tid >> 5, lane = tid & 31;
    int g = lane >> 2, tig = lane & 3;
    int bh = blockIdx.y;
    int b  = bh >> 4, h = bh & 15;
    int q0 = blockIdx.x * 128;
    int wq = warp * 16;

    const float* Qp = g_Q + ((size_t)bh * SS + q0 + wq) * DKk;
    const float* Kg = g_K + (size_t)bh * SS * DKk;
    const float* Vg = g_V + (size_t)bh * SS * DKk;

    // Q A-fragments (persistent, tf32)
    uint32_t qa[8][4];
    #pragma unroll
    for (int kt = 0; kt < 8; kt++) {
        qa[kt][0] = f2tf(Qp[(size_t)g        * DKk + kt * 8 + tig]);
        qa[kt][1] = f2tf(Qp[(size_t)(g + 8)  * DKk + kt * 8 + tig]);
        qa[kt][2] = f2tf(Qp[(size_t)g        * DKk + kt * 8 + tig + 4]);
        qa[kt][3] = f2tf(Qp[(size_t)(g + 8)  * DKk + kt * 8 + tig + 4]);
    }

    float o[8][4];
    #pragma unroll
    for (int n = 0; n < 8; n++)
        #pragma unroll
        for (int c = 0; c < 4; c++) o[n][c] = 0.0f;
    float m0 = -1e30f, m1 = -1e30f, l0 = 0.0f, l1 = 0.0f;

    int lr = tid >> 4;          // 0..15
    int lc = (tid & 15) * 4;    // 0..60

    for (int it = 0; it < SS / 64; it++) {
        int kc0 = it * 64;
        __syncthreads();
        #pragma unroll
        for (int i = 0; i < 4; i++) {
            int rr = lr + i * 16;
            *(float4*)&sK[rr][lc] = *(const float4*)(Kg + (size_t)(kc0 + rr) * DKk + lc);
            *(float4*)&sV[rr][lc] = *(const float4*)(Vg + (size_t)(kc0 + rr) * DKk + lc);
        }
        __syncthreads();

        // S = Q . K^T  (16 x 64 per warp)
        float p[8][4];
        #pragma unroll
        for (int n = 0; n < 8; n++)
            #pragma unroll
            for (int c = 0; c < 4; c++) p[n][c] = 0.0f;
        #pragma unroll
        for (int k0 = 0; k0 < 8; k0++) {
            #pragma unroll
            for (int n0 = 0; n0 < 8; n0++) {
                uint32_t b0 = f2tf(sK[n0 * 8 + g][k0 * 8 + tig]);
                uint32_t b1 = f2tf(sK[n0 * 8 + g][k0 * 8 + tig + 4]);
                mma_tf32(p[n0], qa[k0], b0, b1);
            }
        }

        // online softmax: thread owns rows g (c0,c1) and g+8 (c2,c3)
        float rm0 = -1e30f, rm1 = -1e30f;
        #pragma unroll
        for (int n = 0; n < 8; n++) {
            rm0 = fmaxf(rm0, fmaxf(p[n][0], p[n][1]));
            rm1 = fmaxf(rm1, fmaxf(p[n][2], p[n][3]));
        }
        rm0 = fmaxf(rm0, __shfl_xor_sync(0xffffffffu, rm0, 1));
        rm0 = fmaxf(rm0, __shfl_xor_sync(0xffffffffu, rm0, 2));
        rm1 = fmaxf(rm1, __shfl_xor_sync(0xffffffffu, rm1, 1));
        rm1 = fmaxf(rm1, __shfl_xor_sync(0xffffffffu, rm1, 2));
        float mn0 = fmaxf(m0, rm0), mn1 = fmaxf(m1, rm1);
        float al0 = __expf(m0 - mn0), al1 = __expf(m1 - mn1);
        m0 = mn0; m1 = mn1;
        float rs0 = 0.0f, rs1 = 0.0f;
        #pragma unroll
        for (int n = 0; n < 8; n++) {
            p[n][0] = __expf(p[n][0] - m0);
            p[n][1] = __expf(p[n][1] - m0);
            p[n][2] = __expf(p[n][2] - m1);
            p[n][3] = __expf(p[n][3] - m1);
            rs0 += p[n][0] + p[n][1];
            rs1 += p[n][2] + p[n][3];
        }
        rs0 += __shfl_xor_sync(0xffffffffu, rs0, 1);
        rs0 += __shfl_xor_sync(0xffffffffu, rs0, 2);
        rs1 += __shfl_xor_sync(0xffffffffu, rs1, 1);
        rs1 += __shfl_xor_sync(0xffffffffu, rs1, 2);
        l0 = l0 * al0 + rs0;
        l1 = l1 * al1 + rs1;
        #pragma unroll
        for (int n = 0; n < 8; n++) {
            o[n][0] *= al0; o[n][1] *= al0;
            o[n][2] *= al1; o[n][3] *= al1;
        }

        // O += P . V  ; P re-laid C-frag -> A-frag via quad shuffles
        unsigned base = lane & ~3u;
        int hs = base + (tig >> 1);
        bool odd = tig & 1;
        #pragma unroll
        for (int kt = 0; kt < 8; kt++) {
            float v0 = __shfl_sync(0xffffffffu, p[kt][0], hs);
            float v1 = __shfl_sync(0xffffffffu, p[kt][1], hs);
            float v2 = __shfl_sync(0xffffffffu, p[kt][0], hs + 2);
            float v3 = __shfl_sync(0xffffffffu, p[kt][1], hs + 2);
            float w0 = __shfl_sync(0xffffffffu, p[kt][2], hs);
            float w1 = __shfl_sync(0xffffffffu, p[kt][3], hs);
            float w2 = __shfl_sync(0xffffffffu, p[kt][2], hs + 2);
            float w3 = __shfl_sync(0xffffffffu, p[kt][3], hs + 2);
            uint32_t a[4];
            a[0] = f2tf(odd ? v1 : v0);
            a[1] = f2tf(odd ? w1 : w0);
            a[2] = f2tf(odd ? v3 : v2);
            a[3] = f2tf(odd ? w3 : w2);
            #pragma unroll
            for (int n0 = 0; n0 < 8; n0++) {
                uint32_t b0 = f2tf(sV[kt * 8 + tig][n0 * 8 + g]);
                uint32_t b1 = f2tf(sV[kt * 8 + tig + 4][n0 * 8 + g]);
                mma_tf32(o[n0], a, b0, b1);
            }
        }
    }

    float inv0 = 1.0f / l0, inv1 = 1.0f / l1;
    int s0r = q0 + wq + g;
    #pragma unroll
    for (int n0 = 0; n0 < 8; n0++) {
        int dk = n0 * 8 + 2 * tig;
        float2 ov0 = make_float2(o[n0][0] * inv0, o[n0][1] * inv0);
        float2 ov1 = make_float2(o[n0][2] * inv1, o[n0][3] * inv1);
        *(float2*)(out + ((size_t)(b * SS + s0r)     ) * DDm + h * 64 + dk) = ov0;
        *(float2*)(out + ((size_t)(b * SS + s0r + 8) ) * DDm + h * 64 + dk) = ov1;
    }
}

// ------------------------- launcher ----------------------------------------
extern "C" void kernel_launch(void* const* d_in, const int* in_sizes, int n_in,
                              void* d_out, int out_size) {
    const float* x  = (const float*)d_in[0];
    const float* zq = (const float*)d_in[1];
    const float* bq = (const float*)d_in[2];
    const float* zk = (const float*)d_in[3];
    const float* bk = (const float*)d_in[4];
    const float* wv = (const float*)d_in[5];
    const float* bv = (const float*)d_in[6];
    float* out = (float*)d_out;

    prep_kernel<<<N3, 256>>>(zq, bq, zk, bk, wv);
    lam_kernel<<<BSr, 256>>>(x);
    gemm_kernel<<<dim3(N3 / 128, BSr / 128), 256>>>(x);
    epi_kernel<<<BSr / 4, 256>>>(bv);
    attn_kernel<<<dim3(SS / 128, BHh), 256>>>(out);
}

// round 4
// speedup vs baseline: 2.6765x; 1.6826x over previous
#include <cuda_runtime.h>
#include <cstdint>

// Problem constants
#define BB  4
#define SS  2048
#define DDm 1024
#define HHn 16
#define DKk 64
#define BSr (BB*SS)     // 8192 rows
#define N3  3072        // concat of Q|K|V projection outputs
#define BHh (BB*HHn)    // 64 head-batches

// ------------------------- scratch (static device memory) -------------------
__device__ float  g_B  [DDm * N3];                    // [1024][3072] concat B matrix
__device__ float  g_IN [(size_t)BSr * N3];            // [8192][3072] raw projections
__device__ float  g_lam[BSr];                         // per-row lambda
__device__ float4 g_par[2048];                        // per-col {2*zn, cosh2r, sinh2r, 0} (Q then K)
__device__ float  g_Q  [(size_t)BHh * SS * DKk];      // Q natural [bh][s][dk], pre-scaled 1/8
__device__ float  g_K  [(size_t)BHh * SS * DKk];      // K natural [bh][s][dk]
__device__ float  g_V  [(size_t)BHh * SS * DKk];      // V natural [bh][s][dk]

// ------------------------- mma / cvt helpers --------------------------------
__device__ __forceinline__ uint32_t f2tf(float f) {
    uint32_t r; asm("cvt.rna.tf32.f32 %0, %1;" : "=r"(r) : "f"(f)); return r;
}
__device__ __forceinline__ void mma_tf32(float c[4], const uint32_t a[4],
                                         uint32_t b0, uint32_t b1) {
    asm volatile(
        "mma.sync.aligned.m16n8k8.row.col.f32.tf32.tf32.f32 "
        "{%0,%1,%2,%3}, {%4,%5,%6,%7}, {%8,%9}, {%0,%1,%2,%3};\n"
        : "+f"(c[0]), "+f"(c[1]), "+f"(c[2]), "+f"(c[3])
        : "r"(a[0]), "r"(a[1]), "r"(a[2]), "r"(a[3]), "r"(b0), "r"(b1));
}

// ------------------------- block reduction helpers --------------------------
__device__ __forceinline__ float bcastSum(float v) {
    __shared__ float sm[8];
    #pragma unroll
    for (int m = 16; m > 0; m >>= 1) v += __shfl_xor_sync(0xffffffffu, v, m);
    int w = threadIdx.x >> 5;
    if ((threadIdx.x & 31) == 0) sm[w] = v;
    __syncthreads();
    if (threadIdx.x < 8) {
        v = sm[threadIdx.x];
        #pragma unroll
        for (int m = 4; m > 0; m >>= 1) v += __shfl_xor_sync(0x000000ffu, v, m);
        if (threadIdx.x == 0) sm[0] = v;
    }
    __syncthreads();
    v = sm[0];
    __syncthreads();
    return v;
}

__device__ __forceinline__ void bcastSum4(float v[4]) {
    __shared__ float sm4[8][4];
    #pragma unroll
    for (int m = 16; m > 0; m >>= 1) {
        #pragma unroll
        for (int c = 0; c < 4; c++) v[c] += __shfl_xor_sync(0xffffffffu, v[c], m);
    }
    int w = threadIdx.x >> 5;
    if ((threadIdx.x & 31) == 0) {
        #pragma unroll
        for (int c = 0; c < 4; c++) sm4[w][c] = v[c];
    }
    __syncthreads();
    if (threadIdx.x < 8) {
        #pragma unroll
        for (int c = 0; c < 4; c++) v[c] = sm4[threadIdx.x][c];
        #pragma unroll
        for (int m = 4; m > 0; m >>= 1) {
            #pragma unroll
            for (int c = 0; c < 4; c++) v[c] += __shfl_xor_sync(0x000000ffu, v[c], m);
        }
        if (threadIdx.x == 0) {
            #pragma unroll
            for (int c = 0; c < 4; c++) sm4[0][c] = v[c];
        }
    }
    __syncthreads();
    #pragma unroll
    for (int c = 0; c < 4; c++) v[c] = sm4[0][c];
    __syncthreads();
}

// ------------------------- prep: build concat B + per-col params ------------
__global__ __launch_bounds__(256) void prep_kernel(
    const float* __restrict__ zq, const float* __restrict__ bq,
    const float* __restrict__ zk, const float* __restrict__ bk,
    const float* __restrict__ wv)
{
    int j = blockIdx.x;
    int tid = threadIdx.x;
    if (j >= 2048) {
        int col = j - 2048;
        for (int d = tid; d < DDm; d += 256)
            g_B[(size_t)d * N3 + j] = wv[(size_t)col * DDm + d];
        return;
    }
    const float* z; const float* bias; int col;
    if (j < 1024) { z = zq; bias = bq; col = j; }
    else          { z = zk; bias = bk; col = j - 1024; }

    float ss = 0.0f;
    for (int d = tid; d < DDm; d += 256) {
        float v = z[(size_t)d * DDm + col];
        ss += v * v;
    }
    ss = bcastSum(ss);
    float zn = fmaxf(sqrtf(ss), 1e-15f);
    float inv = 1.0f / zn;
    for (int d = tid; d < DDm; d += 256)
        g_B[(size_t)d * N3 + j] = z[(size_t)d * DDm + col] * inv;
    if (tid == 0) {
        float r2 = 2.0f * bias[col];
        g_par[j] = make_float4(2.0f * zn, coshf(r2), sinhf(r2), 0.0f);
    }
}

// ------------------------- lambda: per-row 2/(1-||x||^2) --------------------
__global__ __launch_bounds__(256) void lam_kernel(const float* __restrict__ x) {
    int r = blockIdx.x;
    float4 v = *(const float4*)(x + (size_t)r * DDm + threadIdx.x * 4);
    float ss = v.x * v.x + v.y * v.y + v.z * v.z + v.w * v.w;
    ss = bcastSum(ss);
    if (threadIdx.x == 0) g_lam[r] = 2.0f / (1.0f - ss);
}

// ------------------------- TF32 GEMM: g_IN = x @ g_B ------------------------
// 128x128x16 block tiles, 256 threads = 8 warps (2 M x 4 N), warp tile 64x32.
// smem stores tf32-converted operands k-major with stride 136
// -> all fragment LDS banks = (8*tig + g) mod 32, conflict-free.
__global__ __launch_bounds__(256, 2) void gemm_tc(const float* __restrict__ A) {
    __shared__ uint32_t As[2][16][136];
    __shared__ uint32_t Bs[2][16][136];

    int tid = threadIdx.x;
    int warp = tid >> 5, lane = tid & 31;
    int g = lane >> 2, tig = lane & 3;
    int wm = warp >> 2, wn = warp & 3;        // wm 0..1, wn 0..3
    int m0 = blockIdx.y * 128, n0 = blockIdx.x * 128;

    int arow = tid >> 1;                      // 0..127
    int akg  = (tid & 1) * 8;                 // 0 or 8
    int brow = tid >> 5;                      // 0..7
    int bcol = (tid & 31) * 4;                // 0..124
    const float* Ap = A + (size_t)(m0 + arow) * DDm + akg;
    const float* Bp = g_B + (size_t)brow * N3 + n0 + bcol;

    float4 a0 = *(const float4*)Ap;
    float4 a1 = *(const float4*)(Ap + 4);
    float4 b0v = *(const float4*)Bp;
    float4 b1v = *(const float4*)(Bp + (size_t)8 * N3);

    float acc[4][4][4];
    #pragma unroll
    for (int mi = 0; mi < 4; mi++)
        #pragma unroll
        for (int ni = 0; ni < 4; ni++)
            #pragma unroll
            for (int c = 0; c < 4; c++) acc[mi][ni][c] = 0.0f;

    // fill buf 0
    As[0][akg + 0][arow] = f2tf(a0.x); As[0][akg + 1][arow] = f2tf(a0.y);
    As[0][akg + 2][arow] = f2tf(a0.z); As[0][akg + 3][arow] = f2tf(a0.w);
    As[0][akg + 4][arow] = f2tf(a1.x); As[0][akg + 5][arow] = f2tf(a1.y);
    As[0][akg + 6][arow] = f2tf(a1.z); As[0][akg + 7][arow] = f2tf(a1.w);
    Bs[0][brow][bcol + 0] = f2tf(b0v.x); Bs[0][brow][bcol + 1] = f2tf(b0v.y);
    Bs[0][brow][bcol + 2] = f2tf(b0v.z); Bs[0][brow][bcol + 3] = f2tf(b0v.w);
    Bs[0][brow + 8][bcol + 0] = f2tf(b1v.x); Bs[0][brow + 8][bcol + 1] = f2tf(b1v.y);
    Bs[0][brow + 8][bcol + 2] = f2tf(b1v.z); Bs[0][brow + 8][bcol + 3] = f2tf(b1v.w);
    __syncthreads();

    int buf = 0;
    for (int kt = 0; kt < 64; kt++) {
        if (kt < 63) {
            a0  = *(const float4*)(Ap + (size_t)(kt + 1) * 16);
            a1  = *(const float4*)(Ap + (size_t)(kt + 1) * 16 + 4);
            b0v = *(const float4*)(Bp + (size_t)(kt + 1) * 16 * N3);
            b1v = *(const float4*)(Bp + (size_t)((kt + 1) * 16 + 8) * N3);
        }
        #pragma unroll
        for (int kk = 0; kk < 2; kk++) {
            int kb = kk * 8;
            uint32_t af[4][4];
            #pragma unroll
            for (int mi = 0; mi < 4; mi++) {
                int mr = wm * 64 + mi * 16 + g;
                af[mi][0] = As[buf][kb + tig    ][mr];
                af[mi][1] = As[buf][kb + tig    ][mr + 8];
                af[mi][2] = As[buf][kb + tig + 4][mr];
                af[mi][3] = As[buf][kb + tig + 4][mr + 8];
            }
            uint32_t bf0[4], bf1[4];
            #pragma unroll
            for (int ni = 0; ni < 4; ni++) {
                int nc = wn * 32 + ni * 8 + g;
                bf0[ni] = Bs[buf][kb + tig    ][nc];
                bf1[ni] = Bs[buf][kb + tig + 4][nc];
            }
            #pragma unroll
            for (int mi = 0; mi < 4; mi++)
                #pragma unroll
                for (int ni = 0; ni < 4; ni++)
                    mma_tf32(acc[mi][ni], af[mi], bf0[ni], bf1[ni]);
        }
        if (kt < 63) {
            int nb = buf ^ 1;
            As[nb][akg + 0][arow] = f2tf(a0.x); As[nb][akg + 1][arow] = f2tf(a0.y);
            As[nb][akg + 2][arow] = f2tf(a0.z); As[nb][akg + 3][arow] = f2tf(a0.w);
            As[nb][akg + 4][arow] = f2tf(a1.x); As[nb][akg + 5][arow] = f2tf(a1.y);
            As[nb][akg + 6][arow] = f2tf(a1.z); As[nb][akg + 7][arow] = f2tf(a1.w);
            Bs[nb][brow][bcol + 0] = f2tf(b0v.x); Bs[nb][brow][bcol + 1] = f2tf(b0v.y);
            Bs[nb][brow][bcol + 2] = f2tf(b0v.z); Bs[nb][brow][bcol + 3] = f2tf(b0v.w);
            Bs[nb][brow + 8][bcol + 0] = f2tf(b1v.x); Bs[nb][brow + 8][bcol + 1] = f2tf(b1v.y);
            Bs[nb][brow + 8][bcol + 2] = f2tf(b1v.z); Bs[nb][brow + 8][bcol + 3] = f2tf(b1v.w);
            buf = nb;
        }
        __syncthreads();
    }

    // epilogue: fp32 accumulators -> g_IN
    #pragma unroll
    for (int mi = 0; mi < 4; mi++) {
        int mr = m0 + wm * 64 + mi * 16 + g;
        #pragma unroll
        for (int ni = 0; ni < 4; ni++) {
            int nc = n0 + wn * 32 + ni * 8 + tig * 2;
            *(float2*)(g_IN + (size_t)mr * N3 + nc) =
                make_float2(acc[mi][ni][0], acc[mi][ni][1]);
            *(float2*)(g_IN + (size_t)(mr + 8) * N3 + nc) =
                make_float2(acc[mi][ni][2], acc[mi][ni][3]);
        }
    }
}

// ------------------------- epilogue: Poincare map + layouts -----------------
__global__ __launch_bounds__(256) void epi_kernel(const float* __restrict__ bvp) {
    int r0 = blockIdx.x * 4;
    int b  = r0 >> 11;
    int s0 = r0 & 2047;
    int tid = threadIdx.x;
    int j0 = tid * 4;
    int h  = j0 >> 6, dk = j0 & 63;

    float lamv[4];
    *(float4*)lamv = *(const float4*)(g_lam + r0);

    float wq[4][4];
    // ---------------- Q ----------------
    {
        float4 par[4];
        #pragma unroll
        for (int c = 0; c < 4; c++) par[c] = g_par[j0 + c];
        float ws[4] = {0.f, 0.f, 0.f, 0.f};
        #pragma unroll
        for (int ri = 0; ri < 4; ri++) {
            float lam = lamv[ri], lm1 = lam - 1.0f;
            float4 inn = *(const float4*)(g_IN + (size_t)(r0 + ri) * N3 + j0);
            float innv[4] = {inn.x, inn.y, inn.z, inn.w};
            #pragma unroll
            for (int c = 0; c < 4; c++) {
                float arg = lam * innv[c] * par[c].y - lm1 * par[c].z;
                float t   = arg + sqrtf(arg * arg + 1.0f);
                float u   = par[c].x * __logf(t);
                float eu  = __expf(u);
                float w   = 0.5f * (eu - __fdividef(1.0f, eu));
                wq[ri][c] = w;
                ws[ri] += w * w;
            }
        }
        bcastSum4(ws);
        #pragma unroll
        for (int ri = 0; ri < 4; ri++) {
            float scl = 0.125f / (1.0f + sqrtf(1.0f + ws[ri]));   // fold 1/sqrt(Dk)
            float4 ov = make_float4(wq[ri][0] * scl, wq[ri][1] * scl,
                                    wq[ri][2] * scl, wq[ri][3] * scl);
            *(float4*)(g_Q + ((size_t)(b * 16 + h) * SS + s0 + ri) * DKk + dk) = ov;
        }
    }
    // ---------------- K ----------------
    {
        float4 par[4];
        #pragma unroll
        for (int c = 0; c < 4; c++) par[c] = g_par[1024 + j0 + c];
        float ws2[4] = {0.f, 0.f, 0.f, 0.f};
        #pragma unroll
        for (int ri = 0; ri < 4; ri++) {
            float lam = lamv[ri], lm1 = lam - 1.0f;
            float4 inn = *(const float4*)(g_IN + (size_t)(r0 + ri) * N3 + 1024 + j0);
            float innv[4] = {inn.x, inn.y, inn.z, inn.w};
            #pragma unroll
            for (int c = 0; c < 4; c++) {
                float arg = lam * innv[c] * par[c].y - lm1 * par[c].z;
                float t   = arg + sqrtf(arg * arg + 1.0f);
                float u   = par[c].x * __logf(t);
                float eu  = __expf(u);
                float w   = 0.5f * (eu - __fdividef(1.0f, eu));
                wq[ri][c] = w;
                ws2[ri] += w * w;
            }
        }
        bcastSum4(ws2);
        #pragma unroll
        for (int ri = 0; ri < 4; ri++) {
            float scl = 1.0f / (1.0f + sqrtf(1.0f + ws2[ri]));
            float4 ov = make_float4(wq[ri][0] * scl, wq[ri][1] * scl,
                                    wq[ri][2] * scl, wq[ri][3] * scl);
            *(float4*)(g_K + ((size_t)(b * 16 + h) * SS + s0 + ri) * DKk + dk) = ov;
        }
    }
    // ---------------- V ----------------
    {
        float4 bvv = *(const float4*)(bvp + j0);
        #pragma unroll
        for (int ri = 0; ri < 4; ri++) {
            float4 inn = *(const float4*)(g_IN + (size_t)(r0 + ri) * N3 + 2048 + j0);
            float4 ov = make_float4(inn.x + bvv.x, inn.y + bvv.y,
                                    inn.z + bvv.z, inn.w + bvv.w);
            *(float4*)(g_V + ((size_t)(b * 16 + h) * SS + s0 + ri) * DKk + dk) = ov;
        }
    }
}

// ------------------------- flash attention (tf32 mma.sync) ------------------
__global__ __launch_bounds__(256, 2) void attn_kernel(float* __restrict__ out) {
    __shared__ float sK[64][68];
    __shared__ float sV[64][72];

    int tid  = threadIdx.x;
    int warp = tid >> 5, lane = tid & 31;
    int g = lane >> 2, tig = lane & 3;
    int bh = blockIdx.y;
    int b  = bh >> 4, h = bh & 15;
    int q0 = blockIdx.x * 128;
    int wq = warp * 16;

    const float* Qp = g_Q + ((size_t)bh * SS + q0 + wq) * DKk;
    const float* Kg = g_K + (size_t)bh * SS * DKk;
    const float* Vg = g_V + (size_t)bh * SS * DKk;

    uint32_t qa[8][4];
    #pragma unroll
    for (int kt = 0; kt < 8; kt++) {
        qa[kt][0] = f2tf(Qp[(size_t)g        * DKk + kt * 8 + tig]);
        qa[kt][1] = f2tf(Qp[(size_t)(g + 8)  * DKk + kt * 8 + tig]);
        qa[kt][2] = f2tf(Qp[(size_t)g        * DKk + kt * 8 + tig + 4]);
        qa[kt][3] = f2tf(Qp[(size_t)(g + 8)  * DKk + kt * 8 + tig + 4]);
    }

    float o[8][4];
    #pragma unroll
    for (int n = 0; n < 8; n++)
        #pragma unroll
        for (int c = 0; c < 4; c++) o[n][c] = 0.0f;
    float m0 = -1e30f, m1 = -1e30f, l0 = 0.0f, l1 = 0.0f;

    int lr = tid >> 4;
    int lc = (tid & 15) * 4;

    for (int it = 0; it < SS / 64; it++) {
        int kc0 = it * 64;
        __syncthreads();
        #pragma unroll
        for (int i = 0; i < 4; i++) {
            int rr = lr + i * 16;
            *(float4*)&sK[rr][lc] = *(const float4*)(Kg + (size_t)(kc0 + rr) * DKk + lc);
            *(float4*)&sV[rr][lc] = *(const float4*)(Vg + (size_t)(kc0 + rr) * DKk + lc);
        }
        __syncthreads();

        float p[8][4];
        #pragma unroll
        for (int n = 0; n < 8; n++)
            #pragma unroll
            for (int c = 0; c < 4; c++) p[n][c] = 0.0f;
        #pragma unroll
        for (int k0 = 0; k0 < 8; k0++) {
            #pragma unroll
            for (int n0 = 0; n0 < 8; n0++) {
                uint32_t b0 = f2tf(sK[n0 * 8 + g][k0 * 8 + tig]);
                uint32_t b1 = f2tf(sK[n0 * 8 + g][k0 * 8 + tig + 4]);
                mma_tf32(p[n0], qa[k0], b0, b1);
            }
        }

        float rm0 = -1e30f, rm1 = -1e30f;
        #pragma unroll
        for (int n = 0; n < 8; n++) {
            rm0 = fmaxf(rm0, fmaxf(p[n][0], p[n][1]));
            rm1 = fmaxf(rm1, fmaxf(p[n][2], p[n][3]));
        }
        rm0 = fmaxf(rm0, __shfl_xor_sync(0xffffffffu, rm0, 1));
        rm0 = fmaxf(rm0, __shfl_xor_sync(0xffffffffu, rm0, 2));
        rm1 = fmaxf(rm1, __shfl_xor_sync(0xffffffffu, rm1, 1));
        rm1 = fmaxf(rm1, __shfl_xor_sync(0xffffffffu, rm1, 2));
        float mn0 = fmaxf(m0, rm0), mn1 = fmaxf(m1, rm1);
        float al0 = __expf(m0 - mn0), al1 = __expf(m1 - mn1);
        m0 = mn0; m1 = mn1;
        float rs0 = 0.0f, rs1 = 0.0f;
        #pragma unroll
        for (int n = 0; n < 8; n++) {
            p[n][0] = __expf(p[n][0] - m0);
            p[n][1] = __expf(p[n][1] - m0);
            p[n][2] = __expf(p[n][2] - m1);
            p[n][3] = __expf(p[n][3] - m1);
            rs0 += p[n][0] + p[n][1];
            rs1 += p[n][2] + p[n][3];
        }
        rs0 += __shfl_xor_sync(0xffffffffu, rs0, 1);
        rs0 += __shfl_xor_sync(0xffffffffu, rs0, 2);
        rs1 += __shfl_xor_sync(0xffffffffu, rs1, 1);
        rs1 += __shfl_xor_sync(0xffffffffu, rs1, 2);
        l0 = l0 * al0 + rs0;
        l1 = l1 * al1 + rs1;
        #pragma unroll
        for (int n = 0; n < 8; n++) {
            o[n][0] *= al0; o[n][1] *= al0;
            o[n][2] *= al1; o[n][3] *= al1;
        }

        unsigned base = lane & ~3u;
        int hs = base + (tig >> 1);
        bool odd = tig & 1;
        #pragma unroll
        for (int kt = 0; kt < 8; kt++) {
            float v0 = __shfl_sync(0xffffffffu, p[kt][0], hs);
            float v1 = __shfl_sync(0xffffffffu, p[kt][1], hs);
            float v2 = __shfl_sync(0xffffffffu, p[kt][0], hs + 2);
            float v3 = __shfl_sync(0xffffffffu, p[kt][1], hs + 2);
            float w0 = __shfl_sync(0xffffffffu, p[kt][2], hs);
            float w1 = __shfl_sync(0xffffffffu, p[kt][3], hs);
            float w2 = __shfl_sync(0xffffffffu, p[kt][2], hs + 2);
            float w3 = __shfl_sync(0xffffffffu, p[kt][3], hs + 2);
            uint32_t a[4];
            a[0] = f2tf(odd ? v1 : v0);
            a[1] = f2tf(odd ? w1 : w0);
            a[2] = f2tf(odd ? v3 : v2);
            a[3] = f2tf(odd ? w3 : w2);
            #pragma unroll
            for (int n0 = 0; n0 < 8; n0++) {
                uint32_t b0 = f2tf(sV[kt * 8 + tig][n0 * 8 + g]);
                uint32_t b1 = f2tf(sV[kt * 8 + tig + 4][n0 * 8 + g]);
                mma_tf32(o[n0], a, b0, b1);
            }
        }
    }

    float inv0 = 1.0f / l0, inv1 = 1.0f / l1;
    int s0r = q0 + wq + g;
    #pragma unroll
    for (int n0 = 0; n0 < 8; n0++) {
        int dk = n0 * 8 + 2 * tig;
        float2 ov0 = make_float2(o[n0][0] * inv0, o[n0][1] * inv0);
        float2 ov1 = make_float2(o[n0][2] * inv1, o[n0][3] * inv1);
        *(float2*)(out + ((size_t)(b * SS + s0r)     ) * DDm + h * 64 + dk) = ov0;
        *(float2*)(out + ((size_t)(b * SS + s0r + 8) ) * DDm + h * 64 + dk) = ov1;
    }
}

// ------------------------- launcher ----------------------------------------
extern "C" void kernel_launch(void* const* d_in, const int* in_sizes, int n_in,
                              void* d_out, int out_size) {
    const float* x  = (const float*)d_in[0];
    const float* zq = (const float*)d_in[1];
    const float* bq = (const float*)d_in[2];
    const float* zk = (const float*)d_in[3];
    const float* bk = (const float*)d_in[4];
    const float* wv = (const float*)d_in[5];
    const float* bv = (const float*)d_in[6];
    float* out = (float*)d_out;

    prep_kernel<<<N3, 256>>>(zq, bq, zk, bk, wv);
    lam_kernel<<<BSr, 256>>>(x);
    gemm_tc<<<dim3(N3 / 128, BSr / 128), 256>>>(x);
    epi_kernel<<<BSr / 4, 256>>>(bv);
    attn_kernel<<<dim3(SS / 128, BHh), 256>>>(out);
}

// round 5
// speedup vs baseline: 2.9292x; 1.0944x over previous
#include <cuda_runtime.h>
#include <cstdint>

// Problem constants
#define BB  4
#define SS  2048
#define DDm 1024
#define HHn 16
#define DKk 64
#define BSr (BB*SS)     // 8192 rows
#define N3  3072        // concat of Q|K|V projection outputs
#define BHh (BB*HHn)    // 64 head-batches

// ------------------------- scratch (static device memory) -------------------
__device__ float  g_B  [DDm * N3];                    // [1024][3072] tf32-rounded B matrix
__device__ float  g_Xc [(size_t)BSr * DDm];           // tf32-rounded copy of x
__device__ float  g_IN [(size_t)BSr * N3];            // [8192][3072] raw projections
__device__ float  g_lam[BSr];                         // per-row lambda
__device__ float4 g_par[2048];                        // per-col {2*zn, cosh2r, sinh2r, 0}
__device__ float  g_Q  [(size_t)BHh * SS * DKk];      // tf32-rounded, pre-scaled 1/8
__device__ float  g_K  [(size_t)BHh * SS * DKk];      // tf32-rounded
__device__ float  g_V  [(size_t)BHh * SS * DKk];      // tf32-rounded

// ------------------------- mma / cvt helpers --------------------------------
__device__ __forceinline__ uint32_t f2tf(float f) {
    uint32_t r; asm("cvt.rna.tf32.f32 %0, %1;" : "=r"(r) : "f"(f)); return r;
}
__device__ __forceinline__ float f2tf_f(float f) {
    uint32_t r = f2tf(f); return __uint_as_float(r);
}
__device__ __forceinline__ void mma_tf32(float c[4], const uint32_t a[4],
                                         uint32_t b0, uint32_t b1) {
    asm volatile(
        "mma.sync.aligned.m16n8k8.row.col.f32.tf32.tf32.f32 "
        "{%0,%1,%2,%3}, {%4,%5,%6,%7}, {%8,%9}, {%0,%1,%2,%3};\n"
        : "+f"(c[0]), "+f"(c[1]), "+f"(c[2]), "+f"(c[3])
        : "r"(a[0]), "r"(a[1]), "r"(a[2]), "r"(a[3]), "r"(b0), "r"(b1));
}

// ------------------------- block reduction helpers --------------------------
__device__ __forceinline__ float bcastSum(float v) {
    __shared__ float sm[8];
    #pragma unroll
    for (int m = 16; m > 0; m >>= 1) v += __shfl_xor_sync(0xffffffffu, v, m);
    int w = threadIdx.x >> 5;
    if ((threadIdx.x & 31) == 0) sm[w] = v;
    __syncthreads();
    if (threadIdx.x < 8) {
        v = sm[threadIdx.x];
        #pragma unroll
        for (int m = 4; m > 0; m >>= 1) v += __shfl_xor_sync(0x000000ffu, v, m);
        if (threadIdx.x == 0) sm[0] = v;
    }
    __syncthreads();
    v = sm[0];
    __syncthreads();
    return v;
}

__device__ __forceinline__ void bcastSum4(float v[4]) {
    __shared__ float sm4[8][4];
    #pragma unroll
    for (int m = 16; m > 0; m >>= 1) {
        #pragma unroll
        for (int c = 0; c < 4; c++) v[c] += __shfl_xor_sync(0xffffffffu, v[c], m);
    }
    int w = threadIdx.x >> 5;
    if ((threadIdx.x & 31) == 0) {
        #pragma unroll
        for (int c = 0; c < 4; c++) sm4[w][c] = v[c];
    }
    __syncthreads();
    if (threadIdx.x < 8) {
        #pragma unroll
        for (int c = 0; c < 4; c++) v[c] = sm4[threadIdx.x][c];
        #pragma unroll
        for (int m = 4; m > 0; m >>= 1) {
            #pragma unroll
            for (int c = 0; c < 4; c++) v[c] += __shfl_xor_sync(0x000000ffu, v[c], m);
        }
        if (threadIdx.x == 0) {
            #pragma unroll
            for (int c = 0; c < 4; c++) sm4[0][c] = v[c];
        }
    }
    __syncthreads();
    #pragma unroll
    for (int c = 0; c < 4; c++) v[c] = sm4[0][c];
    __syncthreads();
}

// ------------------------- prep: build concat B + per-col params ------------
__global__ __launch_bounds__(256) void prep_kernel(
    const float* __restrict__ zq, const float* __restrict__ bq,
    const float* __restrict__ zk, const float* __restrict__ bk,
    const float* __restrict__ wv)
{
    int j = blockIdx.x;
    int tid = threadIdx.x;
    if (j >= 2048) {
        int col = j - 2048;
        for (int d = tid; d < DDm; d += 256)
            g_B[(size_t)d * N3 + j] = f2tf_f(wv[(size_t)col * DDm + d]);
        return;
    }
    const float* z; const float* bias; int col;
    if (j < 1024) { z = zq; bias = bq; col = j; }
    else          { z = zk; bias = bk; col = j - 1024; }

    float ss = 0.0f;
    for (int d = tid; d < DDm; d += 256) {
        float v = z[(size_t)d * DDm + col];
        ss += v * v;
    }
    ss = bcastSum(ss);
    float zn = fmaxf(sqrtf(ss), 1e-15f);
    float inv = 1.0f / zn;
    for (int d = tid; d < DDm; d += 256)
        g_B[(size_t)d * N3 + j] = f2tf_f(z[(size_t)d * DDm + col] * inv);
    if (tid == 0) {
        float r2 = 2.0f * bias[col];
        g_par[j] = make_float4(2.0f * zn, coshf(r2), sinhf(r2), 0.0f);
    }
}

// ------------- lambda + tf32-rounded copy of x (single pass over x) ---------
__global__ __launch_bounds__(256) void lam_kernel(const float* __restrict__ x) {
    int r = blockIdx.x;
    float4 v = *(const float4*)(x + (size_t)r * DDm + threadIdx.x * 4);
    float ss = v.x * v.x + v.y * v.y + v.z * v.z + v.w * v.w;
    float4 cv = make_float4(f2tf_f(v.x), f2tf_f(v.y), f2tf_f(v.z), f2tf_f(v.w));
    *(float4*)(g_Xc + (size_t)r * DDm + threadIdx.x * 4) = cv;
    ss = bcastSum(ss);
    if (threadIdx.x == 0) g_lam[r] = 2.0f / (1.0f - ss);
}

// ------------------------- TF32 GEMM: g_IN = g_Xc @ g_B ---------------------
// operands pre-rounded to tf32 -> fill is pure copy, MMA reads raw bits.
__global__ __launch_bounds__(256, 2) void gemm_tc() {
    __shared__ uint32_t As[2][16][136];
    __shared__ uint32_t Bs[2][16][136];

    int tid = threadIdx.x;
    int warp = tid >> 5, lane = tid & 31;
    int g = lane >> 2, tig = lane & 3;
    int wm = warp >> 2, wn = warp & 3;
    int m0 = blockIdx.y * 128, n0 = blockIdx.x * 128;

    int arow = tid >> 1;
    int akg  = (tid & 1) * 8;
    int brow = tid >> 5;
    int bcol = (tid & 31) * 4;
    const float* Ap = g_Xc + (size_t)(m0 + arow) * DDm + akg;
    const float* Bp = g_B + (size_t)brow * N3 + n0 + bcol;

    uint4 a0 = *(const uint4*)Ap;
    uint4 a1 = *(const uint4*)(Ap + 4);
    uint4 b0v = *(const uint4*)Bp;
    uint4 b1v = *(const uint4*)(Bp + (size_t)8 * N3);

    float acc[4][4][4];
    #pragma unroll
    for (int mi = 0; mi < 4; mi++)
        #pragma unroll
        for (int ni = 0; ni < 4; ni++)
            #pragma unroll
            for (int c = 0; c < 4; c++) acc[mi][ni][c] = 0.0f;

    As[0][akg + 0][arow] = a0.x; As[0][akg + 1][arow] = a0.y;
    As[0][akg + 2][arow] = a0.z; As[0][akg + 3][arow] = a0.w;
    As[0][akg + 4][arow] = a1.x; As[0][akg + 5][arow] = a1.y;
    As[0][akg + 6][arow] = a1.z; As[0][akg + 7][arow] = a1.w;
    *(uint4*)&Bs[0][brow][bcol]     = b0v;
    *(uint4*)&Bs[0][brow + 8][bcol] = b1v;
    __syncthreads();

    int buf = 0;
    for (int kt = 0; kt < 64; kt++) {
        if (kt < 63) {
            a0  = *(const uint4*)(Ap + (size_t)(kt + 1) * 16);
            a1  = *(const uint4*)(Ap + (size_t)(kt + 1) * 16 + 4);
            b0v = *(const uint4*)(Bp + (size_t)(kt + 1) * 16 * N3);
            b1v = *(const uint4*)(Bp + (size_t)((kt + 1) * 16 + 8) * N3);
        }
        #pragma unroll
        for (int kk = 0; kk < 2; kk++) {
            int kb = kk * 8;
            uint32_t af[4][4];
            #pragma unroll
            for (int mi = 0; mi < 4; mi++) {
                int mr = wm * 64 + mi * 16 + g;
                af[mi][0] = As[buf][kb + tig    ][mr];
                af[mi][1] = As[buf][kb + tig    ][mr + 8];
                af[mi][2] = As[buf][kb + tig + 4][mr];
                af[mi][3] = As[buf][kb + tig + 4][mr + 8];
            }
            uint32_t bf0[4], bf1[4];
            #pragma unroll
            for (int ni = 0; ni < 4; ni++) {
                int nc = wn * 32 + ni * 8 + g;
                bf0[ni] = Bs[buf][kb + tig    ][nc];
                bf1[ni] = Bs[buf][kb + tig + 4][nc];
            }
            #pragma unroll
            for (int mi = 0; mi < 4; mi++)
                #pragma unroll
                for (int ni = 0; ni < 4; ni++)
                    mma_tf32(acc[mi][ni], af[mi], bf0[ni], bf1[ni]);
        }
        if (kt < 63) {
            int nb = buf ^ 1;
            As[nb][akg + 0][arow] = a0.x; As[nb][akg + 1][arow] = a0.y;
            As[nb][akg + 2][arow] = a0.z; As[nb][akg + 3][arow] = a0.w;
            As[nb][akg + 4][arow] = a1.x; As[nb][akg + 5][arow] = a1.y;
            As[nb][akg + 6][arow] = a1.z; As[nb][akg + 7][arow] = a1.w;
            *(uint4*)&Bs[nb][brow][bcol]     = b0v;
            *(uint4*)&Bs[nb][brow + 8][bcol] = b1v;
            buf = nb;
        }
        __syncthreads();
    }

    #pragma unroll
    for (int mi = 0; mi < 4; mi++) {
        int mr = m0 + wm * 64 + mi * 16 + g;
        #pragma unroll
        for (int ni = 0; ni < 4; ni++) {
            int nc = n0 + wn * 32 + ni * 8 + tig * 2;
            *(float2*)(g_IN + (size_t)mr * N3 + nc) =
                make_float2(acc[mi][ni][0], acc[mi][ni][1]);
            *(float2*)(g_IN + (size_t)(mr + 8) * N3 + nc) =
                make_float2(acc[mi][ni][2], acc[mi][ni][3]);
        }
    }
}

// ------------------------- epilogue: Poincare map + tf32 layouts ------------
__global__ __launch_bounds__(256) void epi_kernel(const float* __restrict__ bvp) {
    int r0 = blockIdx.x * 4;
    int b  = r0 >> 11;
    int s0 = r0 & 2047;
    int tid = threadIdx.x;
    int j0 = tid * 4;
    int h  = j0 >> 6, dk = j0 & 63;

    float lamv[4];
    *(float4*)lamv = *(const float4*)(g_lam + r0);

    float wq[4][4];
    // ---------------- Q ----------------
    {
        float4 par[4];
        #pragma unroll
        for (int c = 0; c < 4; c++) par[c] = g_par[j0 + c];
        float ws[4] = {0.f, 0.f, 0.f, 0.f};
        #pragma unroll
        for (int ri = 0; ri < 4; ri++) {
            float lam = lamv[ri], lm1 = lam - 1.0f;
            float4 inn = *(const float4*)(g_IN + (size_t)(r0 + ri) * N3 + j0);
            float innv[4] = {inn.x, inn.y, inn.z, inn.w};
            #pragma unroll
            for (int c = 0; c < 4; c++) {
                float arg = lam * innv[c] * par[c].y - lm1 * par[c].z;
                float t   = arg + sqrtf(arg * arg + 1.0f);
                float u   = par[c].x * __logf(t);
                float eu  = __expf(u);
                float w   = 0.5f * (eu - __fdividef(1.0f, eu));
                wq[ri][c] = w;
                ws[ri] += w * w;
            }
        }
        bcastSum4(ws);
        #pragma unroll
        for (int ri = 0; ri < 4; ri++) {
            float scl = 0.125f / (1.0f + sqrtf(1.0f + ws[ri]));
            float4 ov = make_float4(f2tf_f(wq[ri][0] * scl), f2tf_f(wq[ri][1] * scl),
                                    f2tf_f(wq[ri][2] * scl), f2tf_f(wq[ri][3] * scl));
            *(float4*)(g_Q + ((size_t)(b * 16 + h) * SS + s0 + ri) * DKk + dk) = ov;
        }
    }
    // ---------------- K ----------------
    {
        float4 par[4];
        #pragma unroll
        for (int c = 0; c < 4; c++) par[c] = g_par[1024 + j0 + c];
        float ws2[4] = {0.f, 0.f, 0.f, 0.f};
        #pragma unroll
        for (int ri = 0; ri < 4; ri++) {
            float lam = lamv[ri], lm1 = lam - 1.0f;
            float4 inn = *(const float4*)(g_IN + (size_t)(r0 + ri) * N3 + 1024 + j0);
            float innv[4] = {inn.x, inn.y, inn.z, inn.w};
            #pragma unroll
            for (int c = 0; c < 4; c++) {
                float arg = lam * innv[c] * par[c].y - lm1 * par[c].z;
                float t   = arg + sqrtf(arg * arg + 1.0f);
                float u   = par[c].x * __logf(t);
                float eu  = __expf(u);
                float w   = 0.5f * (eu - __fdividef(1.0f, eu));
                wq[ri][c] = w;
                ws2[ri] += w * w;
            }
        }
        bcastSum4(ws2);
        #pragma unroll
        for (int ri = 0; ri < 4; ri++) {
            float scl = 1.0f / (1.0f + sqrtf(1.0f + ws2[ri]));
            float4 ov = make_float4(f2tf_f(wq[ri][0] * scl), f2tf_f(wq[ri][1] * scl),
                                    f2tf_f(wq[ri][2] * scl), f2tf_f(wq[ri][3] * scl));
            *(float4*)(g_K + ((size_t)(b * 16 + h) * SS + s0 + ri) * DKk + dk) = ov;
        }
    }
    // ---------------- V ----------------
    {
        float4 bvv = *(const float4*)(bvp + j0);
        #pragma unroll
        for (int ri = 0; ri < 4; ri++) {
            float4 inn = *(const float4*)(g_IN + (size_t)(r0 + ri) * N3 + 2048 + j0);
            float4 ov = make_float4(f2tf_f(inn.x + bvv.x), f2tf_f(inn.y + bvv.y),
                                    f2tf_f(inn.z + bvv.z), f2tf_f(inn.w + bvv.w));
            *(float4*)(g_V + ((size_t)(b * 16 + h) * SS + s0 + ri) * DKk + dk) = ov;
        }
    }
}

// ------------------------- flash attention (tf32 mma.sync) ------------------
// All K/V/Q values pre-rounded to tf32 -> raw bit loads feed MMA directly.
__global__ __launch_bounds__(256, 2) void attn_kernel(float* __restrict__ out) {
    __shared__ float sK[64][68];
    __shared__ float sV[64][72];

    int tid  = threadIdx.x;
    int warp = tid >> 5, lane = tid & 31;
    int g = lane >> 2, tig = lane & 3;
    int bh = blockIdx.y;
    int b  = bh >> 4, h = bh & 15;
    int q0 = blockIdx.x * 128;
    int wq = warp * 16;

    const float* Qp = g_Q + ((size_t)bh * SS + q0 + wq) * DKk;
    const float* Kg = g_K + (size_t)bh * SS * DKk;
    const float* Vg = g_V + (size_t)bh * SS * DKk;

    uint32_t qa[8][4];
    #pragma unroll
    for (int kt = 0; kt < 8; kt++) {
        qa[kt][0] = __float_as_uint(Qp[(size_t)g       * DKk + kt * 8 + tig]);
        qa[kt][1] = __float_as_uint(Qp[(size_t)(g + 8) * DKk + kt * 8 + tig]);
        qa[kt][2] = __float_as_uint(Qp[(size_t)g       * DKk + kt * 8 + tig + 4]);
        qa[kt][3] = __float_as_uint(Qp[(size_t)(g + 8) * DKk + kt * 8 + tig + 4]);
    }

    float o[8][4];
    #pragma unroll
    for (int n = 0; n < 8; n++)
        #pragma unroll
        for (int c = 0; c < 4; c++) o[n][c] = 0.0f;
    float m0 = -1e30f, m1 = -1e30f, l0 = 0.0f, l1 = 0.0f;

    int lr = tid >> 4;
    int lc = (tid & 15) * 4;

    for (int it = 0; it < SS / 64; it++) {
        int kc0 = it * 64;
        __syncthreads();
        #pragma unroll
        for (int i = 0; i < 4; i++) {
            int rr = lr + i * 16;
            *(float4*)&sK[rr][lc] = *(const float4*)(Kg + (size_t)(kc0 + rr) * DKk + lc);
            *(float4*)&sV[rr][lc] = *(const float4*)(Vg + (size_t)(kc0 + rr) * DKk + lc);
        }
        __syncthreads();

        float p[8][4];
        #pragma unroll
        for (int n = 0; n < 8; n++)
            #pragma unroll
            for (int c = 0; c < 4; c++) p[n][c] = 0.0f;
        #pragma unroll
        for (int k0 = 0; k0 < 8; k0++) {
            #pragma unroll
            for (int n0 = 0; n0 < 8; n0++) {
                uint32_t b0 = __float_as_uint(sK[n0 * 8 + g][k0 * 8 + tig]);
                uint32_t b1 = __float_as_uint(sK[n0 * 8 + g][k0 * 8 + tig + 4]);
                mma_tf32(p[n0], qa[k0], b0, b1);
            }
        }

        float rm0 = -1e30f, rm1 = -1e30f;
        #pragma unroll
        for (int n = 0; n < 8; n++) {
            rm0 = fmaxf(rm0, fmaxf(p[n][0], p[n][1]));
            rm1 = fmaxf(rm1, fmaxf(p[n][2], p[n][3]));
        }
        rm0 = fmaxf(rm0, __shfl_xor_sync(0xffffffffu, rm0, 1));
        rm0 = fmaxf(rm0, __shfl_xor_sync(0xffffffffu, rm0, 2));
        rm1 = fmaxf(rm1, __shfl_xor_sync(0xffffffffu, rm1, 1));
        rm1 = fmaxf(rm1, __shfl_xor_sync(0xffffffffu, rm1, 2));
        float mn0 = fmaxf(m0, rm0), mn1 = fmaxf(m1, rm1);
        float al0 = __expf(m0 - mn0), al1 = __expf(m1 - mn1);
        m0 = mn0; m1 = mn1;
        float rs0 = 0.0f, rs1 = 0.0f;
        #pragma unroll
        for (int n = 0; n < 8; n++) {
            p[n][0] = __expf(p[n][0] - m0);
            p[n][1] = __expf(p[n][1] - m0);
            p[n][2] = __expf(p[n][2] - m1);
            p[n][3] = __expf(p[n][3] - m1);
            rs0 += p[n][0] + p[n][1];
            rs1 += p[n][2] + p[n][3];
        }
        rs0 += __shfl_xor_sync(0xffffffffu, rs0, 1);
        rs0 += __shfl_xor_sync(0xffffffffu, rs0, 2);
        rs1 += __shfl_xor_sync(0xffffffffu, rs1, 1);
        rs1 += __shfl_xor_sync(0xffffffffu, rs1, 2);
        l0 = l0 * al0 + rs0;
        l1 = l1 * al1 + rs1;
        #pragma unroll
        for (int n = 0; n < 8; n++) {
            o[n][0] *= al0; o[n][1] *= al0;
            o[n][2] *= al1; o[n][3] *= al1;
        }

        unsigned base = lane & ~3u;
        int hs = base + (tig >> 1);
        bool odd = tig & 1;
        #pragma unroll
        for (int kt = 0; kt < 8; kt++) {
            float v0 = __shfl_sync(0xffffffffu, p[kt][0], hs);
            float v1 = __shfl_sync(0xffffffffu, p[kt][1], hs);
            float v2 = __shfl_sync(0xffffffffu, p[kt][0], hs + 2);
            float v3 = __shfl_sync(0xffffffffu, p[kt][1], hs + 2);
            float w0 = __shfl_sync(0xffffffffu, p[kt][2], hs);
            float w1 = __shfl_sync(0xffffffffu, p[kt][3], hs);
            float w2 = __shfl_sync(0xffffffffu, p[kt][2], hs + 2);
            float w3 = __shfl_sync(0xffffffffu, p[kt][3], hs + 2);
            uint32_t a[4];
            a[0] = f2tf(odd ? v1 : v0);
            a[1] = f2tf(odd ? w1 : w0);
            a[2] = f2tf(odd ? v3 : v2);
            a[3] = f2tf(odd ? w3 : w2);
            #pragma unroll
            for (int n0 = 0; n0 < 8; n0++) {
                uint32_t b0 = __float_as_uint(sV[kt * 8 + tig][n0 * 8 + g]);
                uint32_t b1 = __float_as_uint(sV[kt * 8 + tig + 4][n0 * 8 + g]);
                mma_tf32(o[n0], a, b0, b1);
            }
        }
    }

    float inv0 = 1.0f / l0, inv1 = 1.0f / l1;
    int s0r = q0 + wq + g;
    #pragma unroll
    for (int n0 = 0; n0 < 8; n0++) {
        int dk = n0 * 8 + 2 * tig;
        float2 ov0 = make_float2(o[n0][0] * inv0, o[n0][1] * inv0);
        float2 ov1 = make_float2(o[n0][2] * inv1, o[n0][3] * inv1);
        *(float2*)(out + ((size_t)(b * SS + s0r)     ) * DDm + h * 64 + dk) = ov0;
        *(float2*)(out + ((size_t)(b * SS + s0r + 8) ) * DDm + h * 64 + dk) = ov1;
    }
}

// ------------------------- launcher ----------------------------------------
extern "C" void kernel_launch(void* const* d_in, const int* in_sizes, int n_in,
                              void* d_out, int out_size) {
    const float* x  = (const float*)d_in[0];
    const float* zq = (const float*)d_in[1];
    const float* bq = (const float*)d_in[2];
    const float* zk = (const float*)d_in[3];
    const float* bk = (const float*)d_in[4];
    const float* wv = (const float*)d_in[5];
    const float* bv = (const float*)d_in[6];
    float* out = (float*)d_out;

    prep_kernel<<<N3, 256>>>(zq, bq, zk, bk, wv);
    lam_kernel<<<BSr, 256>>>(x);
    gemm_tc<<<dim3(N3 / 128, BSr / 128), 256>>>();
    epi_kernel<<<BSr / 4, 256>>>(bv);
    attn_kernel<<<dim3(SS / 128, BHh), 256>>>(out);
}

// round 6
// speedup vs baseline: 3.2333x; 1.1038x over previous
#include <cuda_runtime.h>
#include <cstdint>

// Problem constants
#define BB  4
#define SS  2048
#define DDm 1024
#define HHn 16
#define DKk 64
#define BSr (BB*SS)     // 8192 rows
#define N3  3072        // concat of Q|K|V projection outputs
#define BHh (BB*HHn)    // 64 head-batches

// ------------------------- scratch (static device memory) -------------------
__device__ float  g_B  [DDm * N3];                    // tf32-rounded B matrix
__device__ float  g_Xc [(size_t)BSr * DDm];           // tf32-rounded copy of x
__device__ float  g_IN [(size_t)BSr * N3];            // raw projections
__device__ float  g_lam[BSr];                         // per-row lambda
__device__ float4 g_par[2048];                        // per-col {2*zn, cosh2r, sinh2r, 0}
__device__ float  g_Q  [(size_t)BHh * SS * DKk];      // [bh][s][dk] tf32, pre-scaled 1/8
__device__ float  g_K  [(size_t)BHh * SS * DKk];      // [bh][s][dk] tf32
__device__ float  g_Vt [(size_t)BHh * DKk * SS];      // [bh][dk][s] tf32 (TRANSPOSED)

// ------------------------- mma / cvt helpers --------------------------------
__device__ __forceinline__ uint32_t f2tf(float f) {
    uint32_t r; asm("cvt.rna.tf32.f32 %0, %1;" : "=r"(r) : "f"(f)); return r;
}
__device__ __forceinline__ float f2tf_f(float f) {
    uint32_t r = f2tf(f); return __uint_as_float(r);
}
__device__ __forceinline__ void mma_tf32(float c[4], const uint32_t a[4],
                                         uint32_t b0, uint32_t b1) {
    asm volatile(
        "mma.sync.aligned.m16n8k8.row.col.f32.tf32.tf32.f32 "
        "{%0,%1,%2,%3}, {%4,%5,%6,%7}, {%8,%9}, {%0,%1,%2,%3};\n"
        : "+f"(c[0]), "+f"(c[1]), "+f"(c[2]), "+f"(c[3])
        : "r"(a[0]), "r"(a[1]), "r"(a[2]), "r"(a[3]), "r"(b0), "r"(b1));
}
__device__ __forceinline__ void cpasync16(uint32_t saddr, const float* gptr) {
    asm volatile("cp.async.cg.shared.global [%0], [%1], 16;\n"
                 :: "r"(saddr), "l"(gptr) : "memory");
}
#define CP_COMMIT() asm volatile("cp.async.commit_group;\n" ::: "memory")
#define CP_WAIT1()  asm volatile("cp.async.wait_group 1;\n" ::: "memory")
#define CP_WAIT0()  asm volatile("cp.async.wait_group 0;\n" ::: "memory")

// ------------------------- block reduction helpers --------------------------
__device__ __forceinline__ float bcastSum(float v) {
    __shared__ float sm[8];
    #pragma unroll
    for (int m = 16; m > 0; m >>= 1) v += __shfl_xor_sync(0xffffffffu, v, m);
    int w = threadIdx.x >> 5;
    if ((threadIdx.x & 31) == 0) sm[w] = v;
    __syncthreads();
    if (threadIdx.x < 8) {
        v = sm[threadIdx.x];
        #pragma unroll
        for (int m = 4; m > 0; m >>= 1) v += __shfl_xor_sync(0x000000ffu, v, m);
        if (threadIdx.x == 0) sm[0] = v;
    }
    __syncthreads();
    v = sm[0];
    __syncthreads();
    return v;
}

__device__ __forceinline__ void bcastSum4(float v[4]) {
    __shared__ float sm4[8][4];
    #pragma unroll
    for (int m = 16; m > 0; m >>= 1) {
        #pragma unroll
        for (int c = 0; c < 4; c++) v[c] += __shfl_xor_sync(0xffffffffu, v[c], m);
    }
    int w = threadIdx.x >> 5;
    if ((threadIdx.x & 31) == 0) {
        #pragma unroll
        for (int c = 0; c < 4; c++) sm4[w][c] = v[c];
    }
    __syncthreads();
    if (threadIdx.x < 8) {
        #pragma unroll
        for (int c = 0; c < 4; c++) v[c] = sm4[threadIdx.x][c];
        #pragma unroll
        for (int m = 4; m > 0; m >>= 1) {
            #pragma unroll
            for (int c = 0; c < 4; c++) v[c] += __shfl_xor_sync(0x000000ffu, v[c], m);
        }
        if (threadIdx.x == 0) {
            #pragma unroll
            for (int c = 0; c < 4; c++) sm4[0][c] = v[c];
        }
    }
    __syncthreads();
    #pragma unroll
    for (int c = 0; c < 4; c++) v[c] = sm4[0][c];
    __syncthreads();
}

// ------------------------- prep: build concat B + per-col params ------------
__global__ __launch_bounds__(256) void prep_kernel(
    const float* __restrict__ zq, const float* __restrict__ bq,
    const float* __restrict__ zk, const float* __restrict__ bk,
    const float* __restrict__ wv)
{
    int j = blockIdx.x;
    int tid = threadIdx.x;
    if (j >= 2048) {
        int col = j - 2048;
        for (int d = tid; d < DDm; d += 256)
            g_B[(size_t)d * N3 + j] = f2tf_f(wv[(size_t)col * DDm + d]);
        return;
    }
    const float* z; const float* bias; int col;
    if (j < 1024) { z = zq; bias = bq; col = j; }
    else          { z = zk; bias = bk; col = j - 1024; }

    float ss = 0.0f;
    for (int d = tid; d < DDm; d += 256) {
        float v = z[(size_t)d * DDm + col];
        ss += v * v;
    }
    ss = bcastSum(ss);
    float zn = fmaxf(sqrtf(ss), 1e-15f);
    float inv = 1.0f / zn;
    for (int d = tid; d < DDm; d += 256)
        g_B[(size_t)d * N3 + j] = f2tf_f(z[(size_t)d * DDm + col] * inv);
    if (tid == 0) {
        float r2 = 2.0f * bias[col];
        g_par[j] = make_float4(2.0f * zn, coshf(r2), sinhf(r2), 0.0f);
    }
}

// ------------- lambda + tf32-rounded copy of x (single pass over x) ---------
__global__ __launch_bounds__(256) void lam_kernel(const float* __restrict__ x) {
    int r = blockIdx.x;
    float4 v = *(const float4*)(x + (size_t)r * DDm + threadIdx.x * 4);
    float ss = v.x * v.x + v.y * v.y + v.z * v.z + v.w * v.w;
    float4 cv = make_float4(f2tf_f(v.x), f2tf_f(v.y), f2tf_f(v.z), f2tf_f(v.w));
    *(float4*)(g_Xc + (size_t)r * DDm + threadIdx.x * 4) = cv;
    ss = bcastSum(ss);
    if (threadIdx.x == 0) g_lam[r] = 2.0f / (1.0f - ss);
}

// ------------------------- TF32 GEMM: g_IN = g_Xc @ g_B ---------------------
__global__ __launch_bounds__(256, 2) void gemm_tc() {
    __shared__ uint32_t As[2][16][136];
    __shared__ uint32_t Bs[2][16][136];

    int tid = threadIdx.x;
    int warp = tid >> 5, lane = tid & 31;
    int g = lane >> 2, tig = lane & 3;
    int wm = warp >> 2, wn = warp & 3;
    int m0 = blockIdx.y * 128, n0 = blockIdx.x * 128;

    int arow = tid >> 1;
    int akg  = (tid & 1) * 8;
    int brow = tid >> 5;
    int bcol = (tid & 31) * 4;
    const float* Ap = g_Xc + (size_t)(m0 + arow) * DDm + akg;
    const float* Bp = g_B + (size_t)brow * N3 + n0 + bcol;

    uint4 a0 = *(const uint4*)Ap;
    uint4 a1 = *(const uint4*)(Ap + 4);
    uint4 b0v = *(const uint4*)Bp;
    uint4 b1v = *(const uint4*)(Bp + (size_t)8 * N3);

    float acc[4][4][4];
    #pragma unroll
    for (int mi = 0; mi < 4; mi++)
        #pragma unroll
        for (int ni = 0; ni < 4; ni++)
            #pragma unroll
            for (int c = 0; c < 4; c++) acc[mi][ni][c] = 0.0f;

    As[0][akg + 0][arow] = a0.x; As[0][akg + 1][arow] = a0.y;
    As[0][akg + 2][arow] = a0.z; As[0][akg + 3][arow] = a0.w;
    As[0][akg + 4][arow] = a1.x; As[0][akg + 5][arow] = a1.y;
    As[0][akg + 6][arow] = a1.z; As[0][akg + 7][arow] = a1.w;
    *(uint4*)&Bs[0][brow][bcol]     = b0v;
    *(uint4*)&Bs[0][brow + 8][bcol] = b1v;
    __syncthreads();

    int buf = 0;
    for (int kt = 0; kt < 64; kt++) {
        if (kt < 63) {
            a0  = *(const uint4*)(Ap + (size_t)(kt + 1) * 16);
            a1  = *(const uint4*)(Ap + (size_t)(kt + 1) * 16 + 4);
            b0v = *(const uint4*)(Bp + (size_t)(kt + 1) * 16 * N3);
            b1v = *(const uint4*)(Bp + (size_t)((kt + 1) * 16 + 8) * N3);
        }
        #pragma unroll
        for (int kk = 0; kk < 2; kk++) {
            int kb = kk * 8;
            uint32_t af[4][4];
            #pragma unroll
            for (int mi = 0; mi < 4; mi++) {
                int mr = wm * 64 + mi * 16 + g;
                af[mi][0] = As[buf][kb + tig    ][mr];
                af[mi][1] = As[buf][kb + tig    ][mr + 8];
                af[mi][2] = As[buf][kb + tig + 4][mr];
                af[mi][3] = As[buf][kb + tig + 4][mr + 8];
            }
            uint32_t bf0[4], bf1[4];
            #pragma unroll
            for (int ni = 0; ni < 4; ni++) {
                int nc = wn * 32 + ni * 8 + g;
                bf0[ni] = Bs[buf][kb + tig    ][nc];
                bf1[ni] = Bs[buf][kb + tig + 4][nc];
            }
            #pragma unroll
            for (int mi = 0; mi < 4; mi++)
                #pragma unroll
                for (int ni = 0; ni < 4; ni++)
                    mma_tf32(acc[mi][ni], af[mi], bf0[ni], bf1[ni]);
        }
        if (kt < 63) {
            int nb = buf ^ 1;
            As[nb][akg + 0][arow] = a0.x; As[nb][akg + 1][arow] = a0.y;
            As[nb][akg + 2][arow] = a0.z; As[nb][akg + 3][arow] = a0.w;
            As[nb][akg + 4][arow] = a1.x; As[nb][akg + 5][arow] = a1.y;
            As[nb][akg + 6][arow] = a1.z; As[nb][akg + 7][arow] = a1.w;
            *(uint4*)&Bs[nb][brow][bcol]     = b0v;
            *(uint4*)&Bs[nb][brow + 8][bcol] = b1v;
            buf = nb;
        }
        __syncthreads();
    }

    #pragma unroll
    for (int mi = 0; mi < 4; mi++) {
        int mr = m0 + wm * 64 + mi * 16 + g;
        #pragma unroll
        for (int ni = 0; ni < 4; ni++) {
            int nc = n0 + wn * 32 + ni * 8 + tig * 2;
            *(float2*)(g_IN + (size_t)mr * N3 + nc) =
                make_float2(acc[mi][ni][0], acc[mi][ni][1]);
            *(float2*)(g_IN + (size_t)(mr + 8) * N3 + nc) =
                make_float2(acc[mi][ni][2], acc[mi][ni][3]);
        }
    }
}

// ------------------------- epilogue: Poincare map + tf32 layouts ------------
// Q,K natural [bh][s][dk]; V TRANSPOSED [bh][dk][s].
__global__ __launch_bounds__(256) void epi_kernel(const float* __restrict__ bvp) {
    int r0 = blockIdx.x * 4;
    int b  = r0 >> 11;
    int s0 = r0 & 2047;
    int tid = threadIdx.x;
    int j0 = tid * 4;
    int h  = j0 >> 6, dk = j0 & 63;

    float lamv[4];
    *(float4*)lamv = *(const float4*)(g_lam + r0);

    float wq[4][4];
    // ---------------- Q ----------------
    {
        float4 par[4];
        #pragma unroll
        for (int c = 0; c < 4; c++) par[c] = g_par[j0 + c];
        float ws[4] = {0.f, 0.f, 0.f, 0.f};
        #pragma unroll
        for (int ri = 0; ri < 4; ri++) {
            float lam = lamv[ri], lm1 = lam - 1.0f;
            float4 inn = *(const float4*)(g_IN + (size_t)(r0 + ri) * N3 + j0);
            float innv[4] = {inn.x, inn.y, inn.z, inn.w};
            #pragma unroll
            for (int c = 0; c < 4; c++) {
                float arg = lam * innv[c] * par[c].y - lm1 * par[c].z;
                float t   = arg + sqrtf(arg * arg + 1.0f);
                float u   = par[c].x * __logf(t);
                float eu  = __expf(u);
                float w   = 0.5f * (eu - __fdividef(1.0f, eu));
                wq[ri][c] = w;
                ws[ri] += w * w;
            }
        }
        bcastSum4(ws);
        #pragma unroll
        for (int ri = 0; ri < 4; ri++) {
            float scl = 0.125f / (1.0f + sqrtf(1.0f + ws[ri]));
            float4 ov = make_float4(f2tf_f(wq[ri][0] * scl), f2tf_f(wq[ri][1] * scl),
                                    f2tf_f(wq[ri][2] * scl), f2tf_f(wq[ri][3] * scl));
            *(float4*)(g_Q + ((size_t)(b * 16 + h) * SS + s0 + ri) * DKk + dk) = ov;
        }
    }
    // ---------------- K ----------------
    {
        float4 par[4];
        #pragma unroll
        for (int c = 0; c < 4; c++) par[c] = g_par[1024 + j0 + c];
        float ws2[4] = {0.f, 0.f, 0.f, 0.f};
        #pragma unroll
        for (int ri = 0; ri < 4; ri++) {
            float lam = lamv[ri], lm1 = lam - 1.0f;
            float4 inn = *(const float4*)(g_IN + (size_t)(r0 + ri) * N3 + 1024 + j0);
            float innv[4] = {inn.x, inn.y, inn.z, inn.w};
            #pragma unroll
            for (int c = 0; c < 4; c++) {
                float arg = lam * innv[c] * par[c].y - lm1 * par[c].z;
                float t   = arg + sqrtf(arg * arg + 1.0f);
                float u   = par[c].x * __logf(t);
                float eu  = __expf(u);
                float w   = 0.5f * (eu - __fdividef(1.0f, eu));
                wq[ri][c] = w;
                ws2[ri] += w * w;
            }
        }
        bcastSum4(ws2);
        #pragma unroll
        for (int ri = 0; ri < 4; ri++) {
            float scl = 1.0f / (1.0f + sqrtf(1.0f + ws2[ri]));
            float4 ov = make_float4(f2tf_f(wq[ri][0] * scl), f2tf_f(wq[ri][1] * scl),
                                    f2tf_f(wq[ri][2] * scl), f2tf_f(wq[ri][3] * scl));
            *(float4*)(g_K + ((size_t)(b * 16 + h) * SS + s0 + ri) * DKk + dk) = ov;
        }
    }
    // ---------------- V (transposed store) ----------------
    {
        float4 bvv = *(const float4*)(bvp + j0);
        float vv[4][4];
        #pragma unroll
        for (int ri = 0; ri < 4; ri++) {
            float4 inn = *(const float4*)(g_IN + (size_t)(r0 + ri) * N3 + 2048 + j0);
            vv[ri][0] = f2tf_f(inn.x + bvv.x);
            vv[ri][1] = f2tf_f(inn.y + bvv.y);
            vv[ri][2] = f2tf_f(inn.z + bvv.z);
            vv[ri][3] = f2tf_f(inn.w + bvv.w);
        }
        float* Vb = g_Vt + (size_t)(b * 16 + h) * DKk * SS;
        #pragma unroll
        for (int c = 0; c < 4; c++) {
            float4 ov = make_float4(vv[0][c], vv[1][c], vv[2][c], vv[3][c]);
            *(float4*)(Vb + (size_t)(dk + c) * SS + s0) = ov;
        }
    }
}

// ------------------------- flash attention (tf32, permuted-k, cp.async) -----
// grid = (S/128, BH). 256 threads = 8 warps, 16 query rows/warp, K-tile 64.
// k-slot permutation pi(tig)=2tig, pi(tig+4)=2tig+1 applied consistently:
//  - K/V B-fragments load as float2 (conflict-free, stride 72)
//  - QK C-fragment IS the PV A-fragment (zero shuffles)
__global__ __launch_bounds__(256, 2) void attn_kernel(float* __restrict__ out) {
    extern __shared__ float smem[];
    // layout (floats): sK[2][64][72] then sV[2][64][72]
    const int TILE = 64 * 72;
    float* sKb[2] = { smem,          smem + TILE };
    float* sVb[2] = { smem + 2*TILE, smem + 3*TILE };
    uint32_t sbase = (uint32_t)__cvta_generic_to_shared(smem);

    int tid  = threadIdx.x;
    int warp = tid >> 5, lane = tid & 31;
    int g = lane >> 2, tig = lane & 3;
    int bh = blockIdx.y;
    int b  = bh >> 4, h = bh & 15;
    int q0 = blockIdx.x * 128;
    int wq = warp * 16;

    const float* Qp = g_Q  + ((size_t)bh * SS + q0 + wq) * DKk;
    const float* Kg = g_K  + (size_t)bh * SS * DKk;
    const float* Vg = g_Vt + (size_t)bh * DKk * SS;

    // Q A-fragments with permuted k slots: a0=Q[g][2tig], a2=Q[g][2tig+1]
    uint32_t qa[8][4];
    #pragma unroll
    for (int kt = 0; kt < 8; kt++) {
        float2 qr0 = *(const float2*)(Qp + (size_t)g       * DKk + kt * 8 + 2 * tig);
        float2 qr1 = *(const float2*)(Qp + (size_t)(g + 8) * DKk + kt * 8 + 2 * tig);
        qa[kt][0] = __float_as_uint(qr0.x);
        qa[kt][1] = __float_as_uint(qr1.x);
        qa[kt][2] = __float_as_uint(qr0.y);
        qa[kt][3] = __float_as_uint(qr1.y);
    }

    float o[8][4];
    #pragma unroll
    for (int n = 0; n < 8; n++)
        #pragma unroll
        for (int c = 0; c < 4; c++) o[n][c] = 0.0f;
    float m0 = -1e30f, m1 = -1e30f, l0 = 0.0f, l1 = 0.0f;

    // async tile loader: 1024 16B-chunks per array, 4 per thread
    auto load_tile = [&](int buf, int it) {
        int kc0 = it * 64;
        uint32_t sk = sbase + (uint32_t)(buf * TILE) * 4;
        uint32_t sv = sbase + (uint32_t)((2 + buf) * TILE) * 4;
        #pragma unroll
        for (int i = 0; i < 4; i++) {
            int chunk = tid + i * 256;
            int row = chunk >> 4;
            int c4  = (chunk & 15) * 4;
            cpasync16(sk + (uint32_t)(row * 72 + c4) * 4,
                      Kg + (size_t)(kc0 + row) * DKk + c4);
            cpasync16(sv + (uint32_t)(row * 72 + c4) * 4,
                      Vg + (size_t)row * SS + kc0 + c4);
        }
        CP_COMMIT();
    };

    load_tile(0, 0);

    int buf = 0;
    for (int it = 0; it < SS / 64; it++) {
        if (it + 1 < SS / 64) {
            load_tile(buf ^ 1, it + 1);
            CP_WAIT1();
        } else {
            CP_WAIT0();
        }
        __syncthreads();
        const float* sK = sKb[buf];
        const float* sV = sVb[buf];

        // S = Q . K^T ; B-frag: float2 at sK[key][k0*8+2tig]
        float p[8][4];
        #pragma unroll
        for (int n = 0; n < 8; n++)
            #pragma unroll
            for (int c = 0; c < 4; c++) p[n][c] = 0.0f;
        #pragma unroll
        for (int n0 = 0; n0 < 8; n0++) {
            const float* kr = sK + (n0 * 8 + g) * 72 + 2 * tig;
            #pragma unroll
            for (int k0 = 0; k0 < 8; k0++) {
                float2 bv = *(const float2*)(kr + k0 * 8);
                mma_tf32(p[n0], qa[k0], __float_as_uint(bv.x), __float_as_uint(bv.y));
            }
        }

        // online softmax: thread owns (row g: c0,c1), (row g+8: c2,c3)
        float rm0 = -1e30f, rm1 = -1e30f;
        #pragma unroll
        for (int n = 0; n < 8; n++) {
            rm0 = fmaxf(rm0, fmaxf(p[n][0], p[n][1]));
            rm1 = fmaxf(rm1, fmaxf(p[n][2], p[n][3]));
        }
        rm0 = fmaxf(rm0, __shfl_xor_sync(0xffffffffu, rm0, 1));
        rm0 = fmaxf(rm0, __shfl_xor_sync(0xffffffffu, rm0, 2));
        rm1 = fmaxf(rm1, __shfl_xor_sync(0xffffffffu, rm1, 1));
        rm1 = fmaxf(rm1, __shfl_xor_sync(0xffffffffu, rm1, 2));
        float mn0 = fmaxf(m0, rm0), mn1 = fmaxf(m1, rm1);
        float al0 = __expf(m0 - mn0), al1 = __expf(m1 - mn1);
        m0 = mn0; m1 = mn1;
        float rs0 = 0.0f, rs1 = 0.0f;
        #pragma unroll
        for (int n = 0; n < 8; n++) {
            p[n][0] = __expf(p[n][0] - m0);
            p[n][1] = __expf(p[n][1] - m0);
            p[n][2] = __expf(p[n][2] - m1);
            p[n][3] = __expf(p[n][3] - m1);
            rs0 += p[n][0] + p[n][1];
            rs1 += p[n][2] + p[n][3];
        }
        rs0 += __shfl_xor_sync(0xffffffffu, rs0, 1);
        rs0 += __shfl_xor_sync(0xffffffffu, rs0, 2);
        rs1 += __shfl_xor_sync(0xffffffffu, rs1, 1);
        rs1 += __shfl_xor_sync(0xffffffffu, rs1, 2);
        l0 = l0 * al0 + rs0;
        l1 = l1 * al1 + rs1;
        #pragma unroll
        for (int n = 0; n < 8; n++) {
            o[n][0] *= al0; o[n][1] *= al0;
            o[n][2] *= al1; o[n][3] *= al1;
        }

        // O += P . V : C-frag of S is directly the A-frag under pi.
        // a0=P[g][2tig]=p[kt][0], a1=P[g+8][2tig]=p[kt][2],
        // a2=P[g][2tig+1]=p[kt][1], a3=P[g+8][2tig+1]=p[kt][3]
        #pragma unroll
        for (int kt = 0; kt < 8; kt++) {
            uint32_t a[4];
            a[0] = f2tf(p[kt][0]);
            a[1] = f2tf(p[kt][2]);
            a[2] = f2tf(p[kt][1]);
            a[3] = f2tf(p[kt][3]);
            const float* vr = sV + kt * 8 + 2 * tig;
            #pragma unroll
            for (int n0 = 0; n0 < 8; n0++) {
                float2 bv = *(const float2*)(vr + (n0 * 8 + g) * 72);
                mma_tf32(o[n0], a, __float_as_uint(bv.x), __float_as_uint(bv.y));
            }
        }
        __syncthreads();
        buf ^= 1;
    }

    float inv0 = 1.0f / l0, inv1 = 1.0f / l1;
    int s0r = q0 + wq + g;
    #pragma unroll
    for (int n0 = 0; n0 < 8; n0++) {
        int dk = n0 * 8 + 2 * tig;
        float2 ov0 = make_float2(o[n0][0] * inv0, o[n0][1] * inv0);
        float2 ov1 = make_float2(o[n0][2] * inv1, o[n0][3] * inv1);
        *(float2*)(out + ((size_t)(b * SS + s0r)     ) * DDm + h * 64 + dk) = ov0;
        *(float2*)(out + ((size_t)(b * SS + s0r + 8) ) * DDm + h * 64 + dk) = ov1;
    }
}

// ------------------------- launcher ----------------------------------------
extern "C" void kernel_launch(void* const* d_in, const int* in_sizes, int n_in,
                              void* d_out, int out_size) {
    const float* x  = (const float*)d_in[0];
    const float* zq = (const float*)d_in[1];
    const float* bq = (const float*)d_in[2];
    const float* zk = (const float*)d_in[3];
    const float* bk = (const float*)d_in[4];
    const float* wv = (const float*)d_in[5];
    const float* bv = (const float*)d_in[6];
    float* out = (float*)d_out;

    prep_kernel<<<N3, 256>>>(zq, bq, zk, bk, wv);
    lam_kernel<<<BSr, 256>>>(x);
    gemm_tc<<<dim3(N3 / 128, BSr / 128), 256>>>();
    epi_kernel<<<BSr / 4, 256>>>(bv);

    int smem_bytes = 4 * 64 * 72 * 4;   // 73728
    cudaFuncSetAttribute(attn_kernel, cudaFuncAttributeMaxDynamicSharedMemorySize, smem_bytes);
    attn_kernel<<<dim3(SS / 128, BHh), 256, smem_bytes>>>(out);
}

// round 7
// speedup vs baseline: 3.3283x; 1.0294x over previous
#include <cuda_runtime.h>
#include <cstdint>

// Problem constants
#define BB  4
#define SS  2048
#define DDm 1024
#define HHn 16
#define DKk 64
#define BSr (BB*SS)     // 8192 rows
#define N3  3072        // concat of Q|K|V projection outputs
#define BHh (BB*HHn)    // 64 head-batches

// ------------------------- scratch (static device memory) -------------------
__device__ float  g_B  [DDm * N3];                    // tf32-rounded B matrix
__device__ float  g_Xc [(size_t)BSr * DDm];           // tf32-rounded copy of x
__device__ float  g_IN [(size_t)BSr * N3];            // raw projections
__device__ float  g_lam[BSr];                         // per-row lambda
__device__ float4 g_par[2048];                        // per-col {2*zn, cosh2r, sinh2r, 0}
__device__ float  g_Q  [(size_t)BHh * SS * DKk];      // [bh][s][dk] tf32, scaled log2e/8
__device__ float  g_K  [(size_t)BHh * SS * DKk];      // [bh][s][dk] tf32
__device__ float  g_Vt [(size_t)BHh * DKk * SS];      // [bh][dk][s] tf32 (TRANSPOSED)

// ------------------------- mma / cvt helpers --------------------------------
__device__ __forceinline__ uint32_t f2tf(float f) {
    uint32_t r; asm("cvt.rna.tf32.f32 %0, %1;" : "=r"(r) : "f"(f)); return r;
}
__device__ __forceinline__ float f2tf_f(float f) {
    uint32_t r = f2tf(f); return __uint_as_float(r);
}
__device__ __forceinline__ void mma_tf32(float c[4], const uint32_t a[4],
                                         uint32_t b0, uint32_t b1) {
    asm volatile(
        "mma.sync.aligned.m16n8k8.row.col.f32.tf32.tf32.f32 "
        "{%0,%1,%2,%3}, {%4,%5,%6,%7}, {%8,%9}, {%0,%1,%2,%3};\n"
        : "+f"(c[0]), "+f"(c[1]), "+f"(c[2]), "+f"(c[3])
        : "r"(a[0]), "r"(a[1]), "r"(a[2]), "r"(a[3]), "r"(b0), "r"(b1));
}
__device__ __forceinline__ void cpasync16(uint32_t saddr, const float* gptr) {
    asm volatile("cp.async.cg.shared.global [%0], [%1], 16;\n"
                 :: "r"(saddr), "l"(gptr) : "memory");
}
#define CP_COMMIT() asm volatile("cp.async.commit_group;\n" ::: "memory")
#define CP_WAIT1()  asm volatile("cp.async.wait_group 1;\n" ::: "memory")
#define CP_WAIT0()  asm volatile("cp.async.wait_group 0;\n" ::: "memory")

// ------------------------- block reduction helpers --------------------------
__device__ __forceinline__ float bcastSum(float v) {
    __shared__ float sm[8];
    #pragma unroll
    for (int m = 16; m > 0; m >>= 1) v += __shfl_xor_sync(0xffffffffu, v, m);
    int w = threadIdx.x >> 5;
    if ((threadIdx.x & 31) == 0) sm[w] = v;
    __syncthreads();
    if (threadIdx.x < 8) {
        v = sm[threadIdx.x];
        #pragma unroll
        for (int m = 4; m > 0; m >>= 1) v += __shfl_xor_sync(0x000000ffu, v, m);
        if (threadIdx.x == 0) sm[0] = v;
    }
    __syncthreads();
    v = sm[0];
    __syncthreads();
    return v;
}

__device__ __forceinline__ void bcastSum4(float v[4]) {
    __shared__ float sm4[8][4];
    #pragma unroll
    for (int m = 16; m > 0; m >>= 1) {
        #pragma unroll
        for (int c = 0; c < 4; c++) v[c] += __shfl_xor_sync(0xffffffffu, v[c], m);
    }
    int w = threadIdx.x >> 5;
    if ((threadIdx.x & 31) == 0) {
        #pragma unroll
        for (int c = 0; c < 4; c++) sm4[w][c] = v[c];
    }
    __syncthreads();
    if (threadIdx.x < 8) {
        #pragma unroll
        for (int c = 0; c < 4; c++) v[c] = sm4[threadIdx.x][c];
        #pragma unroll
        for (int m = 4; m > 0; m >>= 1) {
            #pragma unroll
            for (int c = 0; c < 4; c++) v[c] += __shfl_xor_sync(0x000000ffu, v[c], m);
        }
        if (threadIdx.x == 0) {
            #pragma unroll
            for (int c = 0; c < 4; c++) sm4[0][c] = v[c];
        }
    }
    __syncthreads();
    #pragma unroll
    for (int c = 0; c < 4; c++) v[c] = sm4[0][c];
    __syncthreads();
}

// ------------------------- prep: build concat B + per-col params ------------
__global__ __launch_bounds__(256) void prep_kernel(
    const float* __restrict__ zq, const float* __restrict__ bq,
    const float* __restrict__ zk, const float* __restrict__ bk,
    const float* __restrict__ wv)
{
    int j = blockIdx.x;
    int tid = threadIdx.x;
    if (j >= 2048) {
        int col = j - 2048;
        for (int d = tid; d < DDm; d += 256)
            g_B[(size_t)d * N3 + j] = f2tf_f(wv[(size_t)col * DDm + d]);
        return;
    }
    const float* z; const float* bias; int col;
    if (j < 1024) { z = zq; bias = bq; col = j; }
    else          { z = zk; bias = bk; col = j - 1024; }

    float ss = 0.0f;
    for (int d = tid; d < DDm; d += 256) {
        float v = z[(size_t)d * DDm + col];
        ss += v * v;
    }
    ss = bcastSum(ss);
    float zn = fmaxf(sqrtf(ss), 1e-15f);
    float inv = 1.0f / zn;
    for (int d = tid; d < DDm; d += 256)
        g_B[(size_t)d * N3 + j] = f2tf_f(z[(size_t)d * DDm + col] * inv);
    if (tid == 0) {
        float r2 = 2.0f * bias[col];
        g_par[j] = make_float4(2.0f * zn, coshf(r2), sinhf(r2), 0.0f);
    }
}

// ------------- lambda + tf32-rounded copy of x (single pass over x) ---------
__global__ __launch_bounds__(256) void lam_kernel(const float* __restrict__ x) {
    int r = blockIdx.x;
    float4 v = *(const float4*)(x + (size_t)r * DDm + threadIdx.x * 4);
    float ss = v.x * v.x + v.y * v.y + v.z * v.z + v.w * v.w;
    float4 cv = make_float4(f2tf_f(v.x), f2tf_f(v.y), f2tf_f(v.z), f2tf_f(v.w));
    *(float4*)(g_Xc + (size_t)r * DDm + threadIdx.x * 4) = cv;
    ss = bcastSum(ss);
    if (threadIdx.x == 0) g_lam[r] = 2.0f / (1.0f - ss);
}

// ------------------------- TF32 GEMM: g_IN = g_Xc @ g_B ---------------------
__global__ __launch_bounds__(256, 2) void gemm_tc() {
    __shared__ uint32_t As[2][16][136];
    __shared__ uint32_t Bs[2][16][136];

    int tid = threadIdx.x;
    int warp = tid >> 5, lane = tid & 31;
    int g = lane >> 2, tig = lane & 3;
    int wm = warp >> 2, wn = warp & 3;
    int m0 = blockIdx.y * 128, n0 = blockIdx.x * 128;

    int arow = tid >> 1;
    int akg  = (tid & 1) * 8;
    int brow = tid >> 5;
    int bcol = (tid & 31) * 4;
    const float* Ap = g_Xc + (size_t)(m0 + arow) * DDm + akg;
    const float* Bp = g_B + (size_t)brow * N3 + n0 + bcol;

    uint4 a0 = *(const uint4*)Ap;
    uint4 a1 = *(const uint4*)(Ap + 4);
    uint4 b0v = *(const uint4*)Bp;
    uint4 b1v = *(const uint4*)(Bp + (size_t)8 * N3);

    float acc[4][4][4];
    #pragma unroll
    for (int mi = 0; mi < 4; mi++)
        #pragma unroll
        for (int ni = 0; ni < 4; ni++)
            #pragma unroll
            for (int c = 0; c < 4; c++) acc[mi][ni][c] = 0.0f;

    As[0][akg + 0][arow] = a0.x; As[0][akg + 1][arow] = a0.y;
    As[0][akg + 2][arow] = a0.z; As[0][akg + 3][arow] = a0.w;
    As[0][akg + 4][arow] = a1.x; As[0][akg + 5][arow] = a1.y;
    As[0][akg + 6][arow] = a1.z; As[0][akg + 7][arow] = a1.w;
    *(uint4*)&Bs[0][brow][bcol]     = b0v;
    *(uint4*)&Bs[0][brow + 8][bcol] = b1v;
    __syncthreads();

    int buf = 0;
    for (int kt = 0; kt < 64; kt++) {
        if (kt < 63) {
            a0  = *(const uint4*)(Ap + (size_t)(kt + 1) * 16);
            a1  = *(const uint4*)(Ap + (size_t)(kt + 1) * 16 + 4);
            b0v = *(const uint4*)(Bp + (size_t)(kt + 1) * 16 * N3);
            b1v = *(const uint4*)(Bp + (size_t)((kt + 1) * 16 + 8) * N3);
        }
        #pragma unroll
        for (int kk = 0; kk < 2; kk++) {
            int kb = kk * 8;
            uint32_t af[4][4];
            #pragma unroll
            for (int mi = 0; mi < 4; mi++) {
                int mr = wm * 64 + mi * 16 + g;
                af[mi][0] = As[buf][kb + tig    ][mr];
                af[mi][1] = As[buf][kb + tig    ][mr + 8];
                af[mi][2] = As[buf][kb + tig + 4][mr];
                af[mi][3] = As[buf][kb + tig + 4][mr + 8];
            }
            uint32_t bf0[4], bf1[4];
            #pragma unroll
            for (int ni = 0; ni < 4; ni++) {
                int nc = wn * 32 + ni * 8 + g;
                bf0[ni] = Bs[buf][kb + tig    ][nc];
                bf1[ni] = Bs[buf][kb + tig + 4][nc];
            }
            #pragma unroll
            for (int mi = 0; mi < 4; mi++)
                #pragma unroll
                for (int ni = 0; ni < 4; ni++)
                    mma_tf32(acc[mi][ni], af[mi], bf0[ni], bf1[ni]);
        }
        if (kt < 63) {
            int nb = buf ^ 1;
            As[nb][akg + 0][arow] = a0.x; As[nb][akg + 1][arow] = a0.y;
            As[nb][akg + 2][arow] = a0.z; As[nb][akg + 3][arow] = a0.w;
            As[nb][akg + 4][arow] = a1.x; As[nb][akg + 5][arow] = a1.y;
            As[nb][akg + 6][arow] = a1.z; As[nb][akg + 7][arow] = a1.w;
            *(uint4*)&Bs[nb][brow][bcol]     = b0v;
            *(uint4*)&Bs[nb][brow + 8][bcol] = b1v;
            buf = nb;
        }
        __syncthreads();
    }

    #pragma unroll
    for (int mi = 0; mi < 4; mi++) {
        int mr = m0 + wm * 64 + mi * 16 + g;
        #pragma unroll
        for (int ni = 0; ni < 4; ni++) {
            int nc = n0 + wn * 32 + ni * 8 + tig * 2;
            *(float2*)(g_IN + (size_t)mr * N3 + nc) =
                make_float2(acc[mi][ni][0], acc[mi][ni][1]);
            *(float2*)(g_IN + (size_t)(mr + 8) * N3 + nc) =
                make_float2(acc[mi][ni][2], acc[mi][ni][3]);
        }
    }
}

// ------------------------- epilogue: Poincare map + tf32 layouts ------------
// Q scaled by log2(e)/8 so attention can use exp2 directly.
__global__ __launch_bounds__(256) void epi_kernel(const float* __restrict__ bvp) {
    int r0 = blockIdx.x * 4;
    int b  = r0 >> 11;
    int s0 = r0 & 2047;
    int tid = threadIdx.x;
    int j0 = tid * 4;
    int h  = j0 >> 6, dk = j0 & 63;

    float lamv[4];
    *(float4*)lamv = *(const float4*)(g_lam + r0);

    float wq[4][4];
    // ---------------- Q ----------------
    {
        float4 par[4];
        #pragma unroll
        for (int c = 0; c < 4; c++) par[c] = g_par[j0 + c];
        float ws[4] = {0.f, 0.f, 0.f, 0.f};
        #pragma unroll
        for (int ri = 0; ri < 4; ri++) {
            float lam = lamv[ri], lm1 = lam - 1.0f;
            float4 inn = *(const float4*)(g_IN + (size_t)(r0 + ri) * N3 + j0);
            float innv[4] = {inn.x, inn.y, inn.z, inn.w};
            #pragma unroll
            for (int c = 0; c < 4; c++) {
                float arg = lam * innv[c] * par[c].y - lm1 * par[c].z;
                float t   = arg + sqrtf(arg * arg + 1.0f);
                float u   = par[c].x * __logf(t);
                float eu  = __expf(u);
                float w   = 0.5f * (eu - __fdividef(1.0f, eu));
                wq[ri][c] = w;
                ws[ri] += w * w;
            }
        }
        bcastSum4(ws);
        #pragma unroll
        for (int ri = 0; ri < 4; ri++) {
            float scl = 0.18033688f / (1.0f + sqrtf(1.0f + ws[ri]));  // log2(e)/8
            float4 ov = make_float4(f2tf_f(wq[ri][0] * scl), f2tf_f(wq[ri][1] * scl),
                                    f2tf_f(wq[ri][2] * scl), f2tf_f(wq[ri][3] * scl));
            *(float4*)(g_Q + ((size_t)(b * 16 + h) * SS + s0 + ri) * DKk + dk) = ov;
        }
    }
    // ---------------- K ----------------
    {
        float4 par[4];
        #pragma unroll
        for (int c = 0; c < 4; c++) par[c] = g_par[1024 + j0 + c];
        float ws2[4] = {0.f, 0.f, 0.f, 0.f};
        #pragma unroll
        for (int ri = 0; ri < 4; ri++) {
            float lam = lamv[ri], lm1 = lam - 1.0f;
            float4 inn = *(const float4*)(g_IN + (size_t)(r0 + ri) * N3 + 1024 + j0);
            float innv[4] = {inn.x, inn.y, inn.z, inn.w};
            #pragma unroll
            for (int c = 0; c < 4; c++) {
                float arg = lam * innv[c] * par[c].y - lm1 * par[c].z;
                float t   = arg + sqrtf(arg * arg + 1.0f);
                float u   = par[c].x * __logf(t);
                float eu  = __expf(u);
                float w   = 0.5f * (eu - __fdividef(1.0f, eu));
                wq[ri][c] = w;
                ws2[ri] += w * w;
            }
        }
        bcastSum4(ws2);
        #pragma unroll
        for (int ri = 0; ri < 4; ri++) {
            float scl = 1.0f / (1.0f + sqrtf(1.0f + ws2[ri]));
            float4 ov = make_float4(f2tf_f(wq[ri][0] * scl), f2tf_f(wq[ri][1] * scl),
                                    f2tf_f(wq[ri][2] * scl), f2tf_f(wq[ri][3] * scl));
            *(float4*)(g_K + ((size_t)(b * 16 + h) * SS + s0 + ri) * DKk + dk) = ov;
        }
    }
    // ---------------- V (transposed store) ----------------
    {
        float4 bvv = *(const float4*)(bvp + j0);
        float vv[4][4];
        #pragma unroll
        for (int ri = 0; ri < 4; ri++) {
            float4 inn = *(const float4*)(g_IN + (size_t)(r0 + ri) * N3 + 2048 + j0);
            vv[ri][0] = f2tf_f(inn.x + bvv.x);
            vv[ri][1] = f2tf_f(inn.y + bvv.y);
            vv[ri][2] = f2tf_f(inn.z + bvv.z);
            vv[ri][3] = f2tf_f(inn.w + bvv.w);
        }
        float* Vb = g_Vt + (size_t)(b * 16 + h) * DKk * SS;
        #pragma unroll
        for (int c = 0; c < 4; c++) {
            float4 ov = make_float4(vv[0][c], vv[1][c], vv[2][c], vv[3][c]);
            *(float4*)(Vb + (size_t)(dk + c) * SS + s0) = ov;
        }
    }
}

// ------------------------- flash attention (tf32, no-max softmax) -----------
// |score| < 0.125 (unit-ball Q,K, folded 1/sqrt(Dk)) so exp never overflows:
// softmax needs NO max subtraction, NO rescaling, NO in-loop reductions.
// Q pre-scaled by log2e/8 -> p = exp2f(score) directly.
__global__ __launch_bounds__(256, 2) void attn_kernel(float* __restrict__ out) {
    extern __shared__ float smem[];
    const int TILE = 64 * 72;
    float* sKb[2] = { smem,          smem + TILE };
    float* sVb[2] = { smem + 2*TILE, smem + 3*TILE };
    uint32_t sbase = (uint32_t)__cvta_generic_to_shared(smem);

    int tid  = threadIdx.x;
    int warp = tid >> 5, lane = tid & 31;
    int g = lane >> 2, tig = lane & 3;
    int bh = blockIdx.y;
    int b  = bh >> 4, h = bh & 15;
    int q0 = blockIdx.x * 128;
    int wq = warp * 16;

    const float* Qp = g_Q  + ((size_t)bh * SS + q0 + wq) * DKk;
    const float* Kg = g_K  + (size_t)bh * SS * DKk;
    const float* Vg = g_Vt + (size_t)bh * DKk * SS;

    uint32_t qa[8][4];
    #pragma unroll
    for (int kt = 0; kt < 8; kt++) {
        float2 qr0 = *(const float2*)(Qp + (size_t)g       * DKk + kt * 8 + 2 * tig);
        float2 qr1 = *(const float2*)(Qp + (size_t)(g + 8) * DKk + kt * 8 + 2 * tig);
        qa[kt][0] = __float_as_uint(qr0.x);
        qa[kt][1] = __float_as_uint(qr1.x);
        qa[kt][2] = __float_as_uint(qr0.y);
        qa[kt][3] = __float_as_uint(qr1.y);
    }

    float o[8][4];
    #pragma unroll
    for (int n = 0; n < 8; n++)
        #pragma unroll
        for (int c = 0; c < 4; c++) o[n][c] = 0.0f;
    float l0 = 0.0f, l1 = 0.0f;     // per-thread partial softmax sums

    auto load_tile = [&](int buf, int it) {
        int kc0 = it * 64;
        uint32_t sk = sbase + (uint32_t)(buf * TILE) * 4;
        uint32_t sv = sbase + (uint32_t)((2 + buf) * TILE) * 4;
        #pragma unroll
        for (int i = 0; i < 4; i++) {
            int chunk = tid + i * 256;
            int row = chunk >> 4;
            int c4  = (chunk & 15) * 4;
            cpasync16(sk + (uint32_t)(row * 72 + c4) * 4,
                      Kg + (size_t)(kc0 + row) * DKk + c4);
            cpasync16(sv + (uint32_t)(row * 72 + c4) * 4,
                      Vg + (size_t)row * SS + kc0 + c4);
        }
        CP_COMMIT();
    };

    load_tile(0, 0);

    int buf = 0;
    for (int it = 0; it < SS / 64; it++) {
        if (it + 1 < SS / 64) {
            load_tile(buf ^ 1, it + 1);
            CP_WAIT1();
        } else {
            CP_WAIT0();
        }
        __syncthreads();
        const float* sK = sKb[buf];
        const float* sV = sVb[buf];

        // S = Q . K^T (base-2 logits)
        float p[8][4];
        #pragma unroll
        for (int n = 0; n < 8; n++)
            #pragma unroll
            for (int c = 0; c < 4; c++) p[n][c] = 0.0f;
        #pragma unroll
        for (int n0 = 0; n0 < 8; n0++) {
            const float* kr = sK + (n0 * 8 + g) * 72 + 2 * tig;
            #pragma unroll
            for (int k0 = 0; k0 < 8; k0++) {
                float2 bv = *(const float2*)(kr + k0 * 8);
                mma_tf32(p[n0], qa[k0], __float_as_uint(bv.x), __float_as_uint(bv.y));
            }
        }

        // p = exp2(s); accumulate row sums per-thread (reduced once at end)
        #pragma unroll
        for (int n = 0; n < 8; n++) {
            p[n][0] = exp2f(p[n][0]);
            p[n][1] = exp2f(p[n][1]);
            p[n][2] = exp2f(p[n][2]);
            p[n][3] = exp2f(p[n][3]);
            l0 += p[n][0] + p[n][1];
            l1 += p[n][2] + p[n][3];
        }

        // O += P . V (C-frag is the A-frag under the k-slot permutation)
        #pragma unroll
        for (int kt = 0; kt < 8; kt++) {
            uint32_t a[4];
            a[0] = f2tf(p[kt][0]);
            a[1] = f2tf(p[kt][2]);
            a[2] = f2tf(p[kt][1]);
            a[3] = f2tf(p[kt][3]);
            const float* vr = sV + kt * 8 + 2 * tig;
            #pragma unroll
            for (int n0 = 0; n0 < 8; n0++) {
                float2 bv = *(const float2*)(vr + (n0 * 8 + g) * 72);
                mma_tf32(o[n0], a, __float_as_uint(bv.x), __float_as_uint(bv.y));
            }
        }
        __syncthreads();
        buf ^= 1;
    }

    // one-shot row-sum reduction across the quad
    l0 += __shfl_xor_sync(0xffffffffu, l0, 1);
    l0 += __shfl_xor_sync(0xffffffffu, l0, 2);
    l1 += __shfl_xor_sync(0xffffffffu, l1, 1);
    l1 += __shfl_xor_sync(0xffffffffu, l1, 2);

    float inv0 = 1.0f / l0, inv1 = 1.0f / l1;
    int s0r = q0 + wq + g;
    #pragma unroll
    for (int n0 = 0; n0 < 8; n0++) {
        int dk = n0 * 8 + 2 * tig;
        float2 ov0 = make_float2(o[n0][0] * inv0, o[n0][1] * inv0);
        float2 ov1 = make_float2(o[n0][2] * inv1, o[n0][3] * inv1);
        *(float2*)(out + ((size_t)(b * SS + s0r)     ) * DDm + h * 64 + dk) = ov0;
        *(float2*)(out + ((size_t)(b * SS + s0r + 8) ) * DDm + h * 64 + dk) = ov1;
    }
}

// ------------------------- launcher ----------------------------------------
extern "C" void kernel_launch(void* const* d_in, const int* in_sizes, int n_in,
                              void* d_out, int out_size) {
    const float* x  = (const float*)d_in[0];
    const float* zq = (const float*)d_in[1];
    const float* bq = (const float*)d_in[2];
    const float* zk = (const float*)d_in[3];
    const float* bk = (const float*)d_in[4];
    const float* wv = (const float*)d_in[5];
    const float* bv = (const float*)d_in[6];
    float* out = (float*)d_out;

    prep_kernel<<<N3, 256>>>(zq, bq, zk, bk, wv);
    lam_kernel<<<BSr, 256>>>(x);
    gemm_tc<<<dim3(N3 / 128, BSr / 128), 256>>>();
    epi_kernel<<<BSr / 4, 256>>>(bv);

    int smem_bytes = 4 * 64 * 72 * 4;   // 73728
    cudaFuncSetAttribute(attn_kernel, cudaFuncAttributeMaxDynamicSharedMemorySize, smem_bytes);
    attn_kernel<<<dim3(SS / 128, BHh), 256, smem_bytes>>>(out);
}

// round 9
// speedup vs baseline: 4.0499x; 1.2168x over previous
#include <cuda_runtime.h>
#include <cstdint>

// Problem constants
#define BB  4
#define SS  2048
#define DDm 1024
#define HHn 16
#define DKk 64
#define BSr (BB*SS)     // 8192 rows
#define N3  3072        // concat of Q|K|V projection outputs
#define BHh (BB*HHn)    // 64 head-batches

// ------------------------- scratch (static device memory) -------------------
__device__ float    g_B  [DDm * N3];                  // tf32-rounded B matrix
__device__ float    g_Xc [(size_t)BSr * DDm];         // tf32-rounded copy of x
__device__ float    g_IN [(size_t)BSr * N3];          // raw projections (fp32)
__device__ float    g_lam[BSr];                       // per-row lambda
__device__ float4   g_par[2048];                      // per-col {2*zn, cosh2r, sinh2r, 0}
__device__ uint32_t g_Qb [(size_t)BHh * SS * 32];     // Q bf16x2 [bh][s][dk-words], scale log2e/8
__device__ uint32_t g_Kb [(size_t)BHh * SS * 32];     // K bf16x2 [bh][s][dk-words], word-scrambled
__device__ uint32_t g_Vb [(size_t)BHh * DKk * 1024];  // V bf16x2 [bh][dk][s-words], word-scrambled
__device__ float    g_cs [BHh * DKk];                 // colsum of V projection (no bias), fp32

// ------------------------- helpers ------------------------------------------
__device__ __forceinline__ uint32_t f2tf(float f) {
    uint32_t r; asm("cvt.rna.tf32.f32 %0, %1;" : "=r"(r) : "f"(f)); return r;
}
__device__ __forceinline__ float f2tf_f(float f) {
    uint32_t r = f2tf(f); return __uint_as_float(r);
}
// pack two fp32 -> bf16x2 (lo, hi)
__device__ __forceinline__ uint32_t pkbf(float lo, float hi) {
    uint32_t d; asm("cvt.rn.bf16x2.f32 %0, %1, %2;" : "=r"(d) : "f"(hi), "f"(lo)); return d;
}
// word scramble within an 8-word block: phys = 2*(w&3) + ((w>>2)&1)
__device__ __forceinline__ uint32_t ph(uint32_t w) {
    return (w & ~7u) + 2u * (w & 3u) + ((w >> 2) & 1u);
}
__device__ __forceinline__ void mma_tf32(float c[4], const uint32_t a[4],
                                         uint32_t b0, uint32_t b1) {
    asm volatile(
        "mma.sync.aligned.m16n8k8.row.col.f32.tf32.tf32.f32 "
        "{%0,%1,%2,%3}, {%4,%5,%6,%7}, {%8,%9}, {%0,%1,%2,%3};\n"
        : "+f"(c[0]), "+f"(c[1]), "+f"(c[2]), "+f"(c[3])
        : "r"(a[0]), "r"(a[1]), "r"(a[2]), "r"(a[3]), "r"(b0), "r"(b1));
}
__device__ __forceinline__ void mma_bf16(float c[4], const uint32_t a[4],
                                         uint32_t b0, uint32_t b1) {
    asm volatile(
        "mma.sync.aligned.m16n8k16.row.col.f32.bf16.bf16.f32 "
        "{%0,%1,%2,%3}, {%4,%5,%6,%7}, {%8,%9}, {%0,%1,%2,%3};\n"
        : "+f"(c[0]), "+f"(c[1]), "+f"(c[2]), "+f"(c[3])
        : "r"(a[0]), "r"(a[1]), "r"(a[2]), "r"(a[3]), "r"(b0), "r"(b1));
}
__device__ __forceinline__ void cpasync16(uint32_t saddr, const void* gptr) {
    asm volatile("cp.async.cg.shared.global [%0], [%1], 16;\n"
                 :: "r"(saddr), "l"(gptr) : "memory");
}
#define CP_COMMIT() asm volatile("cp.async.commit_group;\n" ::: "memory")
#define CP_WAIT1()  asm volatile("cp.async.wait_group 1;\n" ::: "memory")
#define CP_WAIT0()  asm volatile("cp.async.wait_group 0;\n" ::: "memory")

// ------------------------- block reduction helpers --------------------------
__device__ __forceinline__ float bcastSum(float v) {
    __shared__ float sm[8];
    #pragma unroll
    for (int m = 16; m > 0; m >>= 1) v += __shfl_xor_sync(0xffffffffu, v, m);
    int w = threadIdx.x >> 5;
    if ((threadIdx.x & 31) == 0) sm[w] = v;
    __syncthreads();
    if (threadIdx.x < 8) {
        v = sm[threadIdx.x];
        #pragma unroll
        for (int m = 4; m > 0; m >>= 1) v += __shfl_xor_sync(0x000000ffu, v, m);
        if (threadIdx.x == 0) sm[0] = v;
    }
    __syncthreads();
    v = sm[0];
    __syncthreads();
    return v;
}

__device__ __forceinline__ void bcastSum4(float v[4]) {
    __shared__ float sm4[8][4];
    #pragma unroll
    for (int m = 16; m > 0; m >>= 1) {
        #pragma unroll
        for (int c = 0; c < 4; c++) v[c] += __shfl_xor_sync(0xffffffffu, v[c], m);
    }
    int w = threadIdx.x >> 5;
    if ((threadIdx.x & 31) == 0) {
        #pragma unroll
        for (int c = 0; c < 4; c++) sm4[w][c] = v[c];
    }
    __syncthreads();
    if (threadIdx.x < 8) {
        #pragma unroll
        for (int c = 0; c < 4; c++) v[c] = sm4[threadIdx.x][c];
        #pragma unroll
        for (int m = 4; m > 0; m >>= 1) {
            #pragma unroll
            for (int c = 0; c < 4; c++) v[c] += __shfl_xor_sync(0x000000ffu, v[c], m);
        }
        if (threadIdx.x == 0) {
            #pragma unroll
            for (int c = 0; c < 4; c++) sm4[0][c] = v[c];
        }
    }
    __syncthreads();
    #pragma unroll
    for (int c = 0; c < 4; c++) v[c] = sm4[0][c];
    __syncthreads();
}

// ------------------------- prep: build concat B + per-col params ------------
__global__ __launch_bounds__(256) void prep_kernel(
    const float* __restrict__ zq, const float* __restrict__ bq,
    const float* __restrict__ zk, const float* __restrict__ bk,
    const float* __restrict__ wv)
{
    int j = blockIdx.x;
    int tid = threadIdx.x;
    if (j >= 2048) {
        int col = j - 2048;
        for (int d = tid; d < DDm; d += 256)
            g_B[(size_t)d * N3 + j] = f2tf_f(wv[(size_t)col * DDm + d]);
        return;
    }
    const float* z; const float* bias; int col;
    if (j < 1024) { z = zq; bias = bq; col = j; }
    else          { z = zk; bias = bk; col = j - 1024; }

    float ss = 0.0f;
    for (int d = tid; d < DDm; d += 256) {
        float v = z[(size_t)d * DDm + col];
        ss += v * v;
    }
    ss = bcastSum(ss);
    float zn = fmaxf(sqrtf(ss), 1e-15f);
    float inv = 1.0f / zn;
    for (int d = tid; d < DDm; d += 256)
        g_B[(size_t)d * N3 + j] = f2tf_f(z[(size_t)d * DDm + col] * inv);
    if (tid == 0) {
        float r2 = 2.0f * bias[col];
        g_par[j] = make_float4(2.0f * zn, coshf(r2), sinhf(r2), 0.0f);
    }
}

// ------------- lambda + tf32-rounded copy of x ------------------------------
__global__ __launch_bounds__(256) void lam_kernel(const float* __restrict__ x) {
    int r = blockIdx.x;
    float4 v = *(const float4*)(x + (size_t)r * DDm + threadIdx.x * 4);
    float ss = v.x * v.x + v.y * v.y + v.z * v.z + v.w * v.w;
    float4 cv = make_float4(f2tf_f(v.x), f2tf_f(v.y), f2tf_f(v.z), f2tf_f(v.w));
    *(float4*)(g_Xc + (size_t)r * DDm + threadIdx.x * 4) = cv;
    ss = bcastSum(ss);
    if (threadIdx.x == 0) g_lam[r] = 2.0f / (1.0f - ss);
}

// ------------------------- TF32 GEMM: g_IN = g_Xc @ g_B ---------------------
__global__ __launch_bounds__(256, 2) void gemm_tc() {
    __shared__ uint32_t As[2][16][136];
    __shared__ uint32_t Bs[2][16][136];

    int tid = threadIdx.x;
    int warp = tid >> 5, lane = tid & 31;
    int g = lane >> 2, tig = lane & 3;
    int wm = warp >> 2, wn = warp & 3;
    int m0 = blockIdx.y * 128, n0 = blockIdx.x * 128;

    int arow = tid >> 1;
    int akg  = (tid & 1) * 8;
    int brow = tid >> 5;
    int bcol = (tid & 31) * 4;
    const float* Ap = g_Xc + (size_t)(m0 + arow) * DDm + akg;
    const float* Bp = g_B + (size_t)brow * N3 + n0 + bcol;

    uint4 a0 = *(const uint4*)Ap;
    uint4 a1 = *(const uint4*)(Ap + 4);
    uint4 b0v = *(const uint4*)Bp;
    uint4 b1v = *(const uint4*)(Bp + (size_t)8 * N3);

    float acc[4][4][4];
    #pragma unroll
    for (int mi = 0; mi < 4; mi++)
        #pragma unroll
        for (int ni = 0; ni < 4; ni++)
            #pragma unroll
            for (int c = 0; c < 4; c++) acc[mi][ni][c] = 0.0f;

    As[0][akg + 0][arow] = a0.x; As[0][akg + 1][arow] = a0.y;
    As[0][akg + 2][arow] = a0.z; As[0][akg + 3][arow] = a0.w;
    As[0][akg + 4][arow] = a1.x; As[0][akg + 5][arow] = a1.y;
    As[0][akg + 6][arow] = a1.z; As[0][akg + 7][arow] = a1.w;
    *(uint4*)&Bs[0][brow][bcol]     = b0v;
    *(uint4*)&Bs[0][brow + 8][bcol] = b1v;
    __syncthreads();

    int buf = 0;
    for (int kt = 0; kt < 64; kt++) {
        if (kt < 63) {
            a0  = *(const uint4*)(Ap + (size_t)(kt + 1) * 16);
            a1  = *(const uint4*)(Ap + (size_t)(kt + 1) * 16 + 4);
            b0v = *(const uint4*)(Bp + (size_t)(kt + 1) * 16 * N3);
            b1v = *(const uint4*)(Bp + (size_t)((kt + 1) * 16 + 8) * N3);
        }
        #pragma unroll
        for (int kk = 0; kk < 2; kk++) {
            int kb = kk * 8;
            uint32_t af[4][4];
            #pragma unroll
            for (int mi = 0; mi < 4; mi++) {
                int mr = wm * 64 + mi * 16 + g;
                af[mi][0] = As[buf][kb + tig    ][mr];
                af[mi][1] = As[buf][kb + tig    ][mr + 8];
                af[mi][2] = As[buf][kb + tig + 4][mr];
                af[mi][3] = As[buf][kb + tig + 4][mr + 8];
            }
            uint32_t bf0[4], bf1[4];
            #pragma unroll
            for (int ni = 0; ni < 4; ni++) {
                int nc = wn * 32 + ni * 8 + g;
                bf0[ni] = Bs[buf][kb + tig    ][nc];
                bf1[ni] = Bs[buf][kb + tig + 4][nc];
            }
            #pragma unroll
            for (int mi = 0; mi < 4; mi++)
                #pragma unroll
                for (int ni = 0; ni < 4; ni++)
                    mma_tf32(acc[mi][ni], af[mi], bf0[ni], bf1[ni]);
        }
        if (kt < 63) {
            int nb = buf ^ 1;
            As[nb][akg + 0][arow] = a0.x; As[nb][akg + 1][arow] = a0.y;
            As[nb][akg + 2][arow] = a0.z; As[nb][akg + 3][arow] = a0.w;
            As[nb][akg + 4][arow] = a1.x; As[nb][akg + 5][arow] = a1.y;
            As[nb][akg + 6][arow] = a1.z; As[nb][akg + 7][arow] = a1.w;
            *(uint4*)&Bs[nb][brow][bcol]     = b0v;
            *(uint4*)&Bs[nb][brow + 8][bcol] = b1v;
            buf = nb;
        }
        __syncthreads();
    }

    #pragma unroll
    for (int mi = 0; mi < 4; mi++) {
        int mr = m0 + wm * 64 + mi * 16 + g;
        #pragma unroll
        for (int ni = 0; ni < 4; ni++) {
            int nc = n0 + wn * 32 + ni * 8 + tig * 2;
            *(float2*)(g_IN + (size_t)mr * N3 + nc) =
                make_float2(acc[mi][ni][0], acc[mi][ni][1]);
            *(float2*)(g_IN + (size_t)(mr + 8) * N3 + nc) =
                make_float2(acc[mi][ni][2], acc[mi][ni][3]);
        }
    }
}

// ------------------------- colsum of V projection (deterministic) -----------
// grid = BHh blocks, 256 threads. Thread t: dk = t&63, chunk = t>>6 (512 rows).
// smem 4-way reduce, direct store. No atomics -> identical on every replay.
__global__ __launch_bounds__(256) void csum_kernel() {
    int bh = blockIdx.x;
    int b = bh >> 4, h = bh & 15;
    int t = threadIdx.x;
    int dk = t & 63, chunk = t >> 6;        // 0..3
    const float* base = g_IN + ((size_t)(b * 2048 + chunk * 512)) * N3 + 2048 + h * 64 + dk;
    float s0 = 0.f, s1 = 0.f, s2 = 0.f, s3 = 0.f;
    for (int i = 0; i < 512; i += 4) {
        s0 += base[(size_t)(i + 0) * N3];
        s1 += base[(size_t)(i + 1) * N3];
        s2 += base[(size_t)(i + 2) * N3];
        s3 += base[(size_t)(i + 3) * N3];
    }
    __shared__ float red[256];
    red[t] = (s0 + s1) + (s2 + s3);
    __syncthreads();
    if (t < 64)
        g_cs[bh * 64 + t] = (red[t] + red[t + 64]) + (red[t + 128] + red[t + 192]);
}

// ------------------------- epilogue: Poincare map -> bf16 layouts -----------
__global__ __launch_bounds__(256) void epi_kernel(const float* __restrict__ bvp) {
    int r0 = blockIdx.x * 4;
    int b  = r0 >> 11;
    int s0 = r0 & 2047;
    int tid = threadIdx.x;
    int j0 = tid * 4;
    int h  = j0 >> 6, dk = j0 & 63;
    int bh = b * 16 + h;

    float lamv[4];
    *(float4*)lamv = *(const float4*)(g_lam + r0);

    float wq[4][4];
    // ---------------- Q ----------------
    {
        float4 par[4];
        #pragma unroll
        for (int c = 0; c < 4; c++) par[c] = g_par[j0 + c];
        float ws[4] = {0.f, 0.f, 0.f, 0.f};
        #pragma unroll
        for (int ri = 0; ri < 4; ri++) {
            float lam = lamv[ri], lm1 = lam - 1.0f;
            float4 inn = *(const float4*)(g_IN + (size_t)(r0 + ri) * N3 + j0);
            float innv[4] = {inn.x, inn.y, inn.z, inn.w};
            #pragma unroll
            for (int c = 0; c < 4; c++) {
                float arg = lam * innv[c] * par[c].y - lm1 * par[c].z;
                float t   = arg + sqrtf(arg * arg + 1.0f);
                float u   = par[c].x * __logf(t);
                float eu  = __expf(u);
                float w   = 0.5f * (eu - __fdividef(1.0f, eu));
                wq[ri][c] = w;
                ws[ri] += w * w;
            }
        }
        bcastSum4(ws);
        #pragma unroll
        for (int ri = 0; ri < 4; ri++) {
            float scl = 0.18033688f / (1.0f + sqrtf(1.0f + ws[ri]));  // log2(e)/8
            uint2 ov = make_uint2(pkbf(wq[ri][0] * scl, wq[ri][1] * scl),
                                  pkbf(wq[ri][2] * scl, wq[ri][3] * scl));
            *(uint2*)(g_Qb + ((size_t)bh * SS + s0 + ri) * 32 + (dk >> 1)) = ov;
        }
    }
    // ---------------- K (word-scrambled dk layout) ----------------
    {
        float4 par[4];
        #pragma unroll
        for (int c = 0; c < 4; c++) par[c] = g_par[1024 + j0 + c];
        float ws2[4] = {0.f, 0.f, 0.f, 0.f};
        #pragma unroll
        for (int ri = 0; ri < 4; ri++) {
            float lam = lamv[ri], lm1 = lam - 1.0f;
            float4 inn = *(const float4*)(g_IN + (size_t)(r0 + ri) * N3 + 1024 + j0);
            float innv[4] = {inn.x, inn.y, inn.z, inn.w};
            #pragma unroll
            for (int c = 0; c < 4; c++) {
                float arg = lam * innv[c] * par[c].y - lm1 * par[c].z;
                float t   = arg + sqrtf(arg * arg + 1.0f);
                float u   = par[c].x * __logf(t);
                float eu  = __expf(u);
                float w   = 0.5f * (eu - __fdividef(1.0f, eu));
                wq[ri][c] = w;
                ws2[ri] += w * w;
            }
        }
        bcastSum4(ws2);
        uint32_t wl0 = dk >> 1;
        uint32_t p0 = ph(wl0), p1 = ph(wl0 + 1);
        #pragma unroll
        for (int ri = 0; ri < 4; ri++) {
            float scl = 1.0f / (1.0f + sqrtf(1.0f + ws2[ri]));
            uint32_t* row = g_Kb + ((size_t)bh * SS + s0 + ri) * 32;
            row[p0] = pkbf(wq[ri][0] * scl, wq[ri][1] * scl);
            row[p1] = pkbf(wq[ri][2] * scl, wq[ri][3] * scl);
        }
    }
    // ---------------- V (transposed, word-scrambled s layout) ----------------
    {
        float4 bvv = *(const float4*)(bvp + j0);
        float vv[4][4];
        #pragma unroll
        for (int ri = 0; ri < 4; ri++) {
            float4 inn = *(const float4*)(g_IN + (size_t)(r0 + ri) * N3 + 2048 + j0);
            vv[ri][0] = inn.x + bvv.x;
            vv[ri][1] = inn.y + bvv.y;
            vv[ri][2] = inn.z + bvv.z;
            vv[ri][3] = inn.w + bvv.w;
        }
        uint32_t wl0 = s0 >> 1;
        uint32_t ps0 = ph(wl0), ps1 = ph(wl0 + 1);
        #pragma unroll
        for (int c = 0; c < 4; c++) {
            uint32_t* row = g_Vb + ((size_t)bh * DKk + dk + c) * 1024;
            row[ps0] = pkbf(vv[0][c], vv[1][c]);
            row[ps1] = pkbf(vv[2][c], vv[3][c]);
        }
    }
}

// ------------------------- flash attention (bf16 m16n8k16, centered P) ------
// O = colsumV + sum_k (p_k - 1) v_k ; l = sum p_k.  |p-1| <= 0.13 so bf16
// rounding of the MMA operands stays ~tf32-accurate overall.
__global__ __launch_bounds__(256, 2) void attn_kernel(float* __restrict__ out,
                                                      const float* __restrict__ bvp) {
    extern __shared__ uint32_t smem[];
    const int TW = 64 * 40;                    // words per tile (stride 40)
    uint32_t sbase = (uint32_t)__cvta_generic_to_shared(smem);

    int tid  = threadIdx.x;
    int warp = tid >> 5, lane = tid & 31;
    int g = lane >> 2, tig = lane & 3;
    int bh = blockIdx.y;
    int b  = bh >> 4, h = bh & 15;
    int q0 = blockIdx.x * 128;
    int wq = warp * 16;

    const uint32_t* Qw = g_Qb + ((size_t)bh * SS + q0 + wq) * 32;
    const uint32_t* Kw = g_Kb + (size_t)bh * SS * 32;
    const uint32_t* Vw = g_Vb + (size_t)bh * DKk * 1024;

    // Q A-fragments: a0/a2 from natural-layout bf16 Q words
    uint32_t qa[4][4];
    #pragma unroll
    for (int ktq = 0; ktq < 4; ktq++) {
        qa[ktq][0] = Qw[(size_t)g       * 32 + ktq * 8 + tig];
        qa[ktq][1] = Qw[(size_t)(g + 8) * 32 + ktq * 8 + tig];
        qa[ktq][2] = Qw[(size_t)g       * 32 + ktq * 8 + tig + 4];
        qa[ktq][3] = Qw[(size_t)(g + 8) * 32 + ktq * 8 + tig + 4];
    }

    float o[8][4];
    #pragma unroll
    for (int n = 0; n < 8; n++)
        #pragma unroll
        for (int c = 0; c < 4; c++) o[n][c] = 0.0f;
    float l0 = 0.0f, l1 = 0.0f;

    auto load_tile = [&](int buf, int it) {
        int kc0 = it * 64;
        uint32_t sk = sbase + (uint32_t)(buf * TW) * 4;
        uint32_t sv = sbase + (uint32_t)((2 + buf) * TW) * 4;
        #pragma unroll
        for (int i = 0; i < 2; i++) {
            int chunk = tid + i * 256;         // 0..511
            int row = chunk >> 3;              // 0..63
            int off = (chunk & 7) * 4;         // word offset
            cpasync16(sk + (uint32_t)(row * 40 + off) * 4,
                      Kw + (size_t)(kc0 + row) * 32 + off);
            cpasync16(sv + (uint32_t)(row * 40 + off) * 4,
                      Vw + (size_t)row * 1024 + it * 32 + off);
        }
        CP_COMMIT();
    };

    load_tile(0, 0);

    int buf = 0;
    for (int it = 0; it < SS / 64; it++) {
        if (it + 1 < SS / 64) {
            load_tile(buf ^ 1, it + 1);
            CP_WAIT1();
        } else {
            CP_WAIT0();
        }
        __syncthreads();
        const uint32_t* sK = smem + buf * TW;
        const uint32_t* sV = smem + (2 + buf) * TW;

        // S = Q . K^T : 32 bf16 MMAs, B-frag one LDS.64 each
        float p[8][4];
        #pragma unroll
        for (int n = 0; n < 8; n++)
            #pragma unroll
            for (int c = 0; c < 4; c++) p[n][c] = 0.0f;
        #pragma unroll
        for (int ktq = 0; ktq < 4; ktq++) {
            #pragma unroll
            for (int n0 = 0; n0 < 8; n0++) {
                uint2 kb = *(const uint2*)(sK + (n0 * 8 + g) * 40 + ktq * 8 + 2 * tig);
                mma_bf16(p[n0], qa[ktq], kb.x, kb.y);
            }
        }

        // p = exp2(s); accumulate l; center q = p - 1
        #pragma unroll
        for (int n = 0; n < 8; n++) {
            float e0 = exp2f(p[n][0]);
            float e1 = exp2f(p[n][1]);
            float e2 = exp2f(p[n][2]);
            float e3 = exp2f(p[n][3]);
            l0 += e0 + e1;
            l1 += e2 + e3;
            p[n][0] = e0 - 1.0f;
            p[n][1] = e1 - 1.0f;
            p[n][2] = e2 - 1.0f;
            p[n][3] = e3 - 1.0f;
        }

        // pack centered P into bf16 A-fragments (zero shuffles)
        uint32_t pa[4][4];
        #pragma unroll
        for (int ktp = 0; ktp < 4; ktp++) {
            pa[ktp][0] = pkbf(p[2 * ktp    ][0], p[2 * ktp    ][1]);
            pa[ktp][1] = pkbf(p[2 * ktp    ][2], p[2 * ktp    ][3]);
            pa[ktp][2] = pkbf(p[2 * ktp + 1][0], p[2 * ktp + 1][1]);
            pa[ktp][3] = pkbf(p[2 * ktp + 1][2], p[2 * ktp + 1][3]);
        }

        // O += (P-1) . V : 32 bf16 MMAs
        #pragma unroll
        for (int ktp = 0; ktp < 4; ktp++) {
            #pragma unroll
            for (int n0 = 0; n0 < 8; n0++) {
                uint2 vb = *(const uint2*)(sV + (n0 * 8 + g) * 40 + ktp * 8 + 2 * tig);
                mma_bf16(o[n0], pa[ktp], vb.x, vb.y);
            }
        }
        __syncthreads();
        buf ^= 1;
    }

    // row-sum reductions (once)
    l0 += __shfl_xor_sync(0xffffffffu, l0, 1);
    l0 += __shfl_xor_sync(0xffffffffu, l0, 2);
    l1 += __shfl_xor_sync(0xffffffffu, l1, 1);
    l1 += __shfl_xor_sync(0xffffffffu, l1, 2);

    float inv0 = 1.0f / l0, inv1 = 1.0f / l1;
    int s0r = q0 + wq + g;
    #pragma unroll
    for (int n0 = 0; n0 < 8; n0++) {
        int dk = n0 * 8 + 2 * tig;
        float2 cs  = *(const float2*)(g_cs + bh * 64 + dk);
        float2 bv2 = *(const float2*)(bvp + h * 64 + dk);
        float csx = cs.x + 2048.0f * bv2.x;
        float csy = cs.y + 2048.0f * bv2.y;
        float2 ov0 = make_float2((csx + o[n0][0]) * inv0, (csy + o[n0][1]) * inv0);
        float2 ov1 = make_float2((csx + o[n0][2]) * inv1, (csy + o[n0][3]) * inv1);
        *(float2*)(out + ((size_t)(b * SS + s0r)     ) * DDm + h * 64 + dk) = ov0;
        *(float2*)(out + ((size_t)(b * SS + s0r + 8) ) * DDm + h * 64 + dk) = ov1;
    }
}

// ------------------------- launcher ----------------------------------------
extern "C" void kernel_launch(void* const* d_in, const int* in_sizes, int n_in,
                              void* d_out, int out_size) {
    const float* x  = (const float*)d_in[0];
    const float* zq = (const float*)d_in[1];
    const float* bq = (const float*)d_in[2];
    const float* zk = (const float*)d_in[3];
    const float* bk = (const float*)d_in[4];
    const float* wv = (const float*)d_in[5];
    const float* bv = (const float*)d_in[6];
    float* out = (float*)d_out;

    prep_kernel<<<N3, 256>>>(zq, bq, zk, bk, wv);
    lam_kernel<<<BSr, 256>>>(x);
    gemm_tc<<<dim3(N3 / 128, BSr / 128), 256>>>();
    csum_kernel<<<BHh, 256>>>();
    epi_kernel<<<BSr / 4, 256>>>(bv);

    int smem_bytes = 4 * 64 * 40 * 4;   // 40960
    cudaFuncSetAttribute(attn_kernel, cudaFuncAttributeMaxDynamicSharedMemorySize, smem_bytes);
    attn_kernel<<<dim3(SS / 128, BHh), 256, smem_bytes>>>(out, bv);
}

// round 13
// speedup vs baseline: 7.0500x; 1.7408x over previous
#include <cuda_runtime.h>
#include <cuda_bf16.h>
#include <cstdint>

// Problem constants
#define BB  4
#define SS  2048
#define DDm 1024
#define HHn 16
#define DKk 64
#define BSr (BB*SS)     // 8192 rows
#define N3  3072        // concat of Q|K|V projection outputs
#define BHh (BB*HHn)    // 64 head-batches

// ------------------------- scratch (static device memory) -------------------
__device__ uint32_t g_Bb [(size_t)N3 * 512];          // B bf16x2 [j][d-words], word-scrambled
__device__ uint32_t g_Xb [(size_t)BSr * 512];         // x bf16x2 [r][d-words], word-scrambled
__device__ float    g_IN [(size_t)BSr * N3];          // projections (fp32 accum of bf16 MMA)
__device__ float    g_lam[BSr];                       // per-row lambda
__device__ float4   g_par[2048];                      // per-col {2*zn, cosh2r, sinh2r, 0}
__device__ uint32_t g_Qb [(size_t)BHh * SS * 32];     // Q bf16x2 [bh][s][dk-words], scale log2e/8
__device__ uint32_t g_Kb [(size_t)BHh * SS * 32];     // K bf16x2 word-scrambled
__device__ uint32_t g_Vb [(size_t)BHh * DKk * 1024];  // V bf16x2 [bh][dk][s-words] word-scrambled
__device__ float    g_cs4[4 * BHh * DKk];             // partial colsums of V projection

// ------------------------- helpers ------------------------------------------
__device__ __forceinline__ uint32_t pkbf(float lo, float hi) {
    uint32_t d; asm("cvt.rn.bf16x2.f32 %0, %1, %2;" : "=r"(d) : "f"(hi), "f"(lo)); return d;
}
// word scramble within an 8-word block: phys = 2*(w&3) + ((w>>2)&1)
__device__ __forceinline__ uint32_t ph(uint32_t w) {
    return (w & ~7u) + 2u * (w & 3u) + ((w >> 2) & 1u);
}
__device__ __forceinline__ void mma_bf16(float c[4], const uint32_t a[4],
                                         uint32_t b0, uint32_t b1) {
    asm volatile(
        "mma.sync.aligned.m16n8k16.row.col.f32.bf16.bf16.f32 "
        "{%0,%1,%2,%3}, {%4,%5,%6,%7}, {%8,%9}, {%0,%1,%2,%3};\n"
        : "+f"(c[0]), "+f"(c[1]), "+f"(c[2]), "+f"(c[3])
        : "r"(a[0]), "r"(a[1]), "r"(a[2]), "r"(a[3]), "r"(b0), "r"(b1));
}
__device__ __forceinline__ void cpasync16(uint32_t saddr, const void* gptr) {
    asm volatile("cp.async.cg.shared.global [%0], [%1], 16;\n"
                 :: "r"(saddr), "l"(gptr) : "memory");
}
#define CP_COMMIT() asm volatile("cp.async.commit_group;\n" ::: "memory")
#define CP_WAIT1()  asm volatile("cp.async.wait_group 1;\n" ::: "memory")
#define CP_WAIT0()  asm volatile("cp.async.wait_group 0;\n" ::: "memory")

// ------------------------- block reduction helpers --------------------------
__device__ __forceinline__ float bcastSum(float v) {
    __shared__ float sm[8];
    #pragma unroll
    for (int m = 16; m > 0; m >>= 1) v += __shfl_xor_sync(0xffffffffu, v, m);
    int w = threadIdx.x >> 5;
    if ((threadIdx.x & 31) == 0) sm[w] = v;
    __syncthreads();
    if (threadIdx.x < 8) {
        v = sm[threadIdx.x];
        #pragma unroll
        for (int m = 4; m > 0; m >>= 1) v += __shfl_xor_sync(0x000000ffu, v, m);
        if (threadIdx.x == 0) sm[0] = v;
    }
    __syncthreads();
    v = sm[0];
    __syncthreads();
    return v;
}

__device__ __forceinline__ void bcastSum4(float v[4]) {
    __shared__ float sm4[8][4];
    #pragma unroll
    for (int m = 16; m > 0; m >>= 1) {
        #pragma unroll
        for (int c = 0; c < 4; c++) v[c] += __shfl_xor_sync(0xffffffffu, v[c], m);
    }
    int w = threadIdx.x >> 5;
    if ((threadIdx.x & 31) == 0) {
        #pragma unroll
        for (int c = 0; c < 4; c++) sm4[w][c] = v[c];
    }
    __syncthreads();
    if (threadIdx.x < 8) {
        #pragma unroll
        for (int c = 0; c < 4; c++) v[c] = sm4[threadIdx.x][c];
        #pragma unroll
        for (int m = 4; m > 0; m >>= 1) {
            #pragma unroll
            for (int c = 0; c < 4; c++) v[c] += __shfl_xor_sync(0x000000ffu, v[c], m);
        }
        if (threadIdx.x == 0) {
            #pragma unroll
            for (int c = 0; c < 4; c++) sm4[0][c] = v[c];
        }
    }
    __syncthreads();
    #pragma unroll
    for (int c = 0; c < 4; c++) v[c] = sm4[0][c];
    __syncthreads();
}

// ------------------------- prep: bf16-scrambled B + per-col params ----------
// grid = 3072 blocks, 256 threads; thread t handles elems d = 4t..4t+3.
__global__ __launch_bounds__(256) void prep_kernel(
    const float* __restrict__ zq, const float* __restrict__ bq,
    const float* __restrict__ zk, const float* __restrict__ bk,
    const float* __restrict__ wv)
{
    int j = blockIdx.x;
    int tid = threadIdx.x;
    int d0 = tid * 4;
    uint32_t w0 = tid * 2;
    if (j >= 2048) {
        int col = j - 2048;
        float4 v = *(const float4*)(wv + (size_t)col * DDm + d0);
        uint32_t* row = g_Bb + (size_t)j * 512;
        row[ph(w0)]     = pkbf(v.x, v.y);
        row[ph(w0 + 1)] = pkbf(v.z, v.w);
        return;
    }
    const float* z; const float* bias; int col;
    if (j < 1024) { z = zq; bias = bq; col = j; }
    else          { z = zk; bias = bk; col = j - 1024; }

    float vv[4];
    #pragma unroll
    for (int c = 0; c < 4; c++) vv[c] = z[(size_t)(d0 + c) * DDm + col];
    float ss = vv[0] * vv[0] + vv[1] * vv[1] + vv[2] * vv[2] + vv[3] * vv[3];
    ss = bcastSum(ss);
    float zn = fmaxf(sqrtf(ss), 1e-15f);
    float inv = 1.0f / zn;
    uint32_t* row = g_Bb + (size_t)j * 512;
    row[ph(w0)]     = pkbf(vv[0] * inv, vv[1] * inv);
    row[ph(w0 + 1)] = pkbf(vv[2] * inv, vv[3] * inv);
    if (tid == 0) {
        float r2 = 2.0f * bias[col];
        g_par[j] = make_float4(2.0f * zn, coshf(r2), sinhf(r2), 0.0f);
    }
}

// ------------- lambda + bf16-scrambled x (single pass over x) ---------------
__global__ __launch_bounds__(256) void lam_kernel(const float* __restrict__ x) {
    int r = blockIdx.x;
    int t = threadIdx.x;
    float4 v = *(const float4*)(x + (size_t)r * DDm + t * 4);
    float ss = v.x * v.x + v.y * v.y + v.z * v.z + v.w * v.w;
    uint32_t* row = g_Xb + (size_t)r * 512;
    uint32_t w0 = t * 2;
    row[ph(w0)]     = pkbf(v.x, v.y);
    row[ph(w0 + 1)] = pkbf(v.z, v.w);
    ss = bcastSum(ss);
    if (t == 0) g_lam[r] = 2.0f / (1.0f - ss);
}

// ------------------------- bf16 GEMM: g_IN = x @ B (m16n8k16) ---------------
// 128x128 tiles, K-chunk 64 (4 k16-steps), 8 warps (2M x 4N), warp 64x32.
// Word-scrambled smem rows (stride 40) -> all fragments are single LDS.64.
#define GAT 5120                          // words per [128][40] tile
__global__ __launch_bounds__(256, 2) void gemm_bf() {
    extern __shared__ uint32_t sm[];
    uint32_t sbase = (uint32_t)__cvta_generic_to_shared(sm);

    int tid = threadIdx.x;
    int warp = tid >> 5, lane = tid & 31;
    int g = lane >> 2, tig = lane & 3;
    int wm = warp >> 2, wn = warp & 3;
    int m0 = blockIdx.y * 128, n0 = blockIdx.x * 128;

    const uint32_t* Aw = g_Xb + (size_t)m0 * 512;
    const uint32_t* Bw = g_Bb + (size_t)n0 * 512;

    auto load_chunk = [&](int ch, int buf) {
        uint32_t dst = sbase + (uint32_t)(buf * 2 * GAT) * 4;
        #pragma unroll
        for (int i = 0; i < 8; i++) {
            int id = tid + i * 256;            // 0..2047
            int mat = id >> 10;                // 0:A 1:B
            int r = (id & 1023) >> 3;
            int o4 = (id & 7) * 4;
            uint32_t s = dst + (uint32_t)(mat * GAT + r * 40 + o4) * 4;
            const uint32_t* gp = (mat ? Bw : Aw) + (size_t)r * 512 + ch * 32 + o4;
            cpasync16(s, gp);
        }
        CP_COMMIT();
    };

    float acc[4][4][4];
    #pragma unroll
    for (int mi = 0; mi < 4; mi++)
        #pragma unroll
        for (int ni = 0; ni < 4; ni++)
            #pragma unroll
            for (int c = 0; c < 4; c++) acc[mi][ni][c] = 0.0f;

    load_chunk(0, 0);

    int buf = 0;
    for (int ch = 0; ch < 16; ch++) {
        if (ch + 1 < 16) {
            load_chunk(ch + 1, buf ^ 1);
            CP_WAIT1();
        } else {
            CP_WAIT0();
        }
        __syncthreads();
        const uint32_t* A = sm + buf * 2 * GAT;
        const uint32_t* B = A + GAT;

        #pragma unroll
        for (int ks = 0; ks < 4; ks++) {
            uint32_t af[4][4];
            #pragma unroll
            for (int mi = 0; mi < 4; mi++) {
                int r = wm * 64 + mi * 16;
                uint2 v = *(const uint2*)&A[(r + g)     * 40 + ks * 8 + 2 * tig];
                uint2 u = *(const uint2*)&A[(r + g + 8) * 40 + ks * 8 + 2 * tig];
                af[mi][0] = v.x; af[mi][1] = u.x; af[mi][2] = v.y; af[mi][3] = u.y;
            }
            uint2 bfv[4];
            #pragma unroll
            for (int ni = 0; ni < 4; ni++)
                bfv[ni] = *(const uint2*)&B[(wn * 32 + ni * 8 + g) * 40 + ks * 8 + 2 * tig];
            #pragma unroll
            for (int mi = 0; mi < 4; mi++)
                #pragma unroll
                for (int ni = 0; ni < 4; ni++)
                    mma_bf16(acc[mi][ni], af[mi], bfv[ni].x, bfv[ni].y);
        }
        __syncthreads();
        buf ^= 1;
    }

    #pragma unroll
    for (int mi = 0; mi < 4; mi++) {
        int mr = m0 + wm * 64 + mi * 16 + g;
        #pragma unroll
        for (int ni = 0; ni < 4; ni++) {
            int nc = n0 + wn * 32 + ni * 8 + tig * 2;
            *(float2*)(g_IN + (size_t)mr * N3 + nc) =
                make_float2(acc[mi][ni][0], acc[mi][ni][1]);
            *(float2*)(g_IN + (size_t)(mr + 8) * N3 + nc) =
                make_float2(acc[mi][ni][2], acc[mi][ni][3]);
        }
    }
}

// ------------------------- colsum of V projection (partials, no atomics) ----
// grid (BHh, 4): block sums 512 rows. Thread t: dk=t&63, sub=t>>6 (128 rows).
__global__ __launch_bounds__(256) void csum_kernel() {
    int bh = blockIdx.x;
    int c  = blockIdx.y;
    int b = bh >> 4, h = bh & 15;
    int t = threadIdx.x;
    int dk = t & 63, sub = t >> 6;
    int srow0 = c * 512 + sub * 128;
    const float* base = g_IN + ((size_t)(b * 2048 + srow0)) * N3 + 2048 + h * 64 + dk;
    float s0 = 0.f, s1 = 0.f, s2 = 0.f, s3 = 0.f;
    for (int i = 0; i < 128; i += 4) {
        s0 += base[(size_t)(i + 0) * N3];
        s1 += base[(size_t)(i + 1) * N3];
        s2 += base[(size_t)(i + 2) * N3];
        s3 += base[(size_t)(i + 3) * N3];
    }
    __shared__ float red[256];
    red[t] = (s0 + s1) + (s2 + s3);
    __syncthreads();
    if (t < 64)
        g_cs4[(c * BHh + bh) * 64 + t] =
            (red[t] + red[t + 64]) + (red[t + 128] + red[t + 192]);
}

// ------------------------- epilogue: Poincare map -> bf16 layouts -----------
__global__ __launch_bounds__(256) void epi_kernel(const float* __restrict__ bvp) {
    int r0 = blockIdx.x * 4;
    int b  = r0 >> 11;
    int s0 = r0 & 2047;
    int tid = threadIdx.x;
    int j0 = tid * 4;
    int h  = j0 >> 6, dk = j0 & 63;
    int bh = b * 16 + h;

    float lamv[4];
    *(float4*)lamv = *(const float4*)(g_lam + r0);

    float wq[4][4];
    // ---------------- Q ----------------
    {
        float4 par[4];
        #pragma unroll
        for (int c = 0; c < 4; c++) par[c] = g_par[j0 + c];
        float ws[4] = {0.f, 0.f, 0.f, 0.f};
        #pragma unroll
        for (int ri = 0; ri < 4; ri++) {
            float lam = lamv[ri], lm1 = lam - 1.0f;
            float4 inn = *(const float4*)(g_IN + (size_t)(r0 + ri) * N3 + j0);
            float innv[4] = {inn.x, inn.y, inn.z, inn.w};
            #pragma unroll
            for (int c = 0; c < 4; c++) {
                float arg = lam * innv[c] * par[c].y - lm1 * par[c].z;
                float t   = arg + sqrtf(arg * arg + 1.0f);
                float u   = par[c].x * __logf(t);
                float eu  = __expf(u);
                float w   = 0.5f * (eu - __fdividef(1.0f, eu));
                wq[ri][c] = w;
                ws[ri] += w * w;
            }
        }
        bcastSum4(ws);
        #pragma unroll
        for (int ri = 0; ri < 4; ri++) {
            float scl = 0.18033688f / (1.0f + sqrtf(1.0f + ws[ri]));  // log2(e)/8
            uint2 ov = make_uint2(pkbf(wq[ri][0] * scl, wq[ri][1] * scl),
                                  pkbf(wq[ri][2] * scl, wq[ri][3] * scl));
            *(uint2*)(g_Qb + ((size_t)bh * SS + s0 + ri) * 32 + (dk >> 1)) = ov;
        }
    }
    // ---------------- K (word-scrambled dk layout) ----------------
    {
        float4 par[4];
        #pragma unroll
        for (int c = 0; c < 4; c++) par[c] = g_par[1024 + j0 + c];
        float ws2[4] = {0.f, 0.f, 0.f, 0.f};
        #pragma unroll
        for (int ri = 0; ri < 4; ri++) {
            float lam = lamv[ri], lm1 = lam - 1.0f;
            float4 inn = *(const float4*)(g_IN + (size_t)(r0 + ri) * N3 + 1024 + j0);
            float innv[4] = {inn.x, inn.y, inn.z, inn.w};
            #pragma unroll
            for (int c = 0; c < 4; c++) {
                float arg = lam * innv[c] * par[c].y - lm1 * par[c].z;
                float t   = arg + sqrtf(arg * arg + 1.0f);
                float u   = par[c].x * __logf(t);
                float eu  = __expf(u);
                float w   = 0.5f * (eu - __fdividef(1.0f, eu));
                wq[ri][c] = w;
                ws2[ri] += w * w;
            }
        }
        bcastSum4(ws2);
        uint32_t wl0 = dk >> 1;
        uint32_t p0 = ph(wl0), p1 = ph(wl0 + 1);
        #pragma unroll
        for (int ri = 0; ri < 4; ri++) {
            float scl = 1.0f / (1.0f + sqrtf(1.0f + ws2[ri]));
            uint32_t* row = g_Kb + ((size_t)bh * SS + s0 + ri) * 32;
            row[p0] = pkbf(wq[ri][0] * scl, wq[ri][1] * scl);
            row[p1] = pkbf(wq[ri][2] * scl, wq[ri][3] * scl);
        }
    }
    // ---------------- V (transposed, word-scrambled s layout) ----------------
    {
        float4 bvv = *(const float4*)(bvp + j0);
        float vv[4][4];
        #pragma unroll
        for (int ri = 0; ri < 4; ri++) {
            float4 inn = *(const float4*)(g_IN + (size_t)(r0 + ri) * N3 + 2048 + j0);
            vv[ri][0] = inn.x + bvv.x;
            vv[ri][1] = inn.y + bvv.y;
            vv[ri][2] = inn.z + bvv.z;
            vv[ri][3] = inn.w + bvv.w;
        }
        uint32_t wl0 = s0 >> 1;
        uint32_t ps0 = ph(wl0), ps1 = ph(wl0 + 1);
        #pragma unroll
        for (int c = 0; c < 4; c++) {
            uint32_t* row = g_Vb + ((size_t)bh * DKk + dk + c) * 1024;
            row[ps0] = pkbf(vv[0][c], vv[1][c]);
            row[ps1] = pkbf(vv[2][c], vv[3][c]);
        }
    }
}

// ------------------------- flash attention (bf16 m16n8k16, centered P) ------
// O = colsumV + sum_k (p_k - 1) v_k ; l = sum p_k.
__global__ __launch_bounds__(256, 2) void attn_kernel(float* __restrict__ out,
                                                      const float* __restrict__ bvp) {
    extern __shared__ uint32_t usmem[];
    const int TW = 64 * 40;
    uint32_t sbase = (uint32_t)__cvta_generic_to_shared(usmem);

    int tid  = threadIdx.x;
    int warp = tid >> 5, lane = tid & 31;
    int g = lane >> 2, tig = lane & 3;
    int bh = blockIdx.y;
    int b  = bh >> 4, h = bh & 15;
    int q0 = blockIdx.x * 128;
    int wq = warp * 16;

    const uint32_t* Qw = g_Qb + ((size_t)bh * SS + q0 + wq) * 32;
    const uint32_t* Kw = g_Kb + (size_t)bh * SS * 32;
    const uint32_t* Vw = g_Vb + (size_t)bh * DKk * 1024;

    uint32_t qa[4][4];
    #pragma unroll
    for (int ktq = 0; ktq < 4; ktq++) {
        qa[ktq][0] = Qw[(size_t)g       * 32 + ktq * 8 + tig];
        qa[ktq][1] = Qw[(size_t)(g + 8) * 32 + ktq * 8 + tig];
        qa[ktq][2] = Qw[(size_t)g       * 32 + ktq * 8 + tig + 4];
        qa[ktq][3] = Qw[(size_t)(g + 8) * 32 + ktq * 8 + tig + 4];
    }

    float o[8][4];
    #pragma unroll
    for (int n = 0; n < 8; n++)
        #pragma unroll
        for (int c = 0; c < 4; c++) o[n][c] = 0.0f;
    float l0 = 0.0f, l1 = 0.0f;

    auto load_tile = [&](int buf, int it) {
        int kc0 = it * 64;
        uint32_t sk = sbase + (uint32_t)(buf * TW) * 4;
        uint32_t sv = sbase + (uint32_t)((2 + buf) * TW) * 4;
        #pragma unroll
        for (int i = 0; i < 2; i++) {
            int chunk = tid + i * 256;
            int row = chunk >> 3;
            int off = (chunk & 7) * 4;
            cpasync16(sk + (uint32_t)(row * 40 + off) * 4,
                      Kw + (size_t)(kc0 + row) * 32 + off);
            cpasync16(sv + (uint32_t)(row * 40 + off) * 4,
                      Vw + (size_t)row * 1024 + it * 32 + off);
        }
        CP_COMMIT();
    };

    load_tile(0, 0);

    int buf = 0;
    for (int it = 0; it < SS / 64; it++) {
        if (it + 1 < SS / 64) {
            load_tile(buf ^ 1, it + 1);
            CP_WAIT1();
        } else {
            CP_WAIT0();
        }
        __syncthreads();
        const uint32_t* sK = usmem + buf * TW;
        const uint32_t* sV = usmem + (2 + buf) * TW;

        float p[8][4];
        #pragma unroll
        for (int n = 0; n < 8; n++)
            #pragma unroll
            for (int c = 0; c < 4; c++) p[n][c] = 0.0f;
        #pragma unroll
        for (int ktq = 0; ktq < 4; ktq++) {
            #pragma unroll
            for (int n0 = 0; n0 < 8; n0++) {
                uint2 kb = *(const uint2*)(sK + (n0 * 8 + g) * 40 + ktq * 8 + 2 * tig);
                mma_bf16(p[n0], qa[ktq], kb.x, kb.y);
            }
        }

        #pragma unroll
        for (int n = 0; n < 8; n++) {
            float e0 = exp2f(p[n][0]);
            float e1 = exp2f(p[n][1]);
            float e2 = exp2f(p[n][2]);
            float e3 = exp2f(p[n][3]);
            l0 += e0 + e1;
            l1 += e2 + e3;
            p[n][0] = e0 - 1.0f;
            p[n][1] = e1 - 1.0f;
            p[n][2] = e2 - 1.0f;
            p[n][3] = e3 - 1.0f;
        }

        uint32_t pa[4][4];
        #pragma unroll
        for (int ktp = 0; ktp < 4; ktp++) {
            pa[ktp][0] = pkbf(p[2 * ktp    ][0], p[2 * ktp    ][1]);
            pa[ktp][1] = pkbf(p[2 * ktp    ][2], p[2 * ktp    ][3]);
            pa[ktp][2] = pkbf(p[2 * ktp + 1][0], p[2 * ktp + 1][1]);
            pa[ktp][3] = pkbf(p[2 * ktp + 1][2], p[2 * ktp + 1][3]);
        }

        #pragma unroll
        for (int ktp = 0; ktp < 4; ktp++) {
            #pragma unroll
            for (int n0 = 0; n0 < 8; n0++) {
                uint2 vb = *(const uint2*)(sV + (n0 * 8 + g) * 40 + ktp * 8 + 2 * tig);
                mma_bf16(o[n0], pa[ktp], vb.x, vb.y);
            }
        }
        __syncthreads();
        buf ^= 1;
    }

    l0 += __shfl_xor_sync(0xffffffffu, l0, 1);
    l0 += __shfl_xor_sync(0xffffffffu, l0, 2);
    l1 += __shfl_xor_sync(0xffffffffu, l1, 1);
    l1 += __shfl_xor_sync(0xffffffffu, l1, 2);

    float inv0 = 1.0f / l0, inv1 = 1.0f / l1;
    int s0r = q0 + wq + g;
    #pragma unroll
    for (int n0 = 0; n0 < 8; n0++) {
        int dk = n0 * 8 + 2 * tig;
        float csx = 0.0f, csy = 0.0f;
        #pragma unroll
        for (int c = 0; c < 4; c++) {
            float2 t = *(const float2*)(g_cs4 + ((size_t)(c * BHh + bh)) * 64 + dk);
            csx += t.x; csy += t.y;
        }
        float2 bv2 = *(const float2*)(bvp + h * 64 + dk);
        csx += 2048.0f * bv2.x;
        csy += 2048.0f * bv2.y;
        float2 ov0 = make_float2((csx + o[n0][0]) * inv0, (csy + o[n0][1]) * inv0);
        float2 ov1 = make_float2((csx + o[n0][2]) * inv1, (csy + o[n0][3]) * inv1);
        *(float2*)(out + ((size_t)(b * SS + s0r)     ) * DDm + h * 64 + dk) = ov0;
        *(float2*)(out + ((size_t)(b * SS + s0r + 8) ) * DDm + h * 64 + dk) = ov1;
    }
}

// ------------------------- launcher ----------------------------------------
extern "C" void kernel_launch(void* const* d_in, const int* in_sizes, int n_in,
                              void* d_out, int out_size) {
    const float* x  = (const float*)d_in[0];
    const float* zq = (const float*)d_in[1];
    const float* bq = (const float*)d_in[2];
    const float* zk = (const float*)d_in[3];
    const float* bk = (const float*)d_in[4];
    const float* wv = (const float*)d_in[5];
    const float* bv = (const float*)d_in[6];
    float* out = (float*)d_out;

    prep_kernel<<<N3, 256>>>(zq, bq, zk, bk, wv);
    lam_kernel<<<BSr, 256>>>(x);

    int gsmem = 2 * 2 * GAT * 4;   // 81920
    cudaFuncSetAttribute(gemm_bf, cudaFuncAttributeMaxDynamicSharedMemorySize, gsmem);
    gemm_bf<<<dim3(N3 / 128, BSr / 128), 256, gsmem>>>();

    csum_kernel<<<dim3(BHh, 4), 256>>>();
    epi_kernel<<<BSr / 4, 256>>>(bv);

    int smem_bytes = 4 * 64 * 40 * 4;   // 40960
    cudaFuncSetAttribute(attn_kernel, cudaFuncAttributeMaxDynamicSharedMemorySize, smem_bytes);
    attn_kernel<<<dim3(SS / 128, BHh), 256, smem_bytes>>>(out, bv);
}

// round 14
// speedup vs baseline: 7.4534x; 1.0572x over previous
#include <cuda_runtime.h>
#include <cuda_bf16.h>
#include <cstdint>

// Problem constants
#define BB  4
#define SS  2048
#define DDm 1024
#define HHn 16
#define DKk 64
#define BSr (BB*SS)     // 8192 rows
#define N3  3072        // concat of Q|K|V projection outputs
#define BHh (BB*HHn)    // 64 head-batches

// ------------------------- scratch (static device memory) -------------------
__device__ uint32_t g_Bb [(size_t)N3 * 512];          // B bf16x2 [j][d-words], word-scrambled
__device__ uint32_t g_Xb [(size_t)BSr * 512];         // x bf16x2 [r][d-words], word-scrambled
__device__ uint32_t g_INb[(size_t)BSr * 1536];        // projections bf16x2 [r][j-words]
__device__ float    g_lam[BSr];                       // per-row lambda
__device__ float4   g_par[2048];                      // per-col {2*zn, cosh2r, sinh2r, 0}
__device__ uint32_t g_Qb [(size_t)BHh * SS * 32];     // Q bf16x2 [bh][s][dk-words], scale log2e/8
__device__ uint32_t g_Kb [(size_t)BHh * SS * 32];     // K bf16x2 word-scrambled
__device__ uint32_t g_Vb [(size_t)BHh * DKk * 1024];  // V bf16x2 [bh][dk][s-words] word-scrambled
__device__ float    g_cs4[4 * BHh * DKk];             // partial colsums of V projection

// ------------------------- helpers ------------------------------------------
__device__ __forceinline__ uint32_t pkbf(float lo, float hi) {
    uint32_t d; asm("cvt.rn.bf16x2.f32 %0, %1, %2;" : "=r"(d) : "f"(hi), "f"(lo)); return d;
}
__device__ __forceinline__ float2 upbf(uint32_t w) {
    return make_float2(__uint_as_float(w << 16), __uint_as_float(w & 0xffff0000u));
}
__device__ __forceinline__ float fex2(float x) {
    float r; asm("ex2.approx.ftz.f32 %0, %1;" : "=f"(r) : "f"(x)); return r;
}
// word scramble within an 8-word block: phys = 2*(w&3) + ((w>>2)&1)
__device__ __forceinline__ uint32_t ph(uint32_t w) {
    return (w & ~7u) + 2u * (w & 3u) + ((w >> 2) & 1u);
}
__device__ __forceinline__ void mma_bf16(float c[4], const uint32_t a[4],
                                         uint32_t b0, uint32_t b1) {
    asm volatile(
        "mma.sync.aligned.m16n8k16.row.col.f32.bf16.bf16.f32 "
        "{%0,%1,%2,%3}, {%4,%5,%6,%7}, {%8,%9}, {%0,%1,%2,%3};\n"
        : "+f"(c[0]), "+f"(c[1]), "+f"(c[2]), "+f"(c[3])
        : "r"(a[0]), "r"(a[1]), "r"(a[2]), "r"(a[3]), "r"(b0), "r"(b1));
}
__device__ __forceinline__ void cpasync16(uint32_t saddr, const void* gptr) {
    asm volatile("cp.async.cg.shared.global [%0], [%1], 16;\n"
                 :: "r"(saddr), "l"(gptr) : "memory");
}
#define CP_COMMIT() asm volatile("cp.async.commit_group;\n" ::: "memory")
#define CP_WAIT1()  asm volatile("cp.async.wait_group 1;\n" ::: "memory")
#define CP_WAIT0()  asm volatile("cp.async.wait_group 0;\n" ::: "memory")

// ------------------------- block reduction helpers --------------------------
__device__ __forceinline__ float bcastSum(float v) {
    __shared__ float sm[8];
    #pragma unroll
    for (int m = 16; m > 0; m >>= 1) v += __shfl_xor_sync(0xffffffffu, v, m);
    int w = threadIdx.x >> 5;
    if ((threadIdx.x & 31) == 0) sm[w] = v;
    __syncthreads();
    if (threadIdx.x < 8) {
        v = sm[threadIdx.x];
        #pragma unroll
        for (int m = 4; m > 0; m >>= 1) v += __shfl_xor_sync(0x000000ffu, v, m);
        if (threadIdx.x == 0) sm[0] = v;
    }
    __syncthreads();
    v = sm[0];
    __syncthreads();
    return v;
}

__device__ __forceinline__ void bcastSum4(float v[4]) {
    __shared__ float sm4[8][4];
    #pragma unroll
    for (int m = 16; m > 0; m >>= 1) {
        #pragma unroll
        for (int c = 0; c < 4; c++) v[c] += __shfl_xor_sync(0xffffffffu, v[c], m);
    }
    int w = threadIdx.x >> 5;
    if ((threadIdx.x & 31) == 0) {
        #pragma unroll
        for (int c = 0; c < 4; c++) sm4[w][c] = v[c];
    }
    __syncthreads();
    if (threadIdx.x < 8) {
        #pragma unroll
        for (int c = 0; c < 4; c++) v[c] = sm4[threadIdx.x][c];
        #pragma unroll
        for (int m = 4; m > 0; m >>= 1) {
            #pragma unroll
            for (int c = 0; c < 4; c++) v[c] += __shfl_xor_sync(0x000000ffu, v[c], m);
        }
        if (threadIdx.x == 0) {
            #pragma unroll
            for (int c = 0; c < 4; c++) sm4[0][c] = v[c];
        }
    }
    __syncthreads();
    #pragma unroll
    for (int c = 0; c < 4; c++) v[c] = sm4[0][c];
    __syncthreads();
}

// ------------------------- prep: bf16-scrambled B + per-col params ----------
__global__ __launch_bounds__(256) void prep_kernel(
    const float* __restrict__ zq, const float* __restrict__ bq,
    const float* __restrict__ zk, const float* __restrict__ bk,
    const float* __restrict__ wv)
{
    int j = blockIdx.x;
    int tid = threadIdx.x;
    int d0 = tid * 4;
    uint32_t w0 = tid * 2;
    if (j >= 2048) {
        int col = j - 2048;
        float4 v = *(const float4*)(wv + (size_t)col * DDm + d0);
        uint32_t* row = g_Bb + (size_t)j * 512;
        row[ph(w0)]     = pkbf(v.x, v.y);
        row[ph(w0 + 1)] = pkbf(v.z, v.w);
        return;
    }
    const float* z; const float* bias; int col;
    if (j < 1024) { z = zq; bias = bq; col = j; }
    else          { z = zk; bias = bk; col = j - 1024; }

    float vv[4];
    #pragma unroll
    for (int c = 0; c < 4; c++) vv[c] = z[(size_t)(d0 + c) * DDm + col];
    float ss = vv[0] * vv[0] + vv[1] * vv[1] + vv[2] * vv[2] + vv[3] * vv[3];
    ss = bcastSum(ss);
    float zn = fmaxf(sqrtf(ss), 1e-15f);
    float inv = 1.0f / zn;
    uint32_t* row = g_Bb + (size_t)j * 512;
    row[ph(w0)]     = pkbf(vv[0] * inv, vv[1] * inv);
    row[ph(w0 + 1)] = pkbf(vv[2] * inv, vv[3] * inv);
    if (tid == 0) {
        float r2 = 2.0f * bias[col];
        g_par[j] = make_float4(2.0f * zn, coshf(r2), sinhf(r2), 0.0f);
    }
}

// ------------- lambda + bf16-scrambled x (single pass over x) ---------------
__global__ __launch_bounds__(256) void lam_kernel(const float* __restrict__ x) {
    int r = blockIdx.x;
    int t = threadIdx.x;
    float4 v = *(const float4*)(x + (size_t)r * DDm + t * 4);
    float ss = v.x * v.x + v.y * v.y + v.z * v.z + v.w * v.w;
    uint32_t* row = g_Xb + (size_t)r * 512;
    uint32_t w0 = t * 2;
    row[ph(w0)]     = pkbf(v.x, v.y);
    row[ph(w0 + 1)] = pkbf(v.z, v.w);
    ss = bcastSum(ss);
    if (t == 0) g_lam[r] = 2.0f / (1.0f - ss);
}

// ------------------------- bf16 GEMM: g_INb = x @ B (m16n8k16) --------------
#define GAT 5120                          // words per [128][40] tile
__global__ __launch_bounds__(256, 2) void gemm_bf() {
    extern __shared__ uint32_t sm[];
    uint32_t sbase = (uint32_t)__cvta_generic_to_shared(sm);

    int tid = threadIdx.x;
    int warp = tid >> 5, lane = tid & 31;
    int g = lane >> 2, tig = lane & 3;
    int wm = warp >> 2, wn = warp & 3;
    int m0 = blockIdx.y * 128, n0 = blockIdx.x * 128;

    const uint32_t* Aw = g_Xb + (size_t)m0 * 512;
    const uint32_t* Bw = g_Bb + (size_t)n0 * 512;

    auto load_chunk = [&](int ch, int buf) {
        uint32_t dst = sbase + (uint32_t)(buf * 2 * GAT) * 4;
        #pragma unroll
        for (int i = 0; i < 8; i++) {
            int id = tid + i * 256;            // 0..2047
            int mat = id >> 10;                // 0:A 1:B
            int r = (id & 1023) >> 3;
            int o4 = (id & 7) * 4;
            uint32_t s = dst + (uint32_t)(mat * GAT + r * 40 + o4) * 4;
            const uint32_t* gp = (mat ? Bw : Aw) + (size_t)r * 512 + ch * 32 + o4;
            cpasync16(s, gp);
        }
        CP_COMMIT();
    };

    float acc[4][4][4];
    #pragma unroll
    for (int mi = 0; mi < 4; mi++)
        #pragma unroll
        for (int ni = 0; ni < 4; ni++)
            #pragma unroll
            for (int c = 0; c < 4; c++) acc[mi][ni][c] = 0.0f;

    load_chunk(0, 0);

    int buf = 0;
    for (int ch = 0; ch < 16; ch++) {
        if (ch + 1 < 16) {
            load_chunk(ch + 1, buf ^ 1);
            CP_WAIT1();
        } else {
            CP_WAIT0();
        }
        __syncthreads();
        const uint32_t* A = sm + buf * 2 * GAT;
        const uint32_t* B = A + GAT;

        #pragma unroll
        for (int ks = 0; ks < 4; ks++) {
            uint32_t af[4][4];
            #pragma unroll
            for (int mi = 0; mi < 4; mi++) {
                int r = wm * 64 + mi * 16;
                uint2 v = *(const uint2*)&A[(r + g)     * 40 + ks * 8 + 2 * tig];
                uint2 u = *(const uint2*)&A[(r + g + 8) * 40 + ks * 8 + 2 * tig];
                af[mi][0] = v.x; af[mi][1] = u.x; af[mi][2] = v.y; af[mi][3] = u.y;
            }
            uint2 bfv[4];
            #pragma unroll
            for (int ni = 0; ni < 4; ni++)
                bfv[ni] = *(const uint2*)&B[(wn * 32 + ni * 8 + g) * 40 + ks * 8 + 2 * tig];
            #pragma unroll
            for (int mi = 0; mi < 4; mi++)
                #pragma unroll
                for (int ni = 0; ni < 4; ni++)
                    mma_bf16(acc[mi][ni], af[mi], bfv[ni].x, bfv[ni].y);
        }
        __syncthreads();
        buf ^= 1;
    }

    // epilogue: pack fp32 accumulators to bf16x2 words
    #pragma unroll
    for (int mi = 0; mi < 4; mi++) {
        int mr = m0 + wm * 64 + mi * 16 + g;
        #pragma unroll
        for (int ni = 0; ni < 4; ni++) {
            int wc = (n0 + wn * 32 + ni * 8 + tig * 2) >> 1;
            g_INb[(size_t)mr * 1536 + wc]       = pkbf(acc[mi][ni][0], acc[mi][ni][1]);
            g_INb[(size_t)(mr + 8) * 1536 + wc] = pkbf(acc[mi][ni][2], acc[mi][ni][3]);
        }
    }
}

// ------------------------- colsum of V projection (packed reads) ------------
// grid (BHh, 4): block sums 512 rows. Thread t: word w=t&31 (2 dk), sub=t>>5 (8 subs x 64 rows).
__global__ __launch_bounds__(256) void csum_kernel() {
    int bh = blockIdx.x;
    int c  = blockIdx.y;
    int b = bh >> 4, h = bh & 15;
    int t = threadIdx.x;
    int w = t & 31, sub = t >> 5;            // sub 0..7
    int srow0 = c * 512 + sub * 64;
    const uint32_t* base = g_INb + ((size_t)(b * 2048 + srow0)) * 1536 + 1024 + h * 32 + w;
    float sl = 0.f, sh = 0.f;
    for (int i = 0; i < 64; i++) {
        float2 v = upbf(base[(size_t)i * 1536]);
        sl += v.x; sh += v.y;
    }
    __shared__ float red[256][2];
    red[t][0] = sl; red[t][1] = sh;
    __syncthreads();
    if (t < 32) {
        float al = 0.f, ah = 0.f;
        #pragma unroll
        for (int s = 0; s < 8; s++) {
            al += red[s * 32 + t][0];
            ah += red[s * 32 + t][1];
        }
        g_cs4[(c * BHh + bh) * 64 + 2 * t]     = al;
        g_cs4[(c * BHh + bh) * 64 + 2 * t + 1] = ah;
    }
}

// ------------------------- epilogue: Poincare map -> bf16 layouts -----------
__global__ __launch_bounds__(256) void epi_kernel(const float* __restrict__ bvp) {
    int r0 = blockIdx.x * 4;
    int b  = r0 >> 11;
    int s0 = r0 & 2047;
    int tid = threadIdx.x;
    int j0 = tid * 4;
    int h  = j0 >> 6, dk = j0 & 63;
    int bh = b * 16 + h;

    float lamv[4];
    *(float4*)lamv = *(const float4*)(g_lam + r0);

    float wq[4][4];
    // ---------------- Q ----------------
    {
        float4 par[4];
        #pragma unroll
        for (int c = 0; c < 4; c++) par[c] = g_par[j0 + c];
        float ws[4] = {0.f, 0.f, 0.f, 0.f};
        #pragma unroll
        for (int ri = 0; ri < 4; ri++) {
            float lam = lamv[ri], lm1 = lam - 1.0f;
            uint2 iw = *(const uint2*)(g_INb + (size_t)(r0 + ri) * 1536 + tid * 2);
            float2 i0 = upbf(iw.x), i1 = upbf(iw.y);
            float innv[4] = {i0.x, i0.y, i1.x, i1.y};
            #pragma unroll
            for (int c = 0; c < 4; c++) {
                float arg = lam * innv[c] * par[c].y - lm1 * par[c].z;
                float t   = arg + sqrtf(arg * arg + 1.0f);
                float u   = par[c].x * __logf(t);
                float eu  = __expf(u);
                float w   = 0.5f * (eu - __fdividef(1.0f, eu));
                wq[ri][c] = w;
                ws[ri] += w * w;
            }
        }
        bcastSum4(ws);
        #pragma unroll
        for (int ri = 0; ri < 4; ri++) {
            float scl = 0.18033688f / (1.0f + sqrtf(1.0f + ws[ri]));  // log2(e)/8
            uint2 ov = make_uint2(pkbf(wq[ri][0] * scl, wq[ri][1] * scl),
                                  pkbf(wq[ri][2] * scl, wq[ri][3] * scl));
            *(uint2*)(g_Qb + ((size_t)bh * SS + s0 + ri) * 32 + (dk >> 1)) = ov;
        }
    }
    // ---------------- K (word-scrambled dk layout) ----------------
    {
        float4 par[4];
        #pragma unroll
        for (int c = 0; c < 4; c++) par[c] = g_par[1024 + j0 + c];
        float ws2[4] = {0.f, 0.f, 0.f, 0.f};
        #pragma unroll
        for (int ri = 0; ri < 4; ri++) {
            float lam = lamv[ri], lm1 = lam - 1.0f;
            uint2 iw = *(const uint2*)(g_INb + (size_t)(r0 + ri) * 1536 + 512 + tid * 2);
            float2 i0 = upbf(iw.x), i1 = upbf(iw.y);
            float innv[4] = {i0.x, i0.y, i1.x, i1.y};
            #pragma unroll
            for (int c = 0; c < 4; c++) {
                float arg = lam * innv[c] * par[c].y - lm1 * par[c].z;
                float t   = arg + sqrtf(arg * arg + 1.0f);
                float u   = par[c].x * __logf(t);
                float eu  = __expf(u);
                float w   = 0.5f * (eu - __fdividef(1.0f, eu));
                wq[ri][c] = w;
                ws2[ri] += w * w;
            }
        }
        bcastSum4(ws2);
        uint32_t wl0 = dk >> 1;
        uint32_t p0 = ph(wl0), p1 = ph(wl0 + 1);
        #pragma unroll
        for (int ri = 0; ri < 4; ri++) {
            float scl = 1.0f / (1.0f + sqrtf(1.0f + ws2[ri]));
            uint32_t* row = g_Kb + ((size_t)bh * SS + s0 + ri) * 32;
            row[p0] = pkbf(wq[ri][0] * scl, wq[ri][1] * scl);
            row[p1] = pkbf(wq[ri][2] * scl, wq[ri][3] * scl);
        }
    }
    // ---------------- V (transposed, word-scrambled s layout) ----------------
    {
        float4 bvv = *(const float4*)(bvp + j0);
        float vv[4][4];
        #pragma unroll
        for (int ri = 0; ri < 4; ri++) {
            uint2 iw = *(const uint2*)(g_INb + (size_t)(r0 + ri) * 1536 + 1024 + tid * 2);
            float2 i0 = upbf(iw.x), i1 = upbf(iw.y);
            vv[ri][0] = i0.x + bvv.x;
            vv[ri][1] = i0.y + bvv.y;
            vv[ri][2] = i1.x + bvv.z;
            vv[ri][3] = i1.y + bvv.w;
        }
        uint32_t wl0 = s0 >> 1;
        uint32_t ps0 = ph(wl0), ps1 = ph(wl0 + 1);
        #pragma unroll
        for (int c = 0; c < 4; c++) {
            uint32_t* row = g_Vb + ((size_t)bh * DKk + dk + c) * 1024;
            row[ps0] = pkbf(vv[0][c], vv[1][c]);
            row[ps1] = pkbf(vv[2][c], vv[3][c]);
        }
    }
}

// ------------------------- flash attention (bf16 m16n8k16, centered P) ------
// O = colsumV + sum_k (p_k - 1) v_k ; l = sum p_k.
__global__ __launch_bounds__(256, 2) void attn_kernel(float* __restrict__ out,
                                                      const float* __restrict__ bvp) {
    extern __shared__ uint32_t usmem[];
    const int TW = 64 * 40;
    uint32_t sbase = (uint32_t)__cvta_generic_to_shared(usmem);

    int tid  = threadIdx.x;
    int warp = tid >> 5, lane = tid & 31;
    int g = lane >> 2, tig = lane & 3;
    int bh = blockIdx.y;
    int b  = bh >> 4, h = bh & 15;
    int q0 = blockIdx.x * 128;
    int wq = warp * 16;

    const uint32_t* Qw = g_Qb + ((size_t)bh * SS + q0 + wq) * 32;
    const uint32_t* Kw = g_Kb + (size_t)bh * SS * 32;
    const uint32_t* Vw = g_Vb + (size_t)bh * DKk * 1024;

    uint32_t qa[4][4];
    #pragma unroll
    for (int ktq = 0; ktq < 4; ktq++) {
        qa[ktq][0] = Qw[(size_t)g       * 32 + ktq * 8 + tig];
        qa[ktq][1] = Qw[(size_t)(g + 8) * 32 + ktq * 8 + tig];
        qa[ktq][2] = Qw[(size_t)g       * 32 + ktq * 8 + tig + 4];
        qa[ktq][3] = Qw[(size_t)(g + 8) * 32 + ktq * 8 + tig + 4];
    }

    float o[8][4];
    #pragma unroll
    for (int n = 0; n < 8; n++)
        #pragma unroll
        for (int c = 0; c < 4; c++) o[n][c] = 0.0f;
    float l0 = 0.0f, l1 = 0.0f;

    auto load_tile = [&](int buf, int it) {
        int kc0 = it * 64;
        uint32_t sk = sbase + (uint32_t)(buf * TW) * 4;
        uint32_t sv = sbase + (uint32_t)((2 + buf) * TW) * 4;
        #pragma unroll
        for (int i = 0; i < 2; i++) {
            int chunk = tid + i * 256;
            int row = chunk >> 3;
            int off = (chunk & 7) * 4;
            cpasync16(sk + (uint32_t)(row * 40 + off) * 4,
                      Kw + (size_t)(kc0 + row) * 32 + off);
            cpasync16(sv + (uint32_t)(row * 40 + off) * 4,
                      Vw + (size_t)row * 1024 + it * 32 + off);
        }
        CP_COMMIT();
    };

    load_tile(0, 0);

    int buf = 0;
    for (int it = 0; it < SS / 64; it++) {
        if (it + 1 < SS / 64) {
            load_tile(buf ^ 1, it + 1);
            CP_WAIT1();
        } else {
            CP_WAIT0();
        }
        __syncthreads();
        const uint32_t* sK = usmem + buf * TW;
        const uint32_t* sV = usmem + (2 + buf) * TW;

        float p[8][4];
        #pragma unroll
        for (int n = 0; n < 8; n++)
            #pragma unroll
            for (int c = 0; c < 4; c++) p[n][c] = 0.0f;
        #pragma unroll
        for (int ktq = 0; ktq < 4; ktq++) {
            #pragma unroll
            for (int n0 = 0; n0 < 8; n0++) {
                uint2 kb = *(const uint2*)(sK + (n0 * 8 + g) * 40 + ktq * 8 + 2 * tig);
                mma_bf16(p[n0], qa[ktq], kb.x, kb.y);
            }
        }

        #pragma unroll
        for (int n = 0; n < 8; n++) {
            float e0 = fex2(p[n][0]);
            float e1 = fex2(p[n][1]);
            float e2 = fex2(p[n][2]);
            float e3 = fex2(p[n][3]);
            l0 += e0 + e1;
            l1 += e2 + e3;
            p[n][0] = e0 - 1.0f;
            p[n][1] = e1 - 1.0f;
            p[n][2] = e2 - 1.0f;
            p[n][3] = e3 - 1.0f;
        }

        uint32_t pa[4][4];
        #pragma unroll
        for (int ktp = 0; ktp < 4; ktp++) {
            pa[ktp][0] = pkbf(p[2 * ktp    ][0], p[2 * ktp    ][1]);
            pa[ktp][1] = pkbf(p[2 * ktp    ][2], p[2 * ktp    ][3]);
            pa[ktp][2] = pkbf(p[2 * ktp + 1][0], p[2 * ktp + 1][1]);
            pa[ktp][3] = pkbf(p[2 * ktp + 1][2], p[2 * ktp + 1][3]);
        }

        #pragma unroll
        for (int ktp = 0; ktp < 4; ktp++) {
            #pragma unroll
            for (int n0 = 0; n0 < 8; n0++) {
                uint2 vb = *(const uint2*)(sV + (n0 * 8 + g) * 40 + ktp * 8 + 2 * tig);
                mma_bf16(o[n0], pa[ktp], vb.x, vb.y);
            }
        }
        __syncthreads();
        buf ^= 1;
    }

    l0 += __shfl_xor_sync(0xffffffffu, l0, 1);
    l0 += __shfl_xor_sync(0xffffffffu, l0, 2);
    l1 += __shfl_xor_sync(0xffffffffu, l1, 1);
    l1 += __shfl_xor_sync(0xffffffffu, l1, 2);

    float inv0 = 1.0f / l0, inv1 = 1.0f / l1;
    int s0r = q0 + wq + g;
    #pragma unroll
    for (int n0 = 0; n0 < 8; n0++) {
        int dk = n0 * 8 + 2 * tig;
        float csx = 0.0f, csy = 0.0f;
        #pragma unroll
        for (int c = 0; c < 4; c++) {
            float2 t = *(const float2*)(g_cs4 + ((size_t)(c * BHh + bh)) * 64 + dk);
            csx += t.x; csy += t.y;
        }
        float2 bv2 = *(const float2*)(bvp + h * 64 + dk);
        csx += 2048.0f * bv2.x;
        csy += 2048.0f * bv2.y;
        float2 ov0 = make_float2((csx + o[n0][0]) * inv0, (csy + o[n0][1]) * inv0);
        float2 ov1 = make_float2((csx + o[n0][2]) * inv1, (csy + o[n0][3]) * inv1);
        *(float2*)(out + ((size_t)(b * SS + s0r)     ) * DDm + h * 64 + dk) = ov0;
        *(float2*)(out + ((size_t)(b * SS + s0r + 8) ) * DDm + h * 64 + dk) = ov1;
    }
}

// ------------------------- launcher ----------------------------------------
extern "C" void kernel_launch(void* const* d_in, const int* in_sizes, int n_in,
                              void* d_out, int out_size) {
    const float* x  = (const float*)d_in[0];
    const float* zq = (const float*)d_in[1];
    const float* bq = (const float*)d_in[2];
    const float* zk = (const float*)d_in[3];
    const float* bk = (const float*)d_in[4];
    const float* wv = (const float*)d_in[5];
    const float* bv = (const float*)d_in[6];
    float* out = (float*)d_out;

    prep_kernel<<<N3, 256>>>(zq, bq, zk, bk, wv);
    lam_kernel<<<BSr, 256>>>(x);

    int gsmem = 2 * 2 * GAT * 4;   // 81920
    cudaFuncSetAttribute(gemm_bf, cudaFuncAttributeMaxDynamicSharedMemorySize, gsmem);
    gemm_bf<<<dim3(N3 / 128, BSr / 128), 256, gsmem>>>();

    csum_kernel<<<dim3(BHh, 4), 256>>>();
    epi_kernel<<<BSr / 4, 256>>>(bv);

    int smem_bytes = 4 * 64 * 40 * 4;   // 40960
    cudaFuncSetAttribute(attn_kernel, cudaFuncAttributeMaxDynamicSharedMemorySize, smem_bytes);
    attn_kernel<<<dim3(SS / 128, BHh), 256, smem_bytes>>>(out, bv);
}